// round 6
// baseline (speedup 1.0000x reference)
#include <cuda_runtime.h>
#include <cuda_fp16.h>
#include <cstdint>

// ---------------------------------------------------------------------------
// GlobalGNN layer-1-only pipeline (7 graph nodes):
//   s2  : GEMM xW = x@W^T (tf32 TC, fp16 out) -> tail g1[n2..n1)=xW+b
//   main: memset(hd) -> hist(+w stage) -> scan(vec) -> scatter -> [join]
//         -> gather_gcn(t<n2) -> sage_out(fused SAGE gather + GEMM + l2norm)
// ---------------------------------------------------------------------------

#define H 128
#define MAXN0 131072
#define MAXN2 16384
#define MAXE  1048576
#define GROWS 64
#define SW 132
#define RST 132   // row stride for fused sage smem rows
#define XST 72

__device__ __align__(16) __half g_xWh[(size_t)MAXN0 * H];
__device__ __align__(16) __half g_g1h[(size_t)MAXN0 * H];
__device__ __align__(16) float  g_g1f[(size_t)MAXN2 * H];
__device__ __align__(16) int    g_hd [2 * MAXN2];      // [2t]=count(int), [2t+1]=degx(float bits)
__device__ __align__(16) int    g_off[MAXN2 + 4];
__device__ __align__(16) int    g_esrc[MAXE];
__device__ __align__(16) float  g_ew  [MAXE];
__device__ __align__(16) float  g_wst [MAXE];          // staged edge weights

__device__ __forceinline__ int clamp_n1(const int* p, int N0) {
    int v = *p;
    if (v <= 0 || v > N0) v = N0;
    return v;
}

__device__ __forceinline__ void tf32split(float f, uint32_t& hi, uint32_t& lo) {
    uint32_t h;
    asm("cvt.rna.tf32.f32 %0, %1;" : "=r"(h) : "f"(f));
    float r = f - __uint_as_float(h);
    asm("cvt.rna.tf32.f32 %0, %1;" : "=r"(lo) : "f"(r));
    hi = h;
}

__device__ __forceinline__ float4 h4_to_f4(uint2 raw) {
    __half2 h0 = *reinterpret_cast<__half2*>(&raw.x);
    __half2 h1 = *reinterpret_cast<__half2*>(&raw.y);
    float2 f0 = __half22float2(h0);
    float2 f1 = __half22float2(h1);
    return make_float4(f0.x, f0.y, f1.x, f1.y);
}

__device__ __forceinline__ uint2 f4_to_h4(float4 v) {
    __half2 h0 = __floats2half2_rn(v.x, v.y);
    __half2 h1 = __floats2half2_rn(v.z, v.w);
    uint2 r;
    r.x = *reinterpret_cast<uint32_t*>(&h0);
    r.y = *reinterpret_cast<uint32_t*>(&h1);
    return r;
}

#define MMA(d, a0, a1, a2, a3, b0, b1)                                        \
    asm volatile(                                                             \
        "mma.sync.aligned.m16n8k8.row.col.f32.tf32.tf32.f32 "                 \
        "{%0,%1,%2,%3},{%4,%5,%6,%7},{%8,%9},{%0,%1,%2,%3};"                  \
        : "+f"(d[0]), "+f"(d[1]), "+f"(d[2]), "+f"(d[3])                      \
        : "r"(a0), "r"(a1), "r"(a2), "r"(a3), "r"(b0), "r"(b1))

// ---- K1: histogram + weighted degree + weight staging -------------------------
__global__ void k_hist(const float* __restrict__ attr, const int* __restrict__ eid,
                       const int* __restrict__ tgt, int E, int n2) {
    int e = blockIdx.x * blockDim.x + threadIdx.x;
    if (e >= E) return;
    int t = __ldg(&tgt[e]);
    float w = __ldg(&attr[__ldg(&eid[e])]);
    g_wst[e] = w;
    if (t < n2) {
        atomicAdd(&g_hd[2 * t], 1);
        atomicAdd((float*)&g_hd[2 * t + 1], w);
    }
}

// ---- K2: exclusive scan, single block, vectorized IO --------------------------
__global__ void __launch_bounds__(1024) k_scan(int n2) {
    extern __shared__ int shcnt[];       // MAXN2 ints (64 KB, dynamic)
    __shared__ int wsum[32];
    int tid = threadIdx.x, lane = tid & 31, wid = tid >> 5;

    // stage counts: int4 covers 2 targets (count at .x and .z)
    const int4* hd4 = (const int4*)g_hd;
    for (int v = tid; v < MAXN2 / 2; v += 1024) {
        int4 q = hd4[v];
        *(int2*)&shcnt[2 * v] = make_int2(q.x, q.z);
    }
    __syncthreads();

    int base = tid * 16;
    int vals[16];
    int local = 0;
#pragma unroll
    for (int i4 = 0; i4 < 4; ++i4) {
        int4 q = *(const int4*)&shcnt[base + i4 * 4];
        int c[4] = {q.x, q.y, q.z, q.w};
#pragma unroll
        for (int j = 0; j < 4; ++j) { vals[i4 * 4 + j] = local; local += c[j]; }
    }
    int inc = local;
#pragma unroll
    for (int off = 1; off < 32; off <<= 1) {
        int nb = __shfl_up_sync(0xffffffffu, inc, off);
        if (lane >= off) inc += nb;
    }
    if (lane == 31) wsum[wid] = inc;
    __syncthreads();
    if (wid == 0) {
        int s = wsum[lane];
#pragma unroll
        for (int off = 1; off < 32; off <<= 1) {
            int nb = __shfl_up_sync(0xffffffffu, s, off);
            if (lane >= off) s += nb;
        }
        wsum[lane] = s;
    }
    __syncthreads();
    int excl = ((wid > 0) ? wsum[wid - 1] : 0) + inc - local;
#pragma unroll
    for (int i4 = 0; i4 < 4; ++i4) {
        int4 q = make_int4(excl + vals[i4 * 4], excl + vals[i4 * 4 + 1],
                           excl + vals[i4 * 4 + 2], excl + vals[i4 * 4 + 3]);
        *(int4*)&shcnt[base + i4 * 4] = q;
    }
    int total = wsum[31];
    __syncthreads();
    int4* off4 = (int4*)g_off;
    for (int v = tid; v < MAXN2 / 4; v += 1024)
        off4[v] = *(const int4*)&shcnt[4 * v];
    if (tid == 0) g_off[n2] = total;
}

// ---- K3: scatter edges into CSR (countdown on histogram), inline rsqrt --------
__global__ void k_scatter(const int* __restrict__ src, const int* __restrict__ tgt,
                          int E, int n2) {
    int e = blockIdx.x * blockDim.x + threadIdx.x;
    if (e >= E) return;
    int t = __ldg(&tgt[e]);
    if (t >= n2) return;
    int old = atomicAdd(&g_hd[2 * t], -1);
    int pos = g_off[t] + old - 1;
    int s = __ldg(&src[e]);
    float w = __ldg(&g_wst[e]);
    float dt = rsqrtf(1.f + __int_as_float(__ldg(&g_hd[2 * t + 1])));
    float ds = (s < n2) ? rsqrtf(1.f + __int_as_float(__ldg(&g_hd[2 * s + 1]))) : 1.f;
    g_esrc[pos] = s;
    g_ew[pos] = ds * w * dt;
}

// ---- K4: xW = x @ W^T via tf32 TC, fp16 output (rows < n1) --------------------
__global__ void __launch_bounds__(256) k_gemm_tc(
    const float* __restrict__ x, const float* __restrict__ W,
    const int* __restrict__ n1p, int N0) {
    extern __shared__ float sm[];
    float* xs = sm;
    float* ws = sm + 128 * XST;

    int n1 = clamp_n1(n1p, N0);
    int row0 = blockIdx.x * 128;
    if (row0 >= n1) return;

    int tid = threadIdx.x, lane = tid & 31, warp = tid >> 5;
    int wm = warp >> 1, wn = warp & 1;
    int lq = lane >> 2, lr = lane & 3;

    float acc[2][8][4];
#pragma unroll
    for (int mi = 0; mi < 2; ++mi)
#pragma unroll
        for (int ni = 0; ni < 8; ++ni)
#pragma unroll
            for (int j = 0; j < 4; ++j) acc[mi][ni][j] = 0.f;

    for (int kc = 0; kc < H; kc += 64) {
        if (kc) __syncthreads();
#pragma unroll
        for (int it = 0; it < 8; ++it) {
            int f4 = it * 256 + tid;
            int r = f4 >> 4, k4 = f4 & 15;
            int row = row0 + r;
            float4 v = make_float4(0.f, 0.f, 0.f, 0.f);
            if (row < N0) v = *(const float4*)&x[(size_t)row * H + kc + k4 * 4];
            *(float4*)&xs[r * XST + k4 * 4] = v;
            float4 wv = *(const float4*)&W[(size_t)r * H + kc + k4 * 4];
            *(float4*)&ws[r * XST + k4 * 4] = wv;
        }
        __syncthreads();

#pragma unroll
        for (int ks = 0; ks < 8; ++ks) {
            int kb = ks * 8 + lr;
            uint32_t ah[2][4], al[2][4];
#pragma unroll
            for (int mi = 0; mi < 2; ++mi) {
                int r = wm * 32 + mi * 16 + lq;
                tf32split(xs[r * XST + kb],           ah[mi][0], al[mi][0]);
                tf32split(xs[(r + 8) * XST + kb],     ah[mi][1], al[mi][1]);
                tf32split(xs[r * XST + kb + 4],       ah[mi][2], al[mi][2]);
                tf32split(xs[(r + 8) * XST + kb + 4], ah[mi][3], al[mi][3]);
            }
#pragma unroll
            for (int ni = 0; ni < 8; ++ni) {
                int n = wn * 64 + ni * 8 + lq;
                uint32_t bh0, bl0, bh1, bl1;
                tf32split(ws[n * XST + kb],     bh0, bl0);
                tf32split(ws[n * XST + kb + 4], bh1, bl1);
#pragma unroll
                for (int mi = 0; mi < 2; ++mi) {
                    MMA(acc[mi][ni], ah[mi][0], ah[mi][1], ah[mi][2], ah[mi][3], bh0, bh1);
                    MMA(acc[mi][ni], ah[mi][0], ah[mi][1], ah[mi][2], ah[mi][3], bl0, bl1);
                    MMA(acc[mi][ni], al[mi][0], al[mi][1], al[mi][2], al[mi][3], bh0, bh1);
                }
            }
        }
    }

#pragma unroll
    for (int mi = 0; mi < 2; ++mi) {
        int r0 = row0 + wm * 32 + mi * 16 + lq;
#pragma unroll
        for (int ni = 0; ni < 8; ++ni) {
            int col = wn * 64 + ni * 8 + lr * 2;
            if (r0 < n1) {
                __half2 h = __floats2half2_rn(acc[mi][ni][0], acc[mi][ni][1]);
                *(__half2*)&g_xWh[(size_t)r0 * H + col] = h;
            }
            if (r0 + 8 < n1) {
                __half2 h = __floats2half2_rn(acc[mi][ni][2], acc[mi][ni][3]);
                *(__half2*)&g_xWh[(size_t)(r0 + 8) * H + col] = h;
            }
        }
    }
}

// ---- K5 (stream2): tail g1h[n2..n1) = xWh + b ---------------------------------
__global__ void k_tail(const float* __restrict__ b, const int* __restrict__ n1p,
                       int N0, int n2) {
    int gid = blockIdx.x * blockDim.x + threadIdx.x;
    int row = n2 + (gid >> 5);
    int n1 = clamp_n1(n1p, N0);
    if (row >= n1) return;
    int c = (gid & 31) * 4;
    float4 xw = h4_to_f4(*(const uint2*)&g_xWh[(size_t)row * H + c]);
    float4 bb = *(const float4*)&b[c];
    xw.x += bb.x; xw.y += bb.y; xw.z += bb.z; xw.w += bb.w;
    *(uint2*)&g_g1h[(size_t)row * H + c] = f4_to_h4(xw);
}

// ---- K6: GCN gather (t<n2 only), warp per target ------------------------------
__global__ void __launch_bounds__(256) k_gather_gcn(const float* __restrict__ b, int n2) {
    int t = blockIdx.x * 8 + (threadIdx.x >> 5);
    if (t >= n2) return;
    int lane = threadIdx.x & 31;
    int c = lane * 4;
    float4 bb = *(const float4*)&b[c];
    float4 xw = h4_to_f4(*(const uint2*)&g_xWh[(size_t)t * H + c]);

    int base = __ldg(&g_off[t]);
    int end  = __ldg(&g_off[t + 1]);
    float4 a0 = make_float4(0.f, 0.f, 0.f, 0.f);
    float4 a1 = a0, a2 = a0, a3 = a0;

    for (int i0 = base; i0 < end; i0 += 32) {
        int idx = i0 + lane;
        int s = 0; float w = 0.f;
        if (idx < end) { s = __ldg(&g_esrc[idx]); w = __ldg(&g_ew[idx]); }
        int cnt = min(32, end - i0);
        int j = 0;
        for (; j + 4 <= cnt; j += 4) {
            int   s0 = __shfl_sync(0xffffffffu, s, j);
            float w0 = __shfl_sync(0xffffffffu, w, j);
            int   s1 = __shfl_sync(0xffffffffu, s, j + 1);
            float w1 = __shfl_sync(0xffffffffu, w, j + 1);
            int   s2 = __shfl_sync(0xffffffffu, s, j + 2);
            float w2 = __shfl_sync(0xffffffffu, w, j + 2);
            int   s3 = __shfl_sync(0xffffffffu, s, j + 3);
            float w3 = __shfl_sync(0xffffffffu, w, j + 3);
            float4 v0 = h4_to_f4(*(const uint2*)&g_xWh[(size_t)s0 * H + c]);
            float4 v1 = h4_to_f4(*(const uint2*)&g_xWh[(size_t)s1 * H + c]);
            float4 v2 = h4_to_f4(*(const uint2*)&g_xWh[(size_t)s2 * H + c]);
            float4 v3 = h4_to_f4(*(const uint2*)&g_xWh[(size_t)s3 * H + c]);
            a0.x += w0 * v0.x; a0.y += w0 * v0.y; a0.z += w0 * v0.z; a0.w += w0 * v0.w;
            a1.x += w1 * v1.x; a1.y += w1 * v1.y; a1.z += w1 * v1.z; a1.w += w1 * v1.w;
            a2.x += w2 * v2.x; a2.y += w2 * v2.y; a2.z += w2 * v2.z; a2.w += w2 * v2.w;
            a3.x += w3 * v3.x; a3.y += w3 * v3.y; a3.z += w3 * v3.z; a3.w += w3 * v3.w;
        }
        for (; j < cnt; ++j) {
            int   s0 = __shfl_sync(0xffffffffu, s, j);
            float w0 = __shfl_sync(0xffffffffu, w, j);
            float4 v0 = h4_to_f4(*(const uint2*)&g_xWh[(size_t)s0 * H + c]);
            a0.x += w0 * v0.x; a0.y += w0 * v0.y; a0.z += w0 * v0.z; a0.w += w0 * v0.w;
        }
    }
    float d2 = 1.f / (1.f + __int_as_float(g_hd[2 * t + 1]));
    float4 o;
    o.x = (a0.x + a1.x) + (a2.x + a3.x) + xw.x * d2 + bb.x;
    o.y = (a0.y + a1.y) + (a2.y + a3.y) + xw.y * d2 + bb.y;
    o.z = (a0.z + a1.z) + (a2.z + a3.z) + xw.z * d2 + bb.z;
    o.w = (a0.w + a1.w) + (a2.w + a3.w) + xw.w * d2 + bb.w;
    *(float4*)&g_g1f[(size_t)t * H + c] = o;
    *(uint2*)&g_g1h[(size_t)t * H + c] = f4_to_h4(o);
}

// ---- K7: fused SAGE gather + out GEMM + l2norm --------------------------------
__global__ void __launch_bounds__(512) k_sage_out(
    const float* __restrict__ Wl, const float* __restrict__ bl,
    const float* __restrict__ Wr, int n2, float* __restrict__ out) {
    extern __shared__ float sm[];
    float* Wlt  = sm;                       // H*SW
    float* Wrt  = Wlt  + H * SW;            // H*SW
    float* mrow = Wrt  + H * SW;            // GROWS*RST (mean rows, row-major)
    float* grow = mrow + GROWS * RST;       // GROWS*RST (g1 rows)
    float* psum = grow + GROWS * RST;       // GROWS*16
    float* scl  = psum + GROWS * 16;        // GROWS

    int row0 = blockIdx.x * GROWS;
    int tid = threadIdx.x, lane = tid & 31, warp = tid >> 5;  // 16 warps

    for (int idx = tid; idx < H * H; idx += 512) {
        int j = idx >> 7, k = idx & 127;
        Wlt[k * SW + j] = Wl[idx];
        Wrt[k * SW + j] = Wr[idx];
    }

    // SAGE gather: each warp handles 4 local rows
    int c = lane * 4;
#pragma unroll
    for (int q = 0; q < 4; ++q) {
        int r = warp * 4 + q;
        int t = row0 + r;
        if (t < n2) {
            float4 g = *(const float4*)&g_g1f[(size_t)t * H + c];
            *(float4*)&grow[r * RST + c] = g;
            int base = __ldg(&g_off[t]);
            int end  = __ldg(&g_off[t + 1]);
            float4 a0 = make_float4(0.f, 0.f, 0.f, 0.f);
            float4 a1 = a0, a2 = a0, a3 = a0;
            for (int i0 = base; i0 < end; i0 += 32) {
                int idx = i0 + lane;
                int s = 0;
                if (idx < end) s = __ldg(&g_esrc[idx]);
                int cnt = min(32, end - i0);
                int j = 0;
                for (; j + 4 <= cnt; j += 4) {
                    int s0 = __shfl_sync(0xffffffffu, s, j);
                    int s1 = __shfl_sync(0xffffffffu, s, j + 1);
                    int s2 = __shfl_sync(0xffffffffu, s, j + 2);
                    int s3 = __shfl_sync(0xffffffffu, s, j + 3);
                    float4 v0 = h4_to_f4(*(const uint2*)&g_g1h[(size_t)s0 * H + c]);
                    float4 v1 = h4_to_f4(*(const uint2*)&g_g1h[(size_t)s1 * H + c]);
                    float4 v2 = h4_to_f4(*(const uint2*)&g_g1h[(size_t)s2 * H + c]);
                    float4 v3 = h4_to_f4(*(const uint2*)&g_g1h[(size_t)s3 * H + c]);
                    a0.x += v0.x; a0.y += v0.y; a0.z += v0.z; a0.w += v0.w;
                    a1.x += v1.x; a1.y += v1.y; a1.z += v1.z; a1.w += v1.w;
                    a2.x += v2.x; a2.y += v2.y; a2.z += v2.z; a2.w += v2.w;
                    a3.x += v3.x; a3.y += v3.y; a3.z += v3.z; a3.w += v3.w;
                }
                for (; j < cnt; ++j) {
                    int s0 = __shfl_sync(0xffffffffu, s, j);
                    float4 v0 = h4_to_f4(*(const uint2*)&g_g1h[(size_t)s0 * H + c]);
                    a0.x += v0.x; a0.y += v0.y; a0.z += v0.z; a0.w += v0.w;
                }
            }
            float inv = 1.f / fmaxf((float)(end - base), 1.f);
            float4 m;
            m.x = ((a0.x + a1.x) + (a2.x + a3.x)) * inv;
            m.y = ((a0.y + a1.y) + (a2.y + a3.y)) * inv;
            m.z = ((a0.z + a1.z) + (a2.z + a3.z)) * inv;
            m.w = ((a0.w + a1.w) + (a2.w + a3.w)) * inv;
            *(float4*)&mrow[r * RST + c] = m;
        } else {
            float4 z = make_float4(0.f, 0.f, 0.f, 0.f);
            *(float4*)&grow[r * RST + c] = z;
            *(float4*)&mrow[r * RST + c] = z;
        }
    }
    __syncthreads();

    // out GEMM: 512 threads, thread tile 2 rows x 8 cols
    int col_t = tid & 15;      // cols [col_t*8, col_t*8+8)
    int row_t = tid >> 4;      // 0..31, rows [row_t*2, row_t*2+2)
    float acc[2][8];
#pragma unroll
    for (int j = 0; j < 8; ++j) {
        float bv = bl[col_t * 8 + j];
        acc[0][j] = bv; acc[1][j] = bv;
    }

    for (int k = 0; k < H; ++k) {
        float am0 = mrow[(row_t * 2) * RST + k];
        float am1 = mrow[(row_t * 2 + 1) * RST + k];
        float ag0 = grow[(row_t * 2) * RST + k];
        float ag1 = grow[(row_t * 2 + 1) * RST + k];
        float4 l0 = *(const float4*)&Wlt[k * SW + col_t * 8];
        float4 l1 = *(const float4*)&Wlt[k * SW + col_t * 8 + 4];
        float4 r0 = *(const float4*)&Wrt[k * SW + col_t * 8];
        float4 r1 = *(const float4*)&Wrt[k * SW + col_t * 8 + 4];
        float wl[8] = {l0.x, l0.y, l0.z, l0.w, l1.x, l1.y, l1.z, l1.w};
        float wr[8] = {r0.x, r0.y, r0.z, r0.w, r1.x, r1.y, r1.z, r1.w};
#pragma unroll
        for (int j = 0; j < 8; ++j) {
            acc[0][j] += am0 * wl[j] + ag0 * wr[j];
            acc[1][j] += am1 * wl[j] + ag1 * wr[j];
        }
    }

#pragma unroll
    for (int i = 0; i < 2; ++i) {
        float loc = 0.f;
#pragma unroll
        for (int j = 0; j < 8; ++j) loc += acc[i][j] * acc[i][j];
        psum[(row_t * 2 + i) * 16 + col_t] = loc;
    }
    __syncthreads();
    if (tid < GROWS) {
        float ssum = 0.f;
#pragma unroll
        for (int cc = 0; cc < 16; ++cc) ssum += psum[tid * 16 + cc];
        scl[tid] = 1.f / fmaxf(sqrtf(ssum), 1e-12f);
    }
    __syncthreads();

#pragma unroll
    for (int i = 0; i < 2; ++i) {
        int row = row0 + row_t * 2 + i;
        if (row < n2) {
            float sc = scl[row_t * 2 + i];
            float4 o0 = make_float4(acc[i][0] * sc, acc[i][1] * sc,
                                    acc[i][2] * sc, acc[i][3] * sc);
            float4 o1 = make_float4(acc[i][4] * sc, acc[i][5] * sc,
                                    acc[i][6] * sc, acc[i][7] * sc);
            *(float4*)&out[(size_t)row * H + col_t * 8]     = o0;
            *(float4*)&out[(size_t)row * H + col_t * 8 + 4] = o1;
        }
    }
}

// ---------------------------------------------------------------------------
extern "C" void kernel_launch(void* const* d_in, const int* in_sizes, int n_in,
                              void* d_out, int out_size) {
    const float* x     = (const float*)d_in[0];
    const float* attr  = (const float*)d_in[1];
    const int*   e_id1 = (const int*)d_in[3];
    const int*   src1  = (const int*)d_in[6];
    const int*   tgt1  = (const int*)d_in[7];
    const int*   n1p   = (const int*)d_in[8];
    const float* gcn_W = (const float*)d_in[10];
    const float* gcn_b = (const float*)d_in[11];
    const float* Wl1   = (const float*)d_in[15];
    const float* bl1   = (const float*)d_in[16];
    const float* Wr1   = (const float*)d_in[17];
    float* out = (float*)d_out;

    int N0 = in_sizes[0] / H;  if (N0 > MAXN0) N0 = MAXN0;
    int E1 = in_sizes[3];      if (E1 > MAXE)  E1 = MAXE;
    int n2 = out_size / H;     if (n2 > MAXN2) n2 = MAXN2;

    constexpr int SMEM_GEMM = 128 * XST * 2 * 4;
    constexpr int SMEM_SCAN = MAXN2 * 4;
    constexpr int SMEM_SOUT = (2 * H * SW + 2 * GROWS * RST + GROWS * 16 + GROWS) * 4;
    cudaFuncSetAttribute(k_gemm_tc, cudaFuncAttributeMaxDynamicSharedMemorySize, SMEM_GEMM);
    cudaFuncSetAttribute(k_scan, cudaFuncAttributeMaxDynamicSharedMemorySize, SMEM_SCAN);
    cudaFuncSetAttribute(k_sage_out, cudaFuncAttributeMaxDynamicSharedMemorySize, SMEM_SOUT);

    void* p_hd;
    cudaGetSymbolAddress(&p_hd, g_hd);

    cudaStream_t s2;
    cudaStreamCreateWithFlags(&s2, cudaStreamNonBlocking);
    cudaEvent_t evFork, evGemm;
    cudaEventCreateWithFlags(&evFork, cudaEventDisableTiming);
    cudaEventCreateWithFlags(&evGemm, cudaEventDisableTiming);

    // Fork: GEMM + tail on side stream.
    cudaEventRecord(evFork, 0);
    cudaStreamWaitEvent(s2, evFork, 0);
    k_gemm_tc<<<(N0 + 127) / 128, 256, SMEM_GEMM, s2>>>(x, gcn_W, n1p, N0);
    {
        int tailRows = N0 - n2; if (tailRows < 0) tailRows = 0;
        if (tailRows > 0)
            k_tail<<<(tailRows * 32 + 255) / 256, 256, 0, s2>>>(gcn_b, n1p, N0, n2);
    }
    cudaEventRecord(evGemm, s2);

    // Main stream: edge preprocessing.
    cudaMemsetAsync(p_hd, 0, (size_t)2 * MAXN2 * 4, 0);
    k_hist<<<(E1 + 255) / 256, 256>>>(attr, e_id1, tgt1, E1, n2);
    k_scan<<<1, 1024, SMEM_SCAN>>>(n2);
    k_scatter<<<(E1 + 255) / 256, 256>>>(src1, tgt1, E1, n2);

    cudaStreamWaitEvent(0, evGemm, 0);  // join

    k_gather_gcn<<<(n2 + 7) / 8, 256>>>(gcn_b, n2);
    k_sage_out<<<(n2 + GROWS - 1) / GROWS, 512, SMEM_SOUT>>>(Wl1, bl1, Wr1, n2, out);
}

// round 7
// speedup vs baseline: 1.0796x; 1.0796x over previous
#include <cuda_runtime.h>
#include <cuda_fp16.h>
#include <cstdint>

// ---------------------------------------------------------------------------
// GlobalGNN layer-1-only pipeline:
//   s2  : xW = x@gcn_W^T (tf32 TC GEMM, fp16 out)
//   main: k_preproc (persistent, grid-barrier):
//           zero -> hist+stage -> dinv || scan(block0) -> countdown scatter
//   join: gather_gcn (t<n1, tail inline) -> gather_sage -> sage_out
// Gather operands fp16, all accumulation fp32.
// ---------------------------------------------------------------------------

#define H 128
#define MAXN0 131072
#define MAXN2 16384
#define MAXE  1048576
#define GROWS 64
#define SW 132
#define SX 68
#define XST 72
#define PRE_BLOCKS 112
#define PRE_THREADS 512

__device__ __align__(16) __half g_xWh[(size_t)MAXN0 * H];
__device__ __align__(16) __half g_g1h[(size_t)MAXN0 * H];
__device__ __align__(16) float  g_g1f[(size_t)MAXN2 * H];
__device__ __align__(16) float  g_s  [(size_t)MAXN2 * H];
__device__ __align__(16) int    g_cnt [MAXN2];
__device__ __align__(16) float  g_degx[MAXN2];
__device__ __align__(16) float  g_dinv[MAXN2];
__device__ __align__(16) int    g_off [MAXN2 + 4];
__device__ __align__(16) int    g_esrc[MAXE];
__device__ __align__(16) float  g_ew  [MAXE];
__device__ __align__(16) float  g_wst [MAXE];
__device__ unsigned g_barCnt = 0;
__device__ unsigned g_barGen = 0;

__device__ __forceinline__ void grid_barrier(int nblocks) {
    __syncthreads();
    if (threadIdx.x == 0) {
        unsigned gen = atomicAdd(&g_barGen, 0u);
        __threadfence();
        unsigned old = atomicAdd(&g_barCnt, 1u);
        if (old == (unsigned)nblocks - 1u) {
            g_barCnt = 0;
            __threadfence();
            atomicAdd(&g_barGen, 1u);
        } else {
            while (atomicAdd(&g_barGen, 0u) == gen) { }
        }
        __threadfence();
    }
    __syncthreads();
}

__device__ __forceinline__ int clamp_n1(const int* p, int N0) {
    int v = *p;
    if (v <= 0 || v > N0) v = N0;
    return v;
}

__device__ __forceinline__ void tf32split(float f, uint32_t& hi, uint32_t& lo) {
    uint32_t h;
    asm("cvt.rna.tf32.f32 %0, %1;" : "=r"(h) : "f"(f));
    float r = f - __uint_as_float(h);
    asm("cvt.rna.tf32.f32 %0, %1;" : "=r"(lo) : "f"(r));
    hi = h;
}

__device__ __forceinline__ float4 h4_to_f4(uint2 raw) {
    __half2 h0 = *reinterpret_cast<__half2*>(&raw.x);
    __half2 h1 = *reinterpret_cast<__half2*>(&raw.y);
    float2 f0 = __half22float2(h0);
    float2 f1 = __half22float2(h1);
    return make_float4(f0.x, f0.y, f1.x, f1.y);
}

__device__ __forceinline__ uint2 f4_to_h4(float4 v) {
    __half2 h0 = __floats2half2_rn(v.x, v.y);
    __half2 h1 = __floats2half2_rn(v.z, v.w);
    uint2 r;
    r.x = *reinterpret_cast<uint32_t*>(&h0);
    r.y = *reinterpret_cast<uint32_t*>(&h1);
    return r;
}

#define MMA(d, a0, a1, a2, a3, b0, b1)                                        \
    asm volatile(                                                             \
        "mma.sync.aligned.m16n8k8.row.col.f32.tf32.tf32.f32 "                 \
        "{%0,%1,%2,%3},{%4,%5,%6,%7},{%8,%9},{%0,%1,%2,%3};"                  \
        : "+f"(d[0]), "+f"(d[1]), "+f"(d[2]), "+f"(d[3])                      \
        : "r"(a0), "r"(a1), "r"(a2), "r"(a3), "r"(b0), "r"(b1))

// ---- K1: persistent preprocessing (zero -> hist -> dinv/scan -> scatter) ------
__global__ void __launch_bounds__(PRE_THREADS) k_preproc(
    const float* __restrict__ attr, const int* __restrict__ eid,
    const int* __restrict__ src, const int* __restrict__ tgt,
    int E, int n2) {
    extern __shared__ int sh[];   // MAXN2 ints (only block 0 uses)
    int tid = threadIdx.x;
    int gtid = blockIdx.x * PRE_THREADS + tid;
    const int NT = PRE_BLOCKS * PRE_THREADS;

    // phase 0: zero counters (full MAXN2 so the scan can vector-load blindly)
    for (int i = gtid; i < MAXN2; i += NT) { g_cnt[i] = 0; g_degx[i] = 0.f; }
    grid_barrier(PRE_BLOCKS);

    // phase 1: histogram + weighted degree + weight staging
    for (int e = gtid; e < E; e += NT) {
        int t = __ldg(&tgt[e]);
        float w = __ldg(&attr[__ldg(&eid[e])]);
        g_wst[e] = w;
        if (t < n2) {
            atomicAdd(&g_cnt[t], 1);
            atomicAdd(&g_degx[t], w);
        }
    }
    grid_barrier(PRE_BLOCKS);

    // phase 2: dinv everywhere; block 0 additionally does the exclusive scan
    for (int i = gtid; i < n2; i += NT) g_dinv[i] = rsqrtf(1.f + g_degx[i]);
    if (blockIdx.x == 0) {
        __shared__ int wsum[16];
        int lane = tid & 31, wid = tid >> 5;
        int4* c4 = (int4*)g_cnt;
        for (int v = tid; v < MAXN2 / 4; v += PRE_THREADS)
            ((int4*)sh)[v] = c4[v];
        __syncthreads();
        int base = tid * 32;
        int vals[32];
        int local = 0;
#pragma unroll
        for (int i4 = 0; i4 < 8; ++i4) {
            int4 q = *(const int4*)&sh[base + i4 * 4];
            int cc[4] = {q.x, q.y, q.z, q.w};
#pragma unroll
            for (int j = 0; j < 4; ++j) { vals[i4 * 4 + j] = local; local += cc[j]; }
        }
        int inc = local;
#pragma unroll
        for (int off = 1; off < 32; off <<= 1) {
            int nb = __shfl_up_sync(0xffffffffu, inc, off);
            if (lane >= off) inc += nb;
        }
        if (lane == 31) wsum[wid] = inc;
        __syncthreads();
        if (wid == 0 && lane < 16) {
            int s = wsum[lane];
#pragma unroll
            for (int off = 1; off < 16; off <<= 1) {
                int nb = __shfl_up_sync(0xffffu, s, off);
                if (lane >= off) s += nb;
            }
            wsum[lane] = s;
        }
        __syncthreads();
        int excl = ((wid > 0) ? wsum[wid - 1] : 0) + inc - local;
#pragma unroll
        for (int i4 = 0; i4 < 8; ++i4) {
            int4 q = make_int4(excl + vals[i4 * 4],     excl + vals[i4 * 4 + 1],
                               excl + vals[i4 * 4 + 2], excl + vals[i4 * 4 + 3]);
            *(int4*)&sh[base + i4 * 4] = q;
        }
        int total = wsum[15];
        __syncthreads();
        int4* off4 = (int4*)g_off;
        for (int v = tid; v < MAXN2 / 4; v += PRE_THREADS)
            off4[v] = ((const int4*)sh)[v];
        if (tid == 0) g_off[n2] = total;
    }
    grid_barrier(PRE_BLOCKS);

    // phase 3: scatter into CSR (countdown on g_cnt), precompute norm
    for (int e = gtid; e < E; e += NT) {
        int t = __ldg(&tgt[e]);
        if (t >= n2) continue;
        int old = atomicAdd(&g_cnt[t], -1);
        int pos = g_off[t] + old - 1;
        int s = __ldg(&src[e]);
        float w = g_wst[e];
        float ds = (s < n2) ? g_dinv[s] : 1.f;
        g_esrc[pos] = s;
        g_ew[pos] = ds * w * g_dinv[t];
    }
}

// ---- K2: xW = x @ W^T via tf32 TC, fp16 output (rows < n1) --------------------
__global__ void __launch_bounds__(256) k_gemm_tc(
    const float* __restrict__ x, const float* __restrict__ W,
    const int* __restrict__ n1p, int N0) {
    extern __shared__ float sm[];
    float* xs = sm;
    float* ws = sm + 128 * XST;

    int n1 = clamp_n1(n1p, N0);
    int row0 = blockIdx.x * 128;
    if (row0 >= n1) return;

    int tid = threadIdx.x, lane = tid & 31, warp = tid >> 5;
    int wm = warp >> 1, wn = warp & 1;
    int lq = lane >> 2, lr = lane & 3;

    float acc[2][8][4];
#pragma unroll
    for (int mi = 0; mi < 2; ++mi)
#pragma unroll
        for (int ni = 0; ni < 8; ++ni)
#pragma unroll
            for (int j = 0; j < 4; ++j) acc[mi][ni][j] = 0.f;

    for (int kc = 0; kc < H; kc += 64) {
        if (kc) __syncthreads();
#pragma unroll
        for (int it = 0; it < 8; ++it) {
            int f4 = it * 256 + tid;
            int r = f4 >> 4, k4 = f4 & 15;
            int row = row0 + r;
            float4 v = make_float4(0.f, 0.f, 0.f, 0.f);
            if (row < N0) v = *(const float4*)&x[(size_t)row * H + kc + k4 * 4];
            *(float4*)&xs[r * XST + k4 * 4] = v;
            float4 wv = *(const float4*)&W[(size_t)r * H + kc + k4 * 4];
            *(float4*)&ws[r * XST + k4 * 4] = wv;
        }
        __syncthreads();

#pragma unroll
        for (int ks = 0; ks < 8; ++ks) {
            int kb = ks * 8 + lr;
            uint32_t ah[2][4], al[2][4];
#pragma unroll
            for (int mi = 0; mi < 2; ++mi) {
                int r = wm * 32 + mi * 16 + lq;
                tf32split(xs[r * XST + kb],           ah[mi][0], al[mi][0]);
                tf32split(xs[(r + 8) * XST + kb],     ah[mi][1], al[mi][1]);
                tf32split(xs[r * XST + kb + 4],       ah[mi][2], al[mi][2]);
                tf32split(xs[(r + 8) * XST + kb + 4], ah[mi][3], al[mi][3]);
            }
#pragma unroll
            for (int ni = 0; ni < 8; ++ni) {
                int n = wn * 64 + ni * 8 + lq;
                uint32_t bh0, bl0, bh1, bl1;
                tf32split(ws[n * XST + kb],     bh0, bl0);
                tf32split(ws[n * XST + kb + 4], bh1, bl1);
#pragma unroll
                for (int mi = 0; mi < 2; ++mi) {
                    MMA(acc[mi][ni], ah[mi][0], ah[mi][1], ah[mi][2], ah[mi][3], bh0, bh1);
                    MMA(acc[mi][ni], ah[mi][0], ah[mi][1], ah[mi][2], ah[mi][3], bl0, bl1);
                    MMA(acc[mi][ni], al[mi][0], al[mi][1], al[mi][2], al[mi][3], bh0, bh1);
                }
            }
        }
    }

#pragma unroll
    for (int mi = 0; mi < 2; ++mi) {
        int r0 = row0 + wm * 32 + mi * 16 + lq;
#pragma unroll
        for (int ni = 0; ni < 8; ++ni) {
            int col = wn * 64 + ni * 8 + lr * 2;
            if (r0 < n1) {
                __half2 h = __floats2half2_rn(acc[mi][ni][0], acc[mi][ni][1]);
                *(__half2*)&g_xWh[(size_t)r0 * H + col] = h;
            }
            if (r0 + 8 < n1) {
                __half2 h = __floats2half2_rn(acc[mi][ni][2], acc[mi][ni][3]);
                *(__half2*)&g_xWh[(size_t)(r0 + 8) * H + col] = h;
            }
        }
    }
}

// ---- K3: GCN gather (t<n2) + tail (n2<=t<n1), warp per target -----------------
__global__ void __launch_bounds__(256) k_gather_gcn(
    const float* __restrict__ b, const int* __restrict__ n1p, int N0, int n2) {
    int t = blockIdx.x * 8 + (threadIdx.x >> 5);
    int n1 = clamp_n1(n1p, N0);
    if (t >= n1) return;
    int lane = threadIdx.x & 31;
    int c = lane * 4;
    float4 bb = *(const float4*)&b[c];
    float4 xw = h4_to_f4(*(const uint2*)&g_xWh[(size_t)t * H + c]);

    if (t >= n2) {
        xw.x += bb.x; xw.y += bb.y; xw.z += bb.z; xw.w += bb.w;
        *(uint2*)&g_g1h[(size_t)t * H + c] = f4_to_h4(xw);
        return;
    }

    int base = __ldg(&g_off[t]);
    int end  = __ldg(&g_off[t + 1]);
    float4 a0 = make_float4(0.f, 0.f, 0.f, 0.f);
    float4 a1 = a0, a2 = a0, a3 = a0;

    for (int i0 = base; i0 < end; i0 += 32) {
        int idx = i0 + lane;
        int s = 0; float w = 0.f;
        if (idx < end) { s = __ldg(&g_esrc[idx]); w = __ldg(&g_ew[idx]); }
        int cnt = min(32, end - i0);
        int j = 0;
        for (; j + 4 <= cnt; j += 4) {
            int   s0 = __shfl_sync(0xffffffffu, s, j);
            float w0 = __shfl_sync(0xffffffffu, w, j);
            int   s1 = __shfl_sync(0xffffffffu, s, j + 1);
            float w1 = __shfl_sync(0xffffffffu, w, j + 1);
            int   s2 = __shfl_sync(0xffffffffu, s, j + 2);
            float w2 = __shfl_sync(0xffffffffu, w, j + 2);
            int   s3 = __shfl_sync(0xffffffffu, s, j + 3);
            float w3 = __shfl_sync(0xffffffffu, w, j + 3);
            float4 v0 = h4_to_f4(*(const uint2*)&g_xWh[(size_t)s0 * H + c]);
            float4 v1 = h4_to_f4(*(const uint2*)&g_xWh[(size_t)s1 * H + c]);
            float4 v2 = h4_to_f4(*(const uint2*)&g_xWh[(size_t)s2 * H + c]);
            float4 v3 = h4_to_f4(*(const uint2*)&g_xWh[(size_t)s3 * H + c]);
            a0.x += w0 * v0.x; a0.y += w0 * v0.y; a0.z += w0 * v0.z; a0.w += w0 * v0.w;
            a1.x += w1 * v1.x; a1.y += w1 * v1.y; a1.z += w1 * v1.z; a1.w += w1 * v1.w;
            a2.x += w2 * v2.x; a2.y += w2 * v2.y; a2.z += w2 * v2.z; a2.w += w2 * v2.w;
            a3.x += w3 * v3.x; a3.y += w3 * v3.y; a3.z += w3 * v3.z; a3.w += w3 * v3.w;
        }
        for (; j < cnt; ++j) {
            int   s0 = __shfl_sync(0xffffffffu, s, j);
            float w0 = __shfl_sync(0xffffffffu, w, j);
            float4 v0 = h4_to_f4(*(const uint2*)&g_xWh[(size_t)s0 * H + c]);
            a0.x += w0 * v0.x; a0.y += w0 * v0.y; a0.z += w0 * v0.z; a0.w += w0 * v0.w;
        }
    }
    float d2 = 1.f / (1.f + g_degx[t]);
    float4 o;
    o.x = (a0.x + a1.x) + (a2.x + a3.x) + xw.x * d2 + bb.x;
    o.y = (a0.y + a1.y) + (a2.y + a3.y) + xw.y * d2 + bb.y;
    o.z = (a0.z + a1.z) + (a2.z + a3.z) + xw.z * d2 + bb.z;
    o.w = (a0.w + a1.w) + (a2.w + a3.w) + xw.w * d2 + bb.w;
    *(float4*)&g_g1f[(size_t)t * H + c] = o;
    *(uint2*)&g_g1h[(size_t)t * H + c] = f4_to_h4(o);
}

// ---- K4: SAGE gather: s[t] = mean(g1[src]) -------------------------------------
__global__ void __launch_bounds__(256) k_gather_sage(int n2) {
    int t = blockIdx.x * 8 + (threadIdx.x >> 5);
    if (t >= n2) return;
    int lane = threadIdx.x & 31;
    int c = lane * 4;
    int base = __ldg(&g_off[t]);
    int end  = __ldg(&g_off[t + 1]);
    float4 a0 = make_float4(0.f, 0.f, 0.f, 0.f);
    float4 a1 = a0, a2 = a0, a3 = a0;

    for (int i0 = base; i0 < end; i0 += 32) {
        int idx = i0 + lane;
        int s = 0;
        if (idx < end) s = __ldg(&g_esrc[idx]);
        int cnt = min(32, end - i0);
        int j = 0;
        for (; j + 4 <= cnt; j += 4) {
            int s0 = __shfl_sync(0xffffffffu, s, j);
            int s1 = __shfl_sync(0xffffffffu, s, j + 1);
            int s2 = __shfl_sync(0xffffffffu, s, j + 2);
            int s3 = __shfl_sync(0xffffffffu, s, j + 3);
            float4 v0 = h4_to_f4(*(const uint2*)&g_g1h[(size_t)s0 * H + c]);
            float4 v1 = h4_to_f4(*(const uint2*)&g_g1h[(size_t)s1 * H + c]);
            float4 v2 = h4_to_f4(*(const uint2*)&g_g1h[(size_t)s2 * H + c]);
            float4 v3 = h4_to_f4(*(const uint2*)&g_g1h[(size_t)s3 * H + c]);
            a0.x += v0.x; a0.y += v0.y; a0.z += v0.z; a0.w += v0.w;
            a1.x += v1.x; a1.y += v1.y; a1.z += v1.z; a1.w += v1.w;
            a2.x += v2.x; a2.y += v2.y; a2.z += v2.z; a2.w += v2.w;
            a3.x += v3.x; a3.y += v3.y; a3.z += v3.z; a3.w += v3.w;
        }
        for (; j < cnt; ++j) {
            int s0 = __shfl_sync(0xffffffffu, s, j);
            float4 v0 = h4_to_f4(*(const uint2*)&g_g1h[(size_t)s0 * H + c]);
            a0.x += v0.x; a0.y += v0.y; a0.z += v0.z; a0.w += v0.w;
        }
    }
    float inv = 1.f / fmaxf((float)(end - base), 1.f);
    float4 o;
    o.x = ((a0.x + a1.x) + (a2.x + a3.x)) * inv;
    o.y = ((a0.y + a1.y) + (a2.y + a3.y)) * inv;
    o.z = ((a0.z + a1.z) + (a2.z + a3.z)) * inv;
    o.w = ((a0.w + a1.w) + (a2.w + a3.w)) * inv;
    *(float4*)&g_s[(size_t)t * H + c] = o;
}

// ---- K5: out = l2norm( mean @ Wl^T + bl + g1 @ Wr^T ) --------------------------
__global__ void __launch_bounds__(256) k_sage_out(
    const float* __restrict__ Wl, const float* __restrict__ bl,
    const float* __restrict__ Wr, int n2, float* __restrict__ out) {
    extern __shared__ float sm[];
    float* Wlt  = sm;
    float* Wrt  = Wlt + H * SW;
    float* ms   = Wrt + H * SW;
    float* gs   = ms  + H * SX;
    float* psum = gs  + H * SX;
    float* scl  = psum + GROWS * 16;

    int row0 = blockIdx.x * GROWS;
    int tid = threadIdx.x;

    for (int idx = tid; idx < H * H; idx += 256) {
        int j = idx >> 7, k = idx & 127;
        Wlt[k * SW + j] = Wl[idx];
        Wrt[k * SW + j] = Wr[idx];
    }
    for (int idx = tid; idx < GROWS * H; idx += 256) {
        int r = idx >> 7, k = idx & 127;
        int row = row0 + r;
        if (row < n2) {
            size_t off = (size_t)row * H + k;
            ms[k * SX + r] = g_s[off];
            gs[k * SX + r] = g_g1f[off];
        } else {
            ms[k * SX + r] = 0.f;
            gs[k * SX + r] = 0.f;
        }
    }
    __syncthreads();

    int col_t = tid & 15;
    int row_t = tid >> 4;
    float acc[4][8];
#pragma unroll
    for (int j = 0; j < 8; ++j) {
        float bv = bl[col_t * 8 + j];
#pragma unroll
        for (int i = 0; i < 4; ++i) acc[i][j] = bv;
    }

    for (int k = 0; k < H; ++k) {
        float4 am4 = *(const float4*)&ms[k * SX + row_t * 4];
        float4 ag4 = *(const float4*)&gs[k * SX + row_t * 4];
        float4 l0 = *(const float4*)&Wlt[k * SW + col_t * 8];
        float4 l1 = *(const float4*)&Wlt[k * SW + col_t * 8 + 4];
        float4 r0 = *(const float4*)&Wrt[k * SW + col_t * 8];
        float4 r1 = *(const float4*)&Wrt[k * SW + col_t * 8 + 4];
        float am[4] = {am4.x, am4.y, am4.z, am4.w};
        float ag[4] = {ag4.x, ag4.y, ag4.z, ag4.w};
        float wl[8] = {l0.x, l0.y, l0.z, l0.w, l1.x, l1.y, l1.z, l1.w};
        float wr[8] = {r0.x, r0.y, r0.z, r0.w, r1.x, r1.y, r1.z, r1.w};
#pragma unroll
        for (int i = 0; i < 4; ++i)
#pragma unroll
            for (int j = 0; j < 8; ++j)
                acc[i][j] += am[i] * wl[j] + ag[i] * wr[j];
    }

#pragma unroll
    for (int i = 0; i < 4; ++i) {
        float loc = 0.f;
#pragma unroll
        for (int j = 0; j < 8; ++j) loc += acc[i][j] * acc[i][j];
        psum[(row_t * 4 + i) * 16 + col_t] = loc;
    }
    __syncthreads();
    if (tid < GROWS) {
        float ssum = 0.f;
#pragma unroll
        for (int cc = 0; cc < 16; ++cc) ssum += psum[tid * 16 + cc];
        scl[tid] = 1.f / fmaxf(sqrtf(ssum), 1e-12f);
    }
    __syncthreads();

#pragma unroll
    for (int i = 0; i < 4; ++i) {
        int row = row0 + row_t * 4 + i;
        if (row < n2) {
            float sc = scl[row_t * 4 + i];
            float4 o0 = make_float4(acc[i][0] * sc, acc[i][1] * sc,
                                    acc[i][2] * sc, acc[i][3] * sc);
            float4 o1 = make_float4(acc[i][4] * sc, acc[i][5] * sc,
                                    acc[i][6] * sc, acc[i][7] * sc);
            *(float4*)&out[(size_t)row * H + col_t * 8]     = o0;
            *(float4*)&out[(size_t)row * H + col_t * 8 + 4] = o1;
        }
    }
}

// ---------------------------------------------------------------------------
extern "C" void kernel_launch(void* const* d_in, const int* in_sizes, int n_in,
                              void* d_out, int out_size) {
    const float* x     = (const float*)d_in[0];
    const float* attr  = (const float*)d_in[1];
    const int*   e_id1 = (const int*)d_in[3];
    const int*   src1  = (const int*)d_in[6];
    const int*   tgt1  = (const int*)d_in[7];
    const int*   n1p   = (const int*)d_in[8];
    const float* gcn_W = (const float*)d_in[10];
    const float* gcn_b = (const float*)d_in[11];
    const float* Wl1   = (const float*)d_in[15];
    const float* bl1   = (const float*)d_in[16];
    const float* Wr1   = (const float*)d_in[17];
    float* out = (float*)d_out;

    int N0 = in_sizes[0] / H;  if (N0 > MAXN0) N0 = MAXN0;
    int E1 = in_sizes[3];      if (E1 > MAXE)  E1 = MAXE;
    int n2 = out_size / H;     if (n2 > MAXN2) n2 = MAXN2;

    constexpr int SMEM_GEMM = 128 * XST * 2 * 4;
    constexpr int SMEM_PRE  = MAXN2 * 4;
    constexpr int SMEM_K8 = (2 * H * SW + 2 * H * SX + GROWS * 16 + GROWS) * 4;
    cudaFuncSetAttribute(k_gemm_tc, cudaFuncAttributeMaxDynamicSharedMemorySize, SMEM_GEMM);
    cudaFuncSetAttribute(k_preproc, cudaFuncAttributeMaxDynamicSharedMemorySize, SMEM_PRE);
    cudaFuncSetAttribute(k_sage_out, cudaFuncAttributeMaxDynamicSharedMemorySize, SMEM_K8);

    cudaStream_t s2;
    cudaStreamCreateWithFlags(&s2, cudaStreamNonBlocking);
    cudaEvent_t evFork, evGemm;
    cudaEventCreateWithFlags(&evFork, cudaEventDisableTiming);
    cudaEventCreateWithFlags(&evGemm, cudaEventDisableTiming);

    // Fork: GEMM on side stream.
    cudaEventRecord(evFork, 0);
    cudaStreamWaitEvent(s2, evFork, 0);
    k_gemm_tc<<<(N0 + 127) / 128, 256, SMEM_GEMM, s2>>>(x, gcn_W, n1p, N0);
    cudaEventRecord(evGemm, s2);

    // Main stream: single persistent preprocessing kernel.
    k_preproc<<<PRE_BLOCKS, PRE_THREADS, SMEM_PRE>>>(attr, e_id1, src1, tgt1, E1, n2);

    cudaStreamWaitEvent(0, evGemm, 0);  // join

    k_gather_gcn<<<(N0 + 7) / 8, 256>>>(gcn_b, n1p, N0, n2);
    k_gather_sage<<<(n2 + 7) / 8, 256>>>(n2);
    k_sage_out<<<(n2 + GROWS - 1) / GROWS, 256, SMEM_K8>>>(Wl1, bl1, Wr1, n2, out);
}

// round 8
// speedup vs baseline: 1.2656x; 1.1722x over previous
#include <cuda_runtime.h>
#include <cuda_fp16.h>
#include <cstdint>

// ---------------------------------------------------------------------------
// GlobalGNN layer-1-only pipeline (round-5 structure + SAGE decomposition):
//   s2  : xW = x@gcn_W^T (tf32 TC GEMM, fp16 out)
//   main: memset(hd) -> hist(+stage w) -> scan(int4) -> scatter(countdown)
//   join: gather_gcn: agg[t]=SUM norm*xW[s]; p1[t]=SUM d2[s]*xW[s];
//                     g1=agg+xW[t]*d2[t]+b
//         sage2:      p2[t]=SUM_{s<n2} agg[s]; mean=(p1+p2)/cnt + b (cnt>0)
//         sage_out:   out = l2norm(mean@Wl^T + bl + g1@Wr^T)
// ---------------------------------------------------------------------------

#define H 128
#define MAXN0 131072
#define MAXN2 16384
#define MAXE  1048576
#define GROWS 64
#define SW 132
#define SX 68
#define XST 72

__device__ __align__(16) __half g_xWh [(size_t)MAXN0 * H];
__device__ __align__(16) __half g_aggh[(size_t)MAXN2 * H];
__device__ __align__(16) float  g_g1f [(size_t)MAXN2 * H];
__device__ __align__(16) float  g_p1f [(size_t)MAXN2 * H];
__device__ __align__(16) float  g_s   [(size_t)MAXN2 * H];
__device__ __align__(16) int    g_hd  [2 * MAXN2];   // [2t]=count, [2t+1]=degx bits
__device__ __align__(16) int    g_off [MAXN2 + 4];
__device__ __align__(16) int    g_esrc[MAXE];
__device__ __align__(16) float2 g_ewp [MAXE];        // (norm, d2[src])
__device__ __align__(16) float  g_wst [MAXE];

__device__ __forceinline__ int clamp_n1(const int* p, int N0) {
    int v = *p;
    if (v <= 0 || v > N0) v = N0;
    return v;
}

__device__ __forceinline__ void tf32split(float f, uint32_t& hi, uint32_t& lo) {
    uint32_t h;
    asm("cvt.rna.tf32.f32 %0, %1;" : "=r"(h) : "f"(f));
    float r = f - __uint_as_float(h);
    asm("cvt.rna.tf32.f32 %0, %1;" : "=r"(lo) : "f"(r));
    hi = h;
}

__device__ __forceinline__ float4 h4_to_f4(uint2 raw) {
    __half2 h0 = *reinterpret_cast<__half2*>(&raw.x);
    __half2 h1 = *reinterpret_cast<__half2*>(&raw.y);
    float2 f0 = __half22float2(h0);
    float2 f1 = __half22float2(h1);
    return make_float4(f0.x, f0.y, f1.x, f1.y);
}

__device__ __forceinline__ uint2 f4_to_h4(float4 v) {
    __half2 h0 = __floats2half2_rn(v.x, v.y);
    __half2 h1 = __floats2half2_rn(v.z, v.w);
    uint2 r;
    r.x = *reinterpret_cast<uint32_t*>(&h0);
    r.y = *reinterpret_cast<uint32_t*>(&h1);
    return r;
}

#define MMA(d, a0, a1, a2, a3, b0, b1)                                        \
    asm volatile(                                                             \
        "mma.sync.aligned.m16n8k8.row.col.f32.tf32.tf32.f32 "                 \
        "{%0,%1,%2,%3},{%4,%5,%6,%7},{%8,%9},{%0,%1,%2,%3};"                  \
        : "+f"(d[0]), "+f"(d[1]), "+f"(d[2]), "+f"(d[3])                      \
        : "r"(a0), "r"(a1), "r"(a2), "r"(a3), "r"(b0), "r"(b1))

// ---- K1: histogram + weighted degree + weight staging -------------------------
__global__ void k_hist(const float* __restrict__ attr, const int* __restrict__ eid,
                       const int* __restrict__ tgt, int E, int n2) {
    int e = blockIdx.x * blockDim.x + threadIdx.x;
    if (e >= E) return;
    int t = __ldg(&tgt[e]);
    float w = __ldg(&attr[__ldg(&eid[e])]);
    g_wst[e] = w;
    if (t < n2) {
        atomicAdd(&g_hd[2 * t], 1);
        atomicAdd((float*)&g_hd[2 * t + 1], w);
    }
}

// ---- K2: exclusive scan over counts (full MAXN2, int4 IO), single block -------
__global__ void __launch_bounds__(1024) k_scan(int n2) {
    extern __shared__ int sh[];          // MAXN2 ints (64 KB dynamic)
    __shared__ int wsum[32];
    int tid = threadIdx.x, lane = tid & 31, wid = tid >> 5;

    const int4* hd4 = (const int4*)g_hd;
    for (int v = tid; v < MAXN2 / 2; v += 1024) {
        int4 q = hd4[v];                 // covers targets 2v, 2v+1
        *(int2*)&sh[2 * v] = make_int2(q.x, q.z);
    }
    __syncthreads();

    int base = tid * 16;
    int vals[16];
    int local = 0;
#pragma unroll
    for (int i4 = 0; i4 < 4; ++i4) {
        int4 q = *(const int4*)&sh[base + i4 * 4];
        int cc[4] = {q.x, q.y, q.z, q.w};
#pragma unroll
        for (int j = 0; j < 4; ++j) { vals[i4 * 4 + j] = local; local += cc[j]; }
    }
    int inc = local;
#pragma unroll
    for (int off = 1; off < 32; off <<= 1) {
        int nb = __shfl_up_sync(0xffffffffu, inc, off);
        if (lane >= off) inc += nb;
    }
    if (lane == 31) wsum[wid] = inc;
    __syncthreads();
    if (wid == 0) {
        int s = wsum[lane];
#pragma unroll
        for (int off = 1; off < 32; off <<= 1) {
            int nb = __shfl_up_sync(0xffffffffu, s, off);
            if (lane >= off) s += nb;
        }
        wsum[lane] = s;
    }
    __syncthreads();
    int excl = ((wid > 0) ? wsum[wid - 1] : 0) + inc - local;
#pragma unroll
    for (int i4 = 0; i4 < 4; ++i4) {
        int4 q = make_int4(excl + vals[i4 * 4],     excl + vals[i4 * 4 + 1],
                           excl + vals[i4 * 4 + 2], excl + vals[i4 * 4 + 3]);
        *(int4*)&sh[base + i4 * 4] = q;
    }
    int total = wsum[31];
    __syncthreads();
    int4* off4 = (int4*)g_off;
    for (int v = tid; v < MAXN2 / 4; v += 1024)
        off4[v] = ((const int4*)sh)[v];
    if (tid == 0) g_off[n2] = total;     // counts beyond n2 are 0 -> consistent
}

// ---- K3: scatter into CSR (countdown), precompute norm + d2[src] --------------
__global__ void k_scatter(const int* __restrict__ src, const int* __restrict__ tgt,
                          int E, int n2) {
    int e = blockIdx.x * blockDim.x + threadIdx.x;
    if (e >= E) return;
    int t = __ldg(&tgt[e]);
    if (t >= n2) return;
    int old = atomicAdd(&g_hd[2 * t], -1);
    int pos = g_off[t] + old - 1;
    int s = __ldg(&src[e]);
    float w = __ldg(&g_wst[e]);
    float degt = __int_as_float(__ldg(&g_hd[2 * t + 1]));
    float dt = rsqrtf(1.f + degt);
    float ds = 1.f, ds2 = 1.f;
    if (s < n2) {
        float degs = __int_as_float(__ldg(&g_hd[2 * s + 1]));
        ds = rsqrtf(1.f + degs);
        ds2 = 1.f / (1.f + degs);
    }
    g_esrc[pos] = s;
    g_ewp[pos] = make_float2(ds * w * dt, ds2);
}

// ---- K4: xW = x @ W^T via tf32 TC, fp16 output (rows < n1) --------------------
__global__ void __launch_bounds__(256) k_gemm_tc(
    const float* __restrict__ x, const float* __restrict__ W,
    const int* __restrict__ n1p, int N0) {
    extern __shared__ float sm[];
    float* xs = sm;
    float* ws = sm + 128 * XST;

    int n1 = clamp_n1(n1p, N0);
    int row0 = blockIdx.x * 128;
    if (row0 >= n1) return;

    int tid = threadIdx.x, lane = tid & 31, warp = tid >> 5;
    int wm = warp >> 1, wn = warp & 1;
    int lq = lane >> 2, lr = lane & 3;

    float acc[2][8][4];
#pragma unroll
    for (int mi = 0; mi < 2; ++mi)
#pragma unroll
        for (int ni = 0; ni < 8; ++ni)
#pragma unroll
            for (int j = 0; j < 4; ++j) acc[mi][ni][j] = 0.f;

    for (int kc = 0; kc < H; kc += 64) {
        if (kc) __syncthreads();
#pragma unroll
        for (int it = 0; it < 8; ++it) {
            int f4 = it * 256 + tid;
            int r = f4 >> 4, k4 = f4 & 15;
            int row = row0 + r;
            float4 v = make_float4(0.f, 0.f, 0.f, 0.f);
            if (row < N0) v = *(const float4*)&x[(size_t)row * H + kc + k4 * 4];
            *(float4*)&xs[r * XST + k4 * 4] = v;
            float4 wv = *(const float4*)&W[(size_t)r * H + kc + k4 * 4];
            *(float4*)&ws[r * XST + k4 * 4] = wv;
        }
        __syncthreads();

#pragma unroll
        for (int ks = 0; ks < 8; ++ks) {
            int kb = ks * 8 + lr;
            uint32_t ah[2][4], al[2][4];
#pragma unroll
            for (int mi = 0; mi < 2; ++mi) {
                int r = wm * 32 + mi * 16 + lq;
                tf32split(xs[r * XST + kb],           ah[mi][0], al[mi][0]);
                tf32split(xs[(r + 8) * XST + kb],     ah[mi][1], al[mi][1]);
                tf32split(xs[r * XST + kb + 4],       ah[mi][2], al[mi][2]);
                tf32split(xs[(r + 8) * XST + kb + 4], ah[mi][3], al[mi][3]);
            }
#pragma unroll
            for (int ni = 0; ni < 8; ++ni) {
                int n = wn * 64 + ni * 8 + lq;
                uint32_t bh0, bl0, bh1, bl1;
                tf32split(ws[n * XST + kb],     bh0, bl0);
                tf32split(ws[n * XST + kb + 4], bh1, bl1);
#pragma unroll
                for (int mi = 0; mi < 2; ++mi) {
                    MMA(acc[mi][ni], ah[mi][0], ah[mi][1], ah[mi][2], ah[mi][3], bh0, bh1);
                    MMA(acc[mi][ni], ah[mi][0], ah[mi][1], ah[mi][2], ah[mi][3], bl0, bl1);
                    MMA(acc[mi][ni], al[mi][0], al[mi][1], al[mi][2], al[mi][3], bh0, bh1);
                }
            }
        }
    }

#pragma unroll
    for (int mi = 0; mi < 2; ++mi) {
        int r0 = row0 + wm * 32 + mi * 16 + lq;
#pragma unroll
        for (int ni = 0; ni < 8; ++ni) {
            int col = wn * 64 + ni * 8 + lr * 2;
            if (r0 < n1) {
                __half2 h = __floats2half2_rn(acc[mi][ni][0], acc[mi][ni][1]);
                *(__half2*)&g_xWh[(size_t)r0 * H + col] = h;
            }
            if (r0 + 8 < n1) {
                __half2 h = __floats2half2_rn(acc[mi][ni][2], acc[mi][ni][3]);
                *(__half2*)&g_xWh[(size_t)(r0 + 8) * H + col] = h;
            }
        }
    }
}

// ---- K5: GCN gather + SAGE partial p1 (t<n2), warp per target ------------------
__global__ void __launch_bounds__(256) k_gather_gcn(const float* __restrict__ b, int n2) {
    int t = blockIdx.x * 8 + (threadIdx.x >> 5);
    if (t >= n2) return;
    int lane = threadIdx.x & 31;
    int c = lane * 4;
    int base = __ldg(&g_off[t]);
    int end  = __ldg(&g_off[t + 1]);

    float4 ag0 = make_float4(0.f, 0.f, 0.f, 0.f), ag1 = ag0;
    float4 ap0 = ag0, ap1 = ag0;

    for (int i0 = base; i0 < end; i0 += 32) {
        int idx = i0 + lane;
        int s = 0; float2 wp = make_float2(0.f, 0.f);
        if (idx < end) { s = __ldg(&g_esrc[idx]); wp = __ldg(&g_ewp[idx]); }
        int cnt = min(32, end - i0);
        int j = 0;
        for (; j + 4 <= cnt; j += 4) {
            int   s0 = __shfl_sync(0xffffffffu, s, j);
            float w0 = __shfl_sync(0xffffffffu, wp.x, j);
            float u0 = __shfl_sync(0xffffffffu, wp.y, j);
            int   s1 = __shfl_sync(0xffffffffu, s, j + 1);
            float w1 = __shfl_sync(0xffffffffu, wp.x, j + 1);
            float u1 = __shfl_sync(0xffffffffu, wp.y, j + 1);
            int   s2 = __shfl_sync(0xffffffffu, s, j + 2);
            float w2 = __shfl_sync(0xffffffffu, wp.x, j + 2);
            float u2 = __shfl_sync(0xffffffffu, wp.y, j + 2);
            int   s3 = __shfl_sync(0xffffffffu, s, j + 3);
            float w3 = __shfl_sync(0xffffffffu, wp.x, j + 3);
            float u3 = __shfl_sync(0xffffffffu, wp.y, j + 3);
            float4 v0 = h4_to_f4(*(const uint2*)&g_xWh[(size_t)s0 * H + c]);
            float4 v1 = h4_to_f4(*(const uint2*)&g_xWh[(size_t)s1 * H + c]);
            float4 v2 = h4_to_f4(*(const uint2*)&g_xWh[(size_t)s2 * H + c]);
            float4 v3 = h4_to_f4(*(const uint2*)&g_xWh[(size_t)s3 * H + c]);
            ag0.x += w0 * v0.x; ag0.y += w0 * v0.y; ag0.z += w0 * v0.z; ag0.w += w0 * v0.w;
            ap0.x += u0 * v0.x; ap0.y += u0 * v0.y; ap0.z += u0 * v0.z; ap0.w += u0 * v0.w;
            ag1.x += w1 * v1.x; ag1.y += w1 * v1.y; ag1.z += w1 * v1.z; ag1.w += w1 * v1.w;
            ap1.x += u1 * v1.x; ap1.y += u1 * v1.y; ap1.z += u1 * v1.z; ap1.w += u1 * v1.w;
            ag0.x += w2 * v2.x; ag0.y += w2 * v2.y; ag0.z += w2 * v2.z; ag0.w += w2 * v2.w;
            ap0.x += u2 * v2.x; ap0.y += u2 * v2.y; ap0.z += u2 * v2.z; ap0.w += u2 * v2.w;
            ag1.x += w3 * v3.x; ag1.y += w3 * v3.y; ag1.z += w3 * v3.z; ag1.w += w3 * v3.w;
            ap1.x += u3 * v3.x; ap1.y += u3 * v3.y; ap1.z += u3 * v3.z; ap1.w += u3 * v3.w;
        }
        for (; j < cnt; ++j) {
            int   s0 = __shfl_sync(0xffffffffu, s, j);
            float w0 = __shfl_sync(0xffffffffu, wp.x, j);
            float u0 = __shfl_sync(0xffffffffu, wp.y, j);
            float4 v0 = h4_to_f4(*(const uint2*)&g_xWh[(size_t)s0 * H + c]);
            ag0.x += w0 * v0.x; ag0.y += w0 * v0.y; ag0.z += w0 * v0.z; ag0.w += w0 * v0.w;
            ap0.x += u0 * v0.x; ap0.y += u0 * v0.y; ap0.z += u0 * v0.z; ap0.w += u0 * v0.w;
        }
    }

    float4 agg = make_float4(ag0.x + ag1.x, ag0.y + ag1.y, ag0.z + ag1.z, ag0.w + ag1.w);
    float4 p1  = make_float4(ap0.x + ap1.x, ap0.y + ap1.y, ap0.z + ap1.z, ap0.w + ap1.w);
    float d2t = 1.f / (1.f + __int_as_float(g_hd[2 * t + 1]));
    float4 xw = h4_to_f4(*(const uint2*)&g_xWh[(size_t)t * H + c]);
    float4 bb = *(const float4*)&b[c];
    float4 g1;
    g1.x = agg.x + xw.x * d2t + bb.x;
    g1.y = agg.y + xw.y * d2t + bb.y;
    g1.z = agg.z + xw.z * d2t + bb.z;
    g1.w = agg.w + xw.w * d2t + bb.w;
    *(float4*)&g_g1f[(size_t)t * H + c] = g1;
    *(uint2*)&g_aggh[(size_t)t * H + c] = f4_to_h4(agg);
    *(float4*)&g_p1f[(size_t)t * H + c] = p1;
}

// ---- K6: SAGE p2 gather (only src<n2) + mean -----------------------------------
__global__ void __launch_bounds__(256) k_sage2(const float* __restrict__ b, int n2) {
    int t = blockIdx.x * 8 + (threadIdx.x >> 5);
    if (t >= n2) return;
    int lane = threadIdx.x & 31;
    int c = lane * 4;
    int base = __ldg(&g_off[t]);
    int end  = __ldg(&g_off[t + 1]);
    int cnt = end - base;

    float4 a0 = make_float4(0.f, 0.f, 0.f, 0.f), a1 = a0;

    for (int i0 = base; i0 < end; i0 += 32) {
        int idx = i0 + lane;
        int s = n2;   // sentinel: skipped
        if (idx < end) s = __ldg(&g_esrc[idx]);
        int cl = min(32, end - i0);
        int j = 0;
        for (; j + 4 <= cl; j += 4) {
            int s0 = __shfl_sync(0xffffffffu, s, j);
            int s1 = __shfl_sync(0xffffffffu, s, j + 1);
            int s2 = __shfl_sync(0xffffffffu, s, j + 2);
            int s3 = __shfl_sync(0xffffffffu, s, j + 3);
            if (s0 < n2) {
                float4 v = h4_to_f4(*(const uint2*)&g_aggh[(size_t)s0 * H + c]);
                a0.x += v.x; a0.y += v.y; a0.z += v.z; a0.w += v.w;
            }
            if (s1 < n2) {
                float4 v = h4_to_f4(*(const uint2*)&g_aggh[(size_t)s1 * H + c]);
                a1.x += v.x; a1.y += v.y; a1.z += v.z; a1.w += v.w;
            }
            if (s2 < n2) {
                float4 v = h4_to_f4(*(const uint2*)&g_aggh[(size_t)s2 * H + c]);
                a0.x += v.x; a0.y += v.y; a0.z += v.z; a0.w += v.w;
            }
            if (s3 < n2) {
                float4 v = h4_to_f4(*(const uint2*)&g_aggh[(size_t)s3 * H + c]);
                a1.x += v.x; a1.y += v.y; a1.z += v.z; a1.w += v.w;
            }
        }
        for (; j < cl; ++j) {
            int s0 = __shfl_sync(0xffffffffu, s, j);
            if (s0 < n2) {
                float4 v = h4_to_f4(*(const uint2*)&g_aggh[(size_t)s0 * H + c]);
                a0.x += v.x; a0.y += v.y; a0.z += v.z; a0.w += v.w;
            }
        }
    }

    float4 o = make_float4(0.f, 0.f, 0.f, 0.f);
    if (cnt > 0) {
        float sc = 1.f / (float)cnt;
        float4 p1 = *(const float4*)&g_p1f[(size_t)t * H + c];
        float4 bb = *(const float4*)&b[c];
        o.x = (p1.x + a0.x + a1.x) * sc + bb.x;
        o.y = (p1.y + a0.y + a1.y) * sc + bb.y;
        o.z = (p1.z + a0.z + a1.z) * sc + bb.z;
        o.w = (p1.w + a0.w + a1.w) * sc + bb.w;
    }
    *(float4*)&g_s[(size_t)t * H + c] = o;
}

// ---- K7: out = l2norm( mean @ Wl^T + bl + g1 @ Wr^T ) --------------------------
__global__ void __launch_bounds__(256) k_sage_out(
    const float* __restrict__ Wl, const float* __restrict__ bl,
    const float* __restrict__ Wr, int n2, float* __restrict__ out) {
    extern __shared__ float sm[];
    float* Wlt  = sm;
    float* Wrt  = Wlt + H * SW;
    float* ms   = Wrt + H * SW;
    float* gs   = ms  + H * SX;
    float* psum = gs  + H * SX;
    float* scl  = psum + GROWS * 16;

    int row0 = blockIdx.x * GROWS;
    int tid = threadIdx.x;

    for (int idx = tid; idx < H * H; idx += 256) {
        int j = idx >> 7, k = idx & 127;
        Wlt[k * SW + j] = Wl[idx];
        Wrt[k * SW + j] = Wr[idx];
    }
    for (int idx = tid; idx < GROWS * H; idx += 256) {
        int r = idx >> 7, k = idx & 127;
        int row = row0 + r;
        if (row < n2) {
            size_t off = (size_t)row * H + k;
            ms[k * SX + r] = g_s[off];
            gs[k * SX + r] = g_g1f[off];
        } else {
            ms[k * SX + r] = 0.f;
            gs[k * SX + r] = 0.f;
        }
    }
    __syncthreads();

    int col_t = tid & 15;
    int row_t = tid >> 4;
    float acc[4][8];
#pragma unroll
    for (int j = 0; j < 8; ++j) {
        float bv = bl[col_t * 8 + j];
#pragma unroll
        for (int i = 0; i < 4; ++i) acc[i][j] = bv;
    }

    for (int k = 0; k < H; ++k) {
        float4 am4 = *(const float4*)&ms[k * SX + row_t * 4];
        float4 ag4 = *(const float4*)&gs[k * SX + row_t * 4];
        float4 l0 = *(const float4*)&Wlt[k * SW + col_t * 8];
        float4 l1 = *(const float4*)&Wlt[k * SW + col_t * 8 + 4];
        float4 r0 = *(const float4*)&Wrt[k * SW + col_t * 8];
        float4 r1 = *(const float4*)&Wrt[k * SW + col_t * 8 + 4];
        float am[4] = {am4.x, am4.y, am4.z, am4.w};
        float ag[4] = {ag4.x, ag4.y, ag4.z, ag4.w};
        float wl[8] = {l0.x, l0.y, l0.z, l0.w, l1.x, l1.y, l1.z, l1.w};
        float wr[8] = {r0.x, r0.y, r0.z, r0.w, r1.x, r1.y, r1.z, r1.w};
#pragma unroll
        for (int i = 0; i < 4; ++i)
#pragma unroll
            for (int j = 0; j < 8; ++j)
                acc[i][j] += am[i] * wl[j] + ag[i] * wr[j];
    }

#pragma unroll
    for (int i = 0; i < 4; ++i) {
        float loc = 0.f;
#pragma unroll
        for (int j = 0; j < 8; ++j) loc += acc[i][j] * acc[i][j];
        psum[(row_t * 4 + i) * 16 + col_t] = loc;
    }
    __syncthreads();
    if (tid < GROWS) {
        float ssum = 0.f;
#pragma unroll
        for (int cc = 0; cc < 16; ++cc) ssum += psum[tid * 16 + cc];
        scl[tid] = 1.f / fmaxf(sqrtf(ssum), 1e-12f);
    }
    __syncthreads();

#pragma unroll
    for (int i = 0; i < 4; ++i) {
        int row = row0 + row_t * 4 + i;
        if (row < n2) {
            float sc = scl[row_t * 4 + i];
            float4 o0 = make_float4(acc[i][0] * sc, acc[i][1] * sc,
                                    acc[i][2] * sc, acc[i][3] * sc);
            float4 o1 = make_float4(acc[i][4] * sc, acc[i][5] * sc,
                                    acc[i][6] * sc, acc[i][7] * sc);
            *(float4*)&out[(size_t)row * H + col_t * 8]     = o0;
            *(float4*)&out[(size_t)row * H + col_t * 8 + 4] = o1;
        }
    }
}

// ---------------------------------------------------------------------------
extern "C" void kernel_launch(void* const* d_in, const int* in_sizes, int n_in,
                              void* d_out, int out_size) {
    const float* x     = (const float*)d_in[0];
    const float* attr  = (const float*)d_in[1];
    const int*   e_id1 = (const int*)d_in[3];
    const int*   src1  = (const int*)d_in[6];
    const int*   tgt1  = (const int*)d_in[7];
    const int*   n1p   = (const int*)d_in[8];
    const float* gcn_W = (const float*)d_in[10];
    const float* gcn_b = (const float*)d_in[11];
    const float* Wl1   = (const float*)d_in[15];
    const float* bl1   = (const float*)d_in[16];
    const float* Wr1   = (const float*)d_in[17];
    float* out = (float*)d_out;

    int N0 = in_sizes[0] / H;  if (N0 > MAXN0) N0 = MAXN0;
    int E1 = in_sizes[3];      if (E1 > MAXE)  E1 = MAXE;
    int n2 = out_size / H;     if (n2 > MAXN2) n2 = MAXN2;

    constexpr int SMEM_GEMM = 128 * XST * 2 * 4;
    constexpr int SMEM_SCAN = MAXN2 * 4;
    constexpr int SMEM_K8 = (2 * H * SW + 2 * H * SX + GROWS * 16 + GROWS) * 4;
    cudaFuncSetAttribute(k_gemm_tc, cudaFuncAttributeMaxDynamicSharedMemorySize, SMEM_GEMM);
    cudaFuncSetAttribute(k_scan, cudaFuncAttributeMaxDynamicSharedMemorySize, SMEM_SCAN);
    cudaFuncSetAttribute(k_sage_out, cudaFuncAttributeMaxDynamicSharedMemorySize, SMEM_K8);

    void* p_hd;
    cudaGetSymbolAddress(&p_hd, g_hd);

    cudaStream_t s2;
    cudaStreamCreateWithFlags(&s2, cudaStreamNonBlocking);
    cudaEvent_t evFork, evGemm;
    cudaEventCreateWithFlags(&evFork, cudaEventDisableTiming);
    cudaEventCreateWithFlags(&evGemm, cudaEventDisableTiming);

    // Fork: GEMM on side stream.
    cudaEventRecord(evFork, 0);
    cudaStreamWaitEvent(s2, evFork, 0);
    k_gemm_tc<<<(N0 + 127) / 128, 256, SMEM_GEMM, s2>>>(x, gcn_W, n1p, N0);
    cudaEventRecord(evGemm, s2);

    // Main stream: edge preprocessing.
    cudaMemsetAsync(p_hd, 0, (size_t)2 * MAXN2 * 4, 0);
    k_hist<<<(E1 + 255) / 256, 256>>>(attr, e_id1, tgt1, E1, n2);
    k_scan<<<1, 1024, SMEM_SCAN>>>(n2);
    k_scatter<<<(E1 + 255) / 256, 256>>>(src1, tgt1, E1, n2);

    cudaStreamWaitEvent(0, evGemm, 0);  // join

    k_gather_gcn<<<(n2 + 7) / 8, 256>>>(gcn_b, n2);
    k_sage2<<<(n2 + 7) / 8, 256>>>(gcn_b, n2);
    k_sage_out<<<(n2 + GROWS - 1) / GROWS, 256, SMEM_K8>>>(Wl1, bl1, Wr1, n2, out);
}

// round 9
// speedup vs baseline: 1.2776x; 1.0095x over previous
#include <cuda_runtime.h>
#include <cuda_fp16.h>
#include <cstdint>

// ---------------------------------------------------------------------------
// GlobalGNN layer-1-only pipeline (round-8 champion + ILP preprocessing):
//   s2  : xW = x@gcn_W^T (tf32 TC GEMM, fp16 out)
//   main: memset(hd) -> hist(x4 ILP) -> scan(count-only int4) -> scatter(x4 ILP)
//   join: gather_gcn (agg,p1,g1) -> sage2 (p2,mean) -> sage_out (GEMM+l2norm)
// ---------------------------------------------------------------------------

#define H 128
#define MAXN0 131072
#define MAXN2 16384
#define MAXE  1048576
#define GROWS 64
#define SW 132
#define SX 68
#define XST 72

__device__ __align__(16) __half g_xWh [(size_t)MAXN0 * H];
__device__ __align__(16) __half g_aggh[(size_t)MAXN2 * H];
__device__ __align__(16) float  g_g1f [(size_t)MAXN2 * H];
__device__ __align__(16) float  g_p1f [(size_t)MAXN2 * H];
__device__ __align__(16) float  g_s   [(size_t)MAXN2 * H];
__device__ __align__(16) int    g_hd  [2 * MAXN2];   // [i]=count, [MAXN2+i]=degx bits
__device__ __align__(16) int    g_off [MAXN2 + 4];
__device__ __align__(16) int    g_esrc[MAXE];
__device__ __align__(16) float2 g_ewp [MAXE];        // (norm, d2[src])
__device__ __align__(16) float  g_wst [MAXE];

__device__ __forceinline__ int clamp_n1(const int* p, int N0) {
    int v = *p;
    if (v <= 0 || v > N0) v = N0;
    return v;
}

__device__ __forceinline__ void tf32split(float f, uint32_t& hi, uint32_t& lo) {
    uint32_t h;
    asm("cvt.rna.tf32.f32 %0, %1;" : "=r"(h) : "f"(f));
    float r = f - __uint_as_float(h);
    asm("cvt.rna.tf32.f32 %0, %1;" : "=r"(lo) : "f"(r));
    hi = h;
}

__device__ __forceinline__ float4 h4_to_f4(uint2 raw) {
    __half2 h0 = *reinterpret_cast<__half2*>(&raw.x);
    __half2 h1 = *reinterpret_cast<__half2*>(&raw.y);
    float2 f0 = __half22float2(h0);
    float2 f1 = __half22float2(h1);
    return make_float4(f0.x, f0.y, f1.x, f1.y);
}

__device__ __forceinline__ uint2 f4_to_h4(float4 v) {
    __half2 h0 = __floats2half2_rn(v.x, v.y);
    __half2 h1 = __floats2half2_rn(v.z, v.w);
    uint2 r;
    r.x = *reinterpret_cast<uint32_t*>(&h0);
    r.y = *reinterpret_cast<uint32_t*>(&h1);
    return r;
}

#define MMA(d, a0, a1, a2, a3, b0, b1)                                        \
    asm volatile(                                                             \
        "mma.sync.aligned.m16n8k8.row.col.f32.tf32.tf32.f32 "                 \
        "{%0,%1,%2,%3},{%4,%5,%6,%7},{%8,%9},{%0,%1,%2,%3};"                  \
        : "+f"(d[0]), "+f"(d[1]), "+f"(d[2]), "+f"(d[3])                      \
        : "r"(a0), "r"(a1), "r"(a2), "r"(a3), "r"(b0), "r"(b1))

// ---- K1: histogram + weighted degree + weight staging, 4 edges/thread ---------
__global__ void k_hist(const float* __restrict__ attr, const int* __restrict__ eid,
                       const int* __restrict__ tgt, int E, int n2) {
    int base = (blockIdx.x * blockDim.x + threadIdx.x) * 4;
    if (base >= E) return;
    if (base + 4 <= E) {
        int4 t4  = *(const int4*)&tgt[base];
        int4 id4 = *(const int4*)&eid[base];
        float w0 = __ldg(&attr[id4.x]);
        float w1 = __ldg(&attr[id4.y]);
        float w2 = __ldg(&attr[id4.z]);
        float w3 = __ldg(&attr[id4.w]);
        *(float4*)&g_wst[base] = make_float4(w0, w1, w2, w3);
        if (t4.x < n2) { atomicAdd(&g_hd[t4.x], 1); atomicAdd((float*)&g_hd[MAXN2 + t4.x], w0); }
        if (t4.y < n2) { atomicAdd(&g_hd[t4.y], 1); atomicAdd((float*)&g_hd[MAXN2 + t4.y], w1); }
        if (t4.z < n2) { atomicAdd(&g_hd[t4.z], 1); atomicAdd((float*)&g_hd[MAXN2 + t4.z], w2); }
        if (t4.w < n2) { atomicAdd(&g_hd[t4.w], 1); atomicAdd((float*)&g_hd[MAXN2 + t4.w], w3); }
    } else {
        for (int e = base; e < E; ++e) {
            int t = __ldg(&tgt[e]);
            float w = __ldg(&attr[__ldg(&eid[e])]);
            g_wst[e] = w;
            if (t < n2) {
                atomicAdd(&g_hd[t], 1);
                atomicAdd((float*)&g_hd[MAXN2 + t], w);
            }
        }
    }
}

// ---- K2: exclusive scan over counts (extent n2, int4 IO), single block --------
__global__ void __launch_bounds__(1024) k_scan(int n2) {
    extern __shared__ int sh[];          // MAXN2 ints (64 KB dynamic)
    __shared__ int wsum[32];
    int tid = threadIdx.x, lane = tid & 31, wid = tid >> 5;

    int n2v = (n2 + 3) >> 2;             // int4 count
    const int4* cnt4 = (const int4*)g_hd;
    for (int v = tid; v < n2v; v += 1024)
        ((int4*)sh)[v] = cnt4[v];
    // zero the remainder so every thread's 16-elem window is defined
    for (int v = n2v + tid; v < MAXN2 / 4; v += 1024)
        ((int4*)sh)[v] = make_int4(0, 0, 0, 0);
    __syncthreads();

    int base = tid * 16;
    int vals[16];
    int local = 0;
#pragma unroll
    for (int i4 = 0; i4 < 4; ++i4) {
        int4 q = *(const int4*)&sh[base + i4 * 4];
        int cc[4] = {q.x, q.y, q.z, q.w};
#pragma unroll
        for (int j = 0; j < 4; ++j) { vals[i4 * 4 + j] = local; local += cc[j]; }
    }
    int inc = local;
#pragma unroll
    for (int off = 1; off < 32; off <<= 1) {
        int nb = __shfl_up_sync(0xffffffffu, inc, off);
        if (lane >= off) inc += nb;
    }
    if (lane == 31) wsum[wid] = inc;
    __syncthreads();
    if (wid == 0) {
        int s = wsum[lane];
#pragma unroll
        for (int off = 1; off < 32; off <<= 1) {
            int nb = __shfl_up_sync(0xffffffffu, s, off);
            if (lane >= off) s += nb;
        }
        wsum[lane] = s;
    }
    __syncthreads();
    int excl = ((wid > 0) ? wsum[wid - 1] : 0) + inc - local;
#pragma unroll
    for (int i4 = 0; i4 < 4; ++i4) {
        int4 q = make_int4(excl + vals[i4 * 4],     excl + vals[i4 * 4 + 1],
                           excl + vals[i4 * 4 + 2], excl + vals[i4 * 4 + 3]);
        *(int4*)&sh[base + i4 * 4] = q;
    }
    int total = wsum[31];
    __syncthreads();
    int4* off4 = (int4*)g_off;
    for (int v = tid; v < n2v; v += 1024)
        off4[v] = ((const int4*)sh)[v];
    if (tid == 0) g_off[n2] = total;
}

// ---- K3: scatter into CSR (countdown), 4 edges/thread --------------------------
__global__ void k_scatter(const int* __restrict__ src, const int* __restrict__ tgt,
                          int E, int n2) {
    int base = (blockIdx.x * blockDim.x + threadIdx.x) * 4;
    if (base >= E) return;
    int t[4], s[4];
    float w[4];
    int ne = min(4, E - base);
    if (ne == 4) {
        int4 t4 = *(const int4*)&tgt[base];
        int4 s4 = *(const int4*)&src[base];
        float4 w4 = *(const float4*)&g_wst[base];
        t[0] = t4.x; t[1] = t4.y; t[2] = t4.z; t[3] = t4.w;
        s[0] = s4.x; s[1] = s4.y; s[2] = s4.z; s[3] = s4.w;
        w[0] = w4.x; w[1] = w4.y; w[2] = w4.z; w[3] = w4.w;
    } else {
        for (int j = 0; j < ne; ++j) {
            t[j] = __ldg(&tgt[base + j]);
            s[j] = __ldg(&src[base + j]);
            w[j] = __ldg(&g_wst[base + j]);
        }
    }
    // issue independent atomics + offset loads first (MLP=4)
    int old[4], ofs[4];
    float degt[4], degs[4];
#pragma unroll
    for (int j = 0; j < 4; ++j) {
        if (j < ne && t[j] < n2) {
            old[j] = atomicAdd(&g_hd[t[j]], -1);
            ofs[j] = __ldg(&g_off[t[j]]);
            degt[j] = __int_as_float(__ldg(&g_hd[MAXN2 + t[j]]));
            degs[j] = (s[j] < n2) ? __int_as_float(__ldg(&g_hd[MAXN2 + s[j]])) : 0.f;
        } else {
            old[j] = 0; ofs[j] = 0; degt[j] = 0.f; degs[j] = 0.f;
        }
    }
#pragma unroll
    for (int j = 0; j < 4; ++j) {
        if (j < ne && t[j] < n2) {
            int pos = ofs[j] + old[j] - 1;
            float dt = rsqrtf(1.f + degt[j]);
            float ds = 1.f, ds2 = 1.f;
            if (s[j] < n2) {
                ds = rsqrtf(1.f + degs[j]);
                ds2 = 1.f / (1.f + degs[j]);
            }
            g_esrc[pos] = s[j];
            g_ewp[pos] = make_float2(ds * w[j] * dt, ds2);
        }
    }
}

// ---- K4: xW = x @ W^T via tf32 TC, fp16 output (rows < n1) --------------------
__global__ void __launch_bounds__(256) k_gemm_tc(
    const float* __restrict__ x, const float* __restrict__ W,
    const int* __restrict__ n1p, int N0) {
    extern __shared__ float sm[];
    float* xs = sm;
    float* ws = sm + 128 * XST;

    int n1 = clamp_n1(n1p, N0);
    int row0 = blockIdx.x * 128;
    if (row0 >= n1) return;

    int tid = threadIdx.x, lane = tid & 31, warp = tid >> 5;
    int wm = warp >> 1, wn = warp & 1;
    int lq = lane >> 2, lr = lane & 3;

    float acc[2][8][4];
#pragma unroll
    for (int mi = 0; mi < 2; ++mi)
#pragma unroll
        for (int ni = 0; ni < 8; ++ni)
#pragma unroll
            for (int j = 0; j < 4; ++j) acc[mi][ni][j] = 0.f;

    for (int kc = 0; kc < H; kc += 64) {
        if (kc) __syncthreads();
#pragma unroll
        for (int it = 0; it < 8; ++it) {
            int f4 = it * 256 + tid;
            int r = f4 >> 4, k4 = f4 & 15;
            int row = row0 + r;
            float4 v = make_float4(0.f, 0.f, 0.f, 0.f);
            if (row < N0) v = *(const float4*)&x[(size_t)row * H + kc + k4 * 4];
            *(float4*)&xs[r * XST + k4 * 4] = v;
            float4 wv = *(const float4*)&W[(size_t)r * H + kc + k4 * 4];
            *(float4*)&ws[r * XST + k4 * 4] = wv;
        }
        __syncthreads();

#pragma unroll
        for (int ks = 0; ks < 8; ++ks) {
            int kb = ks * 8 + lr;
            uint32_t ah[2][4], al[2][4];
#pragma unroll
            for (int mi = 0; mi < 2; ++mi) {
                int r = wm * 32 + mi * 16 + lq;
                tf32split(xs[r * XST + kb],           ah[mi][0], al[mi][0]);
                tf32split(xs[(r + 8) * XST + kb],     ah[mi][1], al[mi][1]);
                tf32split(xs[r * XST + kb + 4],       ah[mi][2], al[mi][2]);
                tf32split(xs[(r + 8) * XST + kb + 4], ah[mi][3], al[mi][3]);
            }
#pragma unroll
            for (int ni = 0; ni < 8; ++ni) {
                int n = wn * 64 + ni * 8 + lq;
                uint32_t bh0, bl0, bh1, bl1;
                tf32split(ws[n * XST + kb],     bh0, bl0);
                tf32split(ws[n * XST + kb + 4], bh1, bl1);
#pragma unroll
                for (int mi = 0; mi < 2; ++mi) {
                    MMA(acc[mi][ni], ah[mi][0], ah[mi][1], ah[mi][2], ah[mi][3], bh0, bh1);
                    MMA(acc[mi][ni], ah[mi][0], ah[mi][1], ah[mi][2], ah[mi][3], bl0, bl1);
                    MMA(acc[mi][ni], al[mi][0], al[mi][1], al[mi][2], al[mi][3], bh0, bh1);
                }
            }
        }
    }

#pragma unroll
    for (int mi = 0; mi < 2; ++mi) {
        int r0 = row0 + wm * 32 + mi * 16 + lq;
#pragma unroll
        for (int ni = 0; ni < 8; ++ni) {
            int col = wn * 64 + ni * 8 + lr * 2;
            if (r0 < n1) {
                __half2 h = __floats2half2_rn(acc[mi][ni][0], acc[mi][ni][1]);
                *(__half2*)&g_xWh[(size_t)r0 * H + col] = h;
            }
            if (r0 + 8 < n1) {
                __half2 h = __floats2half2_rn(acc[mi][ni][2], acc[mi][ni][3]);
                *(__half2*)&g_xWh[(size_t)(r0 + 8) * H + col] = h;
            }
        }
    }
}

// ---- K5: GCN gather + SAGE partial p1 (t<n2), warp per target ------------------
__global__ void __launch_bounds__(256) k_gather_gcn(const float* __restrict__ b, int n2) {
    int t = blockIdx.x * 8 + (threadIdx.x >> 5);
    if (t >= n2) return;
    int lane = threadIdx.x & 31;
    int c = lane * 4;
    int base = __ldg(&g_off[t]);
    int end  = __ldg(&g_off[t + 1]);

    float4 ag0 = make_float4(0.f, 0.f, 0.f, 0.f), ag1 = ag0;
    float4 ap0 = ag0, ap1 = ag0;

    for (int i0 = base; i0 < end; i0 += 32) {
        int idx = i0 + lane;
        int s = 0; float2 wp = make_float2(0.f, 0.f);
        if (idx < end) { s = __ldg(&g_esrc[idx]); wp = __ldg(&g_ewp[idx]); }
        int cnt = min(32, end - i0);
        int j = 0;
        for (; j + 4 <= cnt; j += 4) {
            int   s0 = __shfl_sync(0xffffffffu, s, j);
            float w0 = __shfl_sync(0xffffffffu, wp.x, j);
            float u0 = __shfl_sync(0xffffffffu, wp.y, j);
            int   s1 = __shfl_sync(0xffffffffu, s, j + 1);
            float w1 = __shfl_sync(0xffffffffu, wp.x, j + 1);
            float u1 = __shfl_sync(0xffffffffu, wp.y, j + 1);
            int   s2 = __shfl_sync(0xffffffffu, s, j + 2);
            float w2 = __shfl_sync(0xffffffffu, wp.x, j + 2);
            float u2 = __shfl_sync(0xffffffffu, wp.y, j + 2);
            int   s3 = __shfl_sync(0xffffffffu, s, j + 3);
            float w3 = __shfl_sync(0xffffffffu, wp.x, j + 3);
            float u3 = __shfl_sync(0xffffffffu, wp.y, j + 3);
            float4 v0 = h4_to_f4(*(const uint2*)&g_xWh[(size_t)s0 * H + c]);
            float4 v1 = h4_to_f4(*(const uint2*)&g_xWh[(size_t)s1 * H + c]);
            float4 v2 = h4_to_f4(*(const uint2*)&g_xWh[(size_t)s2 * H + c]);
            float4 v3 = h4_to_f4(*(const uint2*)&g_xWh[(size_t)s3 * H + c]);
            ag0.x += w0 * v0.x; ag0.y += w0 * v0.y; ag0.z += w0 * v0.z; ag0.w += w0 * v0.w;
            ap0.x += u0 * v0.x; ap0.y += u0 * v0.y; ap0.z += u0 * v0.z; ap0.w += u0 * v0.w;
            ag1.x += w1 * v1.x; ag1.y += w1 * v1.y; ag1.z += w1 * v1.z; ag1.w += w1 * v1.w;
            ap1.x += u1 * v1.x; ap1.y += u1 * v1.y; ap1.z += u1 * v1.z; ap1.w += u1 * v1.w;
            ag0.x += w2 * v2.x; ag0.y += w2 * v2.y; ag0.z += w2 * v2.z; ag0.w += w2 * v2.w;
            ap0.x += u2 * v2.x; ap0.y += u2 * v2.y; ap0.z += u2 * v2.z; ap0.w += u2 * v2.w;
            ag1.x += w3 * v3.x; ag1.y += w3 * v3.y; ag1.z += w3 * v3.z; ag1.w += w3 * v3.w;
            ap1.x += u3 * v3.x; ap1.y += u3 * v3.y; ap1.z += u3 * v3.z; ap1.w += u3 * v3.w;
        }
        for (; j < cnt; ++j) {
            int   s0 = __shfl_sync(0xffffffffu, s, j);
            float w0 = __shfl_sync(0xffffffffu, wp.x, j);
            float u0 = __shfl_sync(0xffffffffu, wp.y, j);
            float4 v0 = h4_to_f4(*(const uint2*)&g_xWh[(size_t)s0 * H + c]);
            ag0.x += w0 * v0.x; ag0.y += w0 * v0.y; ag0.z += w0 * v0.z; ag0.w += w0 * v0.w;
            ap0.x += u0 * v0.x; ap0.y += u0 * v0.y; ap0.z += u0 * v0.z; ap0.w += u0 * v0.w;
        }
    }

    float4 agg = make_float4(ag0.x + ag1.x, ag0.y + ag1.y, ag0.z + ag1.z, ag0.w + ag1.w);
    float4 p1  = make_float4(ap0.x + ap1.x, ap0.y + ap1.y, ap0.z + ap1.z, ap0.w + ap1.w);
    float d2t = 1.f / (1.f + __int_as_float(g_hd[MAXN2 + t]));
    float4 xw = h4_to_f4(*(const uint2*)&g_xWh[(size_t)t * H + c]);
    float4 bb = *(const float4*)&b[c];
    float4 g1;
    g1.x = agg.x + xw.x * d2t + bb.x;
    g1.y = agg.y + xw.y * d2t + bb.y;
    g1.z = agg.z + xw.z * d2t + bb.z;
    g1.w = agg.w + xw.w * d2t + bb.w;
    *(float4*)&g_g1f[(size_t)t * H + c] = g1;
    *(uint2*)&g_aggh[(size_t)t * H + c] = f4_to_h4(agg);
    *(float4*)&g_p1f[(size_t)t * H + c] = p1;
}

// ---- K6: SAGE p2 gather (only src<n2) + mean -----------------------------------
__global__ void __launch_bounds__(256) k_sage2(const float* __restrict__ b, int n2) {
    int t = blockIdx.x * 8 + (threadIdx.x >> 5);
    if (t >= n2) return;
    int lane = threadIdx.x & 31;
    int c = lane * 4;
    int base = __ldg(&g_off[t]);
    int end  = __ldg(&g_off[t + 1]);
    int cnt = end - base;

    float4 a0 = make_float4(0.f, 0.f, 0.f, 0.f), a1 = a0;

    for (int i0 = base; i0 < end; i0 += 32) {
        int idx = i0 + lane;
        int s = n2;   // sentinel: skipped
        if (idx < end) s = __ldg(&g_esrc[idx]);
        int cl = min(32, end - i0);
        int j = 0;
        for (; j + 4 <= cl; j += 4) {
            int s0 = __shfl_sync(0xffffffffu, s, j);
            int s1 = __shfl_sync(0xffffffffu, s, j + 1);
            int s2 = __shfl_sync(0xffffffffu, s, j + 2);
            int s3 = __shfl_sync(0xffffffffu, s, j + 3);
            if (s0 < n2) {
                float4 v = h4_to_f4(*(const uint2*)&g_aggh[(size_t)s0 * H + c]);
                a0.x += v.x; a0.y += v.y; a0.z += v.z; a0.w += v.w;
            }
            if (s1 < n2) {
                float4 v = h4_to_f4(*(const uint2*)&g_aggh[(size_t)s1 * H + c]);
                a1.x += v.x; a1.y += v.y; a1.z += v.z; a1.w += v.w;
            }
            if (s2 < n2) {
                float4 v = h4_to_f4(*(const uint2*)&g_aggh[(size_t)s2 * H + c]);
                a0.x += v.x; a0.y += v.y; a0.z += v.z; a0.w += v.w;
            }
            if (s3 < n2) {
                float4 v = h4_to_f4(*(const uint2*)&g_aggh[(size_t)s3 * H + c]);
                a1.x += v.x; a1.y += v.y; a1.z += v.z; a1.w += v.w;
            }
        }
        for (; j < cl; ++j) {
            int s0 = __shfl_sync(0xffffffffu, s, j);
            if (s0 < n2) {
                float4 v = h4_to_f4(*(const uint2*)&g_aggh[(size_t)s0 * H + c]);
                a0.x += v.x; a0.y += v.y; a0.z += v.z; a0.w += v.w;
            }
        }
    }

    float4 o = make_float4(0.f, 0.f, 0.f, 0.f);
    if (cnt > 0) {
        float sc = 1.f / (float)cnt;
        float4 p1 = *(const float4*)&g_p1f[(size_t)t * H + c];
        float4 bb = *(const float4*)&b[c];
        o.x = (p1.x + a0.x + a1.x) * sc + bb.x;
        o.y = (p1.y + a0.y + a1.y) * sc + bb.y;
        o.z = (p1.z + a0.z + a1.z) * sc + bb.z;
        o.w = (p1.w + a0.w + a1.w) * sc + bb.w;
    }
    *(float4*)&g_s[(size_t)t * H + c] = o;
}

// ---- K7: out = l2norm( mean @ Wl^T + bl + g1 @ Wr^T ) --------------------------
__global__ void __launch_bounds__(256) k_sage_out(
    const float* __restrict__ Wl, const float* __restrict__ bl,
    const float* __restrict__ Wr, int n2, float* __restrict__ out) {
    extern __shared__ float sm[];
    float* Wlt  = sm;
    float* Wrt  = Wlt + H * SW;
    float* ms   = Wrt + H * SW;
    float* gs   = ms  + H * SX;
    float* psum = gs  + H * SX;
    float* scl  = psum + GROWS * 16;

    int row0 = blockIdx.x * GROWS;
    int tid = threadIdx.x;

    for (int idx = tid; idx < H * H; idx += 256) {
        int j = idx >> 7, k = idx & 127;
        Wlt[k * SW + j] = Wl[idx];
        Wrt[k * SW + j] = Wr[idx];
    }
    for (int idx = tid; idx < GROWS * H; idx += 256) {
        int r = idx >> 7, k = idx & 127;
        int row = row0 + r;
        if (row < n2) {
            size_t off = (size_t)row * H + k;
            ms[k * SX + r] = g_s[off];
            gs[k * SX + r] = g_g1f[off];
        } else {
            ms[k * SX + r] = 0.f;
            gs[k * SX + r] = 0.f;
        }
    }
    __syncthreads();

    int col_t = tid & 15;
    int row_t = tid >> 4;
    float acc[4][8];
#pragma unroll
    for (int j = 0; j < 8; ++j) {
        float bv = bl[col_t * 8 + j];
#pragma unroll
        for (int i = 0; i < 4; ++i) acc[i][j] = bv;
    }

    for (int k = 0; k < H; ++k) {
        float4 am4 = *(const float4*)&ms[k * SX + row_t * 4];
        float4 ag4 = *(const float4*)&gs[k * SX + row_t * 4];
        float4 l0 = *(const float4*)&Wlt[k * SW + col_t * 8];
        float4 l1 = *(const float4*)&Wlt[k * SW + col_t * 8 + 4];
        float4 r0 = *(const float4*)&Wrt[k * SW + col_t * 8];
        float4 r1 = *(const float4*)&Wrt[k * SW + col_t * 8 + 4];
        float am[4] = {am4.x, am4.y, am4.z, am4.w};
        float ag[4] = {ag4.x, ag4.y, ag4.z, ag4.w};
        float wl[8] = {l0.x, l0.y, l0.z, l0.w, l1.x, l1.y, l1.z, l1.w};
        float wr[8] = {r0.x, r0.y, r0.z, r0.w, r1.x, r1.y, r1.z, r1.w};
#pragma unroll
        for (int i = 0; i < 4; ++i)
#pragma unroll
            for (int j = 0; j < 8; ++j)
                acc[i][j] += am[i] * wl[j] + ag[i] * wr[j];
    }

#pragma unroll
    for (int i = 0; i < 4; ++i) {
        float loc = 0.f;
#pragma unroll
        for (int j = 0; j < 8; ++j) loc += acc[i][j] * acc[i][j];
        psum[(row_t * 4 + i) * 16 + col_t] = loc;
    }
    __syncthreads();
    if (tid < GROWS) {
        float ssum = 0.f;
#pragma unroll
        for (int cc = 0; cc < 16; ++cc) ssum += psum[tid * 16 + cc];
        scl[tid] = 1.f / fmaxf(sqrtf(ssum), 1e-12f);
    }
    __syncthreads();

#pragma unroll
    for (int i = 0; i < 4; ++i) {
        int row = row0 + row_t * 4 + i;
        if (row < n2) {
            float sc = scl[row_t * 4 + i];
            float4 o0 = make_float4(acc[i][0] * sc, acc[i][1] * sc,
                                    acc[i][2] * sc, acc[i][3] * sc);
            float4 o1 = make_float4(acc[i][4] * sc, acc[i][5] * sc,
                                    acc[i][6] * sc, acc[i][7] * sc);
            *(float4*)&out[(size_t)row * H + col_t * 8]     = o0;
            *(float4*)&out[(size_t)row * H + col_t * 8 + 4] = o1;
        }
    }
}

// ---------------------------------------------------------------------------
extern "C" void kernel_launch(void* const* d_in, const int* in_sizes, int n_in,
                              void* d_out, int out_size) {
    const float* x     = (const float*)d_in[0];
    const float* attr  = (const float*)d_in[1];
    const int*   e_id1 = (const int*)d_in[3];
    const int*   src1  = (const int*)d_in[6];
    const int*   tgt1  = (const int*)d_in[7];
    const int*   n1p   = (const int*)d_in[8];
    const float* gcn_W = (const float*)d_in[10];
    const float* gcn_b = (const float*)d_in[11];
    const float* Wl1   = (const float*)d_in[15];
    const float* bl1   = (const float*)d_in[16];
    const float* Wr1   = (const float*)d_in[17];
    float* out = (float*)d_out;

    int N0 = in_sizes[0] / H;  if (N0 > MAXN0) N0 = MAXN0;
    int E1 = in_sizes[3];      if (E1 > MAXE)  E1 = MAXE;
    int n2 = out_size / H;     if (n2 > MAXN2) n2 = MAXN2;

    constexpr int SMEM_GEMM = 128 * XST * 2 * 4;
    constexpr int SMEM_SCAN = MAXN2 * 4;
    constexpr int SMEM_K8 = (2 * H * SW + 2 * H * SX + GROWS * 16 + GROWS) * 4;
    cudaFuncSetAttribute(k_gemm_tc, cudaFuncAttributeMaxDynamicSharedMemorySize, SMEM_GEMM);
    cudaFuncSetAttribute(k_scan, cudaFuncAttributeMaxDynamicSharedMemorySize, SMEM_SCAN);
    cudaFuncSetAttribute(k_sage_out, cudaFuncAttributeMaxDynamicSharedMemorySize, SMEM_K8);

    void* p_hd;
    cudaGetSymbolAddress(&p_hd, g_hd);

    cudaStream_t s2;
    cudaStreamCreateWithFlags(&s2, cudaStreamNonBlocking);
    cudaEvent_t evFork, evGemm;
    cudaEventCreateWithFlags(&evFork, cudaEventDisableTiming);
    cudaEventCreateWithFlags(&evGemm, cudaEventDisableTiming);

    // Fork: GEMM on side stream.
    cudaEventRecord(evFork, 0);
    cudaStreamWaitEvent(s2, evFork, 0);
    k_gemm_tc<<<(N0 + 127) / 128, 256, SMEM_GEMM, s2>>>(x, gcn_W, n1p, N0);
    cudaEventRecord(evGemm, s2);

    // Main stream: edge preprocessing.
    cudaMemsetAsync(p_hd, 0, (size_t)2 * MAXN2 * 4, 0);
    k_hist<<<(E1 + 1023) / 1024, 256>>>(attr, e_id1, tgt1, E1, n2);
    k_scan<<<1, 1024, SMEM_SCAN>>>(n2);
    k_scatter<<<(E1 + 1023) / 1024, 256>>>(src1, tgt1, E1, n2);

    cudaStreamWaitEvent(0, evGemm, 0);  // join

    k_gather_gcn<<<(n2 + 7) / 8, 256>>>(gcn_b, n2);
    k_sage2<<<(n2 + 7) / 8, 256>>>(gcn_b, n2);
    k_sage_out<<<(n2 + GROWS - 1) / GROWS, 256, SMEM_K8>>>(Wl1, bl1, Wr1, n2, out);
}

// round 10
// speedup vs baseline: 1.3228x; 1.0354x over previous
#include <cuda_runtime.h>
#include <cuda_fp16.h>
#include <cstdint>

// ---------------------------------------------------------------------------
// GlobalGNN layer-1-only pipeline:
//   s2  : xW = x@gcn_W^T (tf32 TC GEMM, fp16 out)
//   main: memset(hd) -> hist(x2) -> scan(count int4) -> scatter(x2, (s,w) only)
//   join: gather_gcn (agg,p1,g1; norm computed in-gather) -> sage2 -> sage_out
// ---------------------------------------------------------------------------

#define H 128
#define MAXN0 131072
#define MAXN2 16384
#define MAXE  1048576
#define GROWS 64
#define SW 132
#define SX 68
#define XST 72

__device__ __align__(16) __half g_xWh [(size_t)MAXN0 * H];
__device__ __align__(16) __half g_aggh[(size_t)MAXN2 * H];
__device__ __align__(16) float  g_g1f [(size_t)MAXN2 * H];
__device__ __align__(16) float  g_p1f [(size_t)MAXN2 * H];
__device__ __align__(16) float  g_s   [(size_t)MAXN2 * H];
__device__ __align__(16) int    g_hd  [2 * MAXN2];   // [i]=count, [MAXN2+i]=degx bits
__device__ __align__(16) int    g_off [MAXN2 + 4];
__device__ __align__(16) float2 g_epk [MAXE];        // (.x=src bits, .y=w)
__device__ __align__(16) float  g_wst [MAXE];

__device__ __forceinline__ int clamp_n1(const int* p, int N0) {
    int v = *p;
    if (v <= 0 || v > N0) v = N0;
    return v;
}

__device__ __forceinline__ void tf32split(float f, uint32_t& hi, uint32_t& lo) {
    uint32_t h;
    asm("cvt.rna.tf32.f32 %0, %1;" : "=r"(h) : "f"(f));
    float r = f - __uint_as_float(h);
    asm("cvt.rna.tf32.f32 %0, %1;" : "=r"(lo) : "f"(r));
    hi = h;
}

__device__ __forceinline__ float4 h4_to_f4(uint2 raw) {
    __half2 h0 = *reinterpret_cast<__half2*>(&raw.x);
    __half2 h1 = *reinterpret_cast<__half2*>(&raw.y);
    float2 f0 = __half22float2(h0);
    float2 f1 = __half22float2(h1);
    return make_float4(f0.x, f0.y, f1.x, f1.y);
}

__device__ __forceinline__ uint2 f4_to_h4(float4 v) {
    __half2 h0 = __floats2half2_rn(v.x, v.y);
    __half2 h1 = __floats2half2_rn(v.z, v.w);
    uint2 r;
    r.x = *reinterpret_cast<uint32_t*>(&h0);
    r.y = *reinterpret_cast<uint32_t*>(&h1);
    return r;
}

#define MMA(d, a0, a1, a2, a3, b0, b1)                                        \
    asm volatile(                                                             \
        "mma.sync.aligned.m16n8k8.row.col.f32.tf32.tf32.f32 "                 \
        "{%0,%1,%2,%3},{%4,%5,%6,%7},{%8,%9},{%0,%1,%2,%3};"                  \
        : "+f"(d[0]), "+f"(d[1]), "+f"(d[2]), "+f"(d[3])                      \
        : "r"(a0), "r"(a1), "r"(a2), "r"(a3), "r"(b0), "r"(b1))

// ---- K1: histogram + weighted degree + weight staging, 2 edges/thread ---------
__global__ void k_hist(const float* __restrict__ attr, const int* __restrict__ eid,
                       const int* __restrict__ tgt, int E, int n2) {
    int base = (blockIdx.x * blockDim.x + threadIdx.x) * 2;
    if (base >= E) return;
    if (base + 2 <= E) {
        int2 t2  = *(const int2*)&tgt[base];
        int2 id2 = *(const int2*)&eid[base];
        float w0 = __ldg(&attr[id2.x]);
        float w1 = __ldg(&attr[id2.y]);
        *(float2*)&g_wst[base] = make_float2(w0, w1);
        if (t2.x < n2) { atomicAdd(&g_hd[t2.x], 1); atomicAdd((float*)&g_hd[MAXN2 + t2.x], w0); }
        if (t2.y < n2) { atomicAdd(&g_hd[t2.y], 1); atomicAdd((float*)&g_hd[MAXN2 + t2.y], w1); }
    } else {
        int t = __ldg(&tgt[base]);
        float w = __ldg(&attr[__ldg(&eid[base])]);
        g_wst[base] = w;
        if (t < n2) {
            atomicAdd(&g_hd[t], 1);
            atomicAdd((float*)&g_hd[MAXN2 + t], w);
        }
    }
}

// ---- K2: exclusive scan over counts (extent n2, int4 IO), single block --------
__global__ void __launch_bounds__(1024) k_scan(int n2) {
    extern __shared__ int sh[];          // MAXN2 ints (64 KB dynamic)
    __shared__ int wsum[32];
    int tid = threadIdx.x, lane = tid & 31, wid = tid >> 5;

    int n2v = (n2 + 3) >> 2;
    const int4* cnt4 = (const int4*)g_hd;
    for (int v = tid; v < n2v; v += 1024)
        ((int4*)sh)[v] = cnt4[v];
    for (int v = n2v + tid; v < MAXN2 / 4; v += 1024)
        ((int4*)sh)[v] = make_int4(0, 0, 0, 0);
    __syncthreads();

    int base = tid * 16;
    int vals[16];
    int local = 0;
#pragma unroll
    for (int i4 = 0; i4 < 4; ++i4) {
        int4 q = *(const int4*)&sh[base + i4 * 4];
        int cc[4] = {q.x, q.y, q.z, q.w};
#pragma unroll
        for (int j = 0; j < 4; ++j) { vals[i4 * 4 + j] = local; local += cc[j]; }
    }
    int inc = local;
#pragma unroll
    for (int off = 1; off < 32; off <<= 1) {
        int nb = __shfl_up_sync(0xffffffffu, inc, off);
        if (lane >= off) inc += nb;
    }
    if (lane == 31) wsum[wid] = inc;
    __syncthreads();
    if (wid == 0) {
        int s = wsum[lane];
#pragma unroll
        for (int off = 1; off < 32; off <<= 1) {
            int nb = __shfl_up_sync(0xffffffffu, s, off);
            if (lane >= off) s += nb;
        }
        wsum[lane] = s;
    }
    __syncthreads();
    int excl = ((wid > 0) ? wsum[wid - 1] : 0) + inc - local;
#pragma unroll
    for (int i4 = 0; i4 < 4; ++i4) {
        int4 q = make_int4(excl + vals[i4 * 4],     excl + vals[i4 * 4 + 1],
                           excl + vals[i4 * 4 + 2], excl + vals[i4 * 4 + 3]);
        *(int4*)&sh[base + i4 * 4] = q;
    }
    int total = wsum[31];
    __syncthreads();
    int4* off4 = (int4*)g_off;
    for (int v = tid; v < n2v; v += 1024)
        off4[v] = ((const int4*)sh)[v];
    if (tid == 0) g_off[n2] = total;
}

// ---- K3: scatter into CSR (countdown), 2 edges/thread, packed (s,w) -----------
__global__ void k_scatter(const int* __restrict__ src, const int* __restrict__ tgt,
                          int E, int n2) {
    int base = (blockIdx.x * blockDim.x + threadIdx.x) * 2;
    if (base >= E) return;
    int t[2], s[2];
    float w[2];
    int ne = min(2, E - base);
    if (ne == 2) {
        int2 t2 = *(const int2*)&tgt[base];
        int2 s2 = *(const int2*)&src[base];
        float2 w2 = *(const float2*)&g_wst[base];
        t[0] = t2.x; t[1] = t2.y;
        s[0] = s2.x; s[1] = s2.y;
        w[0] = w2.x; w[1] = w2.y;
    } else {
        t[0] = __ldg(&tgt[base]); t[1] = n2;
        s[0] = __ldg(&src[base]); s[1] = 0;
        w[0] = __ldg(&g_wst[base]); w[1] = 0.f;
    }
    int old[2], ofs[2];
#pragma unroll
    for (int j = 0; j < 2; ++j) {
        if (t[j] < n2) {
            old[j] = atomicAdd(&g_hd[t[j]], -1);
            ofs[j] = __ldg(&g_off[t[j]]);
        } else { old[j] = 0; ofs[j] = 0; }
    }
#pragma unroll
    for (int j = 0; j < 2; ++j) {
        if (t[j] < n2) {
            int pos = ofs[j] + old[j] - 1;
            g_epk[pos] = make_float2(__int_as_float(s[j]), w[j]);
        }
    }
}

// ---- K4: xW = x @ W^T via tf32 TC, fp16 output (rows < n1) --------------------
__global__ void __launch_bounds__(256) k_gemm_tc(
    const float* __restrict__ x, const float* __restrict__ W,
    const int* __restrict__ n1p, int N0) {
    extern __shared__ float sm[];
    float* xs = sm;
    float* ws = sm + 128 * XST;

    int n1 = clamp_n1(n1p, N0);
    int row0 = blockIdx.x * 128;
    if (row0 >= n1) return;

    int tid = threadIdx.x, lane = tid & 31, warp = tid >> 5;
    int wm = warp >> 1, wn = warp & 1;
    int lq = lane >> 2, lr = lane & 3;

    float acc[2][8][4];
#pragma unroll
    for (int mi = 0; mi < 2; ++mi)
#pragma unroll
        for (int ni = 0; ni < 8; ++ni)
#pragma unroll
            for (int j = 0; j < 4; ++j) acc[mi][ni][j] = 0.f;

    for (int kc = 0; kc < H; kc += 64) {
        if (kc) __syncthreads();
#pragma unroll
        for (int it = 0; it < 8; ++it) {
            int f4 = it * 256 + tid;
            int r = f4 >> 4, k4 = f4 & 15;
            int row = row0 + r;
            float4 v = make_float4(0.f, 0.f, 0.f, 0.f);
            if (row < N0) v = *(const float4*)&x[(size_t)row * H + kc + k4 * 4];
            *(float4*)&xs[r * XST + k4 * 4] = v;
            float4 wv = *(const float4*)&W[(size_t)r * H + kc + k4 * 4];
            *(float4*)&ws[r * XST + k4 * 4] = wv;
        }
        __syncthreads();

#pragma unroll
        for (int ks = 0; ks < 8; ++ks) {
            int kb = ks * 8 + lr;
            uint32_t ah[2][4], al[2][4];
#pragma unroll
            for (int mi = 0; mi < 2; ++mi) {
                int r = wm * 32 + mi * 16 + lq;
                tf32split(xs[r * XST + kb],           ah[mi][0], al[mi][0]);
                tf32split(xs[(r + 8) * XST + kb],     ah[mi][1], al[mi][1]);
                tf32split(xs[r * XST + kb + 4],       ah[mi][2], al[mi][2]);
                tf32split(xs[(r + 8) * XST + kb + 4], ah[mi][3], al[mi][3]);
            }
#pragma unroll
            for (int ni = 0; ni < 8; ++ni) {
                int n = wn * 64 + ni * 8 + lq;
                uint32_t bh0, bl0, bh1, bl1;
                tf32split(ws[n * XST + kb],     bh0, bl0);
                tf32split(ws[n * XST + kb + 4], bh1, bl1);
#pragma unroll
                for (int mi = 0; mi < 2; ++mi) {
                    MMA(acc[mi][ni], ah[mi][0], ah[mi][1], ah[mi][2], ah[mi][3], bh0, bh1);
                    MMA(acc[mi][ni], ah[mi][0], ah[mi][1], ah[mi][2], ah[mi][3], bl0, bl1);
                    MMA(acc[mi][ni], al[mi][0], al[mi][1], al[mi][2], al[mi][3], bh0, bh1);
                }
            }
        }
    }

#pragma unroll
    for (int mi = 0; mi < 2; ++mi) {
        int r0 = row0 + wm * 32 + mi * 16 + lq;
#pragma unroll
        for (int ni = 0; ni < 8; ++ni) {
            int col = wn * 64 + ni * 8 + lr * 2;
            if (r0 < n1) {
                __half2 h = __floats2half2_rn(acc[mi][ni][0], acc[mi][ni][1]);
                *(__half2*)&g_xWh[(size_t)r0 * H + col] = h;
            }
            if (r0 + 8 < n1) {
                __half2 h = __floats2half2_rn(acc[mi][ni][2], acc[mi][ni][3]);
                *(__half2*)&g_xWh[(size_t)(r0 + 8) * H + col] = h;
            }
        }
    }
}

// ---- K5: GCN gather + SAGE partial p1 (t<n2), warp per target, in-gather norm --
__global__ void __launch_bounds__(256) k_gather_gcn(const float* __restrict__ b, int n2) {
    int t = blockIdx.x * 8 + (threadIdx.x >> 5);
    if (t >= n2) return;
    int lane = threadIdx.x & 31;
    int c = lane * 4;
    int base = __ldg(&g_off[t]);
    int end  = __ldg(&g_off[t + 1]);

    float4 ag0 = make_float4(0.f, 0.f, 0.f, 0.f), ag1 = ag0;
    float4 ap0 = ag0, ap1 = ag0;

    for (int i0 = base; i0 < end; i0 += 32) {
        int idx = i0 + lane;
        int s = 0; float nm = 0.f, u = 0.f;
        if (idx < end) {
            float2 p = __ldg(&g_epk[idx]);
            s = __float_as_int(p.x);
            float w = p.y;
            float ds = 1.f, d2 = 1.f;
            if (s < n2) {
                float dg = __int_as_float(__ldg(&g_hd[MAXN2 + s]));
                d2 = 1.f / (1.f + dg);
                ds = rsqrtf(1.f + dg);
            }
            nm = ds * w;     // dinv[t] factored out of the agg sum
            u = d2;
        }
        int cnt = min(32, end - i0);
        int j = 0;
        for (; j + 4 <= cnt; j += 4) {
            int   s0 = __shfl_sync(0xffffffffu, s, j);
            float w0 = __shfl_sync(0xffffffffu, nm, j);
            float u0 = __shfl_sync(0xffffffffu, u, j);
            int   s1 = __shfl_sync(0xffffffffu, s, j + 1);
            float w1 = __shfl_sync(0xffffffffu, nm, j + 1);
            float u1 = __shfl_sync(0xffffffffu, u, j + 1);
            int   s2 = __shfl_sync(0xffffffffu, s, j + 2);
            float w2 = __shfl_sync(0xffffffffu, nm, j + 2);
            float u2 = __shfl_sync(0xffffffffu, u, j + 2);
            int   s3 = __shfl_sync(0xffffffffu, s, j + 3);
            float w3 = __shfl_sync(0xffffffffu, nm, j + 3);
            float u3 = __shfl_sync(0xffffffffu, u, j + 3);
            float4 v0 = h4_to_f4(*(const uint2*)&g_xWh[(size_t)s0 * H + c]);
            float4 v1 = h4_to_f4(*(const uint2*)&g_xWh[(size_t)s1 * H + c]);
            float4 v2 = h4_to_f4(*(const uint2*)&g_xWh[(size_t)s2 * H + c]);
            float4 v3 = h4_to_f4(*(const uint2*)&g_xWh[(size_t)s3 * H + c]);
            ag0.x += w0 * v0.x; ag0.y += w0 * v0.y; ag0.z += w0 * v0.z; ag0.w += w0 * v0.w;
            ap0.x += u0 * v0.x; ap0.y += u0 * v0.y; ap0.z += u0 * v0.z; ap0.w += u0 * v0.w;
            ag1.x += w1 * v1.x; ag1.y += w1 * v1.y; ag1.z += w1 * v1.z; ag1.w += w1 * v1.w;
            ap1.x += u1 * v1.x; ap1.y += u1 * v1.y; ap1.z += u1 * v1.z; ap1.w += u1 * v1.w;
            ag0.x += w2 * v2.x; ag0.y += w2 * v2.y; ag0.z += w2 * v2.z; ag0.w += w2 * v2.w;
            ap0.x += u2 * v2.x; ap0.y += u2 * v2.y; ap0.z += u2 * v2.z; ap0.w += u2 * v2.w;
            ag1.x += w3 * v3.x; ag1.y += w3 * v3.y; ag1.z += w3 * v3.z; ag1.w += w3 * v3.w;
            ap1.x += u3 * v3.x; ap1.y += u3 * v3.y; ap1.z += u3 * v3.z; ap1.w += u3 * v3.w;
        }
        for (; j < cnt; ++j) {
            int   s0 = __shfl_sync(0xffffffffu, s, j);
            float w0 = __shfl_sync(0xffffffffu, nm, j);
            float u0 = __shfl_sync(0xffffffffu, u, j);
            float4 v0 = h4_to_f4(*(const uint2*)&g_xWh[(size_t)s0 * H + c]);
            ag0.x += w0 * v0.x; ag0.y += w0 * v0.y; ag0.z += w0 * v0.z; ag0.w += w0 * v0.w;
            ap0.x += u0 * v0.x; ap0.y += u0 * v0.y; ap0.z += u0 * v0.z; ap0.w += u0 * v0.w;
        }
    }

    float degt = __int_as_float(g_hd[MAXN2 + t]);
    float dt  = rsqrtf(1.f + degt);
    float d2t = 1.f / (1.f + degt);
    float4 agg;
    agg.x = ((ag0.x + ag1.x)) * dt;
    agg.y = ((ag0.y + ag1.y)) * dt;
    agg.z = ((ag0.z + ag1.z)) * dt;
    agg.w = ((ag0.w + ag1.w)) * dt;
    float4 p1 = make_float4(ap0.x + ap1.x, ap0.y + ap1.y, ap0.z + ap1.z, ap0.w + ap1.w);
    float4 xw = h4_to_f4(*(const uint2*)&g_xWh[(size_t)t * H + c]);
    float4 bb = *(const float4*)&b[c];
    float4 g1;
    g1.x = agg.x + xw.x * d2t + bb.x;
    g1.y = agg.y + xw.y * d2t + bb.y;
    g1.z = agg.z + xw.z * d2t + bb.z;
    g1.w = agg.w + xw.w * d2t + bb.w;
    *(float4*)&g_g1f[(size_t)t * H + c] = g1;
    *(uint2*)&g_aggh[(size_t)t * H + c] = f4_to_h4(agg);
    *(float4*)&g_p1f[(size_t)t * H + c] = p1;
}

// ---- K6: SAGE p2 gather (only src<n2) + mean -----------------------------------
__global__ void __launch_bounds__(256) k_sage2(const float* __restrict__ b, int n2) {
    int t = blockIdx.x * 8 + (threadIdx.x >> 5);
    if (t >= n2) return;
    int lane = threadIdx.x & 31;
    int c = lane * 4;
    int base = __ldg(&g_off[t]);
    int end  = __ldg(&g_off[t + 1]);
    int cnt = end - base;

    float4 a0 = make_float4(0.f, 0.f, 0.f, 0.f), a1 = a0;

    for (int i0 = base; i0 < end; i0 += 32) {
        int idx = i0 + lane;
        int s = n2;
        if (idx < end) s = __float_as_int(__ldg(&g_epk[idx]).x);
        int cl = min(32, end - i0);
        int j = 0;
        for (; j + 4 <= cl; j += 4) {
            int s0 = __shfl_sync(0xffffffffu, s, j);
            int s1 = __shfl_sync(0xffffffffu, s, j + 1);
            int s2 = __shfl_sync(0xffffffffu, s, j + 2);
            int s3 = __shfl_sync(0xffffffffu, s, j + 3);
            if (s0 < n2) {
                float4 v = h4_to_f4(*(const uint2*)&g_aggh[(size_t)s0 * H + c]);
                a0.x += v.x; a0.y += v.y; a0.z += v.z; a0.w += v.w;
            }
            if (s1 < n2) {
                float4 v = h4_to_f4(*(const uint2*)&g_aggh[(size_t)s1 * H + c]);
                a1.x += v.x; a1.y += v.y; a1.z += v.z; a1.w += v.w;
            }
            if (s2 < n2) {
                float4 v = h4_to_f4(*(const uint2*)&g_aggh[(size_t)s2 * H + c]);
                a0.x += v.x; a0.y += v.y; a0.z += v.z; a0.w += v.w;
            }
            if (s3 < n2) {
                float4 v = h4_to_f4(*(const uint2*)&g_aggh[(size_t)s3 * H + c]);
                a1.x += v.x; a1.y += v.y; a1.z += v.z; a1.w += v.w;
            }
        }
        for (; j < cl; ++j) {
            int s0 = __shfl_sync(0xffffffffu, s, j);
            if (s0 < n2) {
                float4 v = h4_to_f4(*(const uint2*)&g_aggh[(size_t)s0 * H + c]);
                a0.x += v.x; a0.y += v.y; a0.z += v.z; a0.w += v.w;
            }
        }
    }

    float4 o = make_float4(0.f, 0.f, 0.f, 0.f);
    if (cnt > 0) {
        float sc = 1.f / (float)cnt;
        float4 p1 = *(const float4*)&g_p1f[(size_t)t * H + c];
        float4 bb = *(const float4*)&b[c];
        o.x = (p1.x + a0.x + a1.x) * sc + bb.x;
        o.y = (p1.y + a0.y + a1.y) * sc + bb.y;
        o.z = (p1.z + a0.z + a1.z) * sc + bb.z;
        o.w = (p1.w + a0.w + a1.w) * sc + bb.w;
    }
    *(float4*)&g_s[(size_t)t * H + c] = o;
}

// ---- K7: out = l2norm( mean @ Wl^T + bl + g1 @ Wr^T ) --------------------------
__global__ void __launch_bounds__(256) k_sage_out(
    const float* __restrict__ Wl, const float* __restrict__ bl,
    const float* __restrict__ Wr, int n2, float* __restrict__ out) {
    extern __shared__ float sm[];
    float* Wlt  = sm;
    float* Wrt  = Wlt + H * SW;
    float* ms   = Wrt + H * SW;
    float* gs   = ms  + H * SX;
    float* psum = gs  + H * SX;
    float* scl  = psum + GROWS * 16;

    int row0 = blockIdx.x * GROWS;
    int tid = threadIdx.x;

    for (int idx = tid; idx < H * H; idx += 256) {
        int j = idx >> 7, k = idx & 127;
        Wlt[k * SW + j] = Wl[idx];
        Wrt[k * SW + j] = Wr[idx];
    }
    for (int idx = tid; idx < GROWS * H; idx += 256) {
        int r = idx >> 7, k = idx & 127;
        int row = row0 + r;
        if (row < n2) {
            size_t off = (size_t)row * H + k;
            ms[k * SX + r] = g_s[off];
            gs[k * SX + r] = g_g1f[off];
        } else {
            ms[k * SX + r] = 0.f;
            gs[k * SX + r] = 0.f;
        }
    }
    __syncthreads();

    int col_t = tid & 15;
    int row_t = tid >> 4;
    float acc[4][8];
#pragma unroll
    for (int j = 0; j < 8; ++j) {
        float bv = bl[col_t * 8 + j];
#pragma unroll
        for (int i = 0; i < 4; ++i) acc[i][j] = bv;
    }

    for (int k = 0; k < H; ++k) {
        float4 am4 = *(const float4*)&ms[k * SX + row_t * 4];
        float4 ag4 = *(const float4*)&gs[k * SX + row_t * 4];
        float4 l0 = *(const float4*)&Wlt[k * SW + col_t * 8];
        float4 l1 = *(const float4*)&Wlt[k * SW + col_t * 8 + 4];
        float4 r0 = *(const float4*)&Wrt[k * SW + col_t * 8];
        float4 r1 = *(const float4*)&Wrt[k * SW + col_t * 8 + 4];
        float am[4] = {am4.x, am4.y, am4.z, am4.w};
        float ag[4] = {ag4.x, ag4.y, ag4.z, ag4.w};
        float wl[8] = {l0.x, l0.y, l0.z, l0.w, l1.x, l1.y, l1.z, l1.w};
        float wr[8] = {r0.x, r0.y, r0.z, r0.w, r1.x, r1.y, r1.z, r1.w};
#pragma unroll
        for (int i = 0; i < 4; ++i)
#pragma unroll
            for (int j = 0; j < 8; ++j)
                acc[i][j] += am[i] * wl[j] + ag[i] * wr[j];
    }

#pragma unroll
    for (int i = 0; i < 4; ++i) {
        float loc = 0.f;
#pragma unroll
        for (int j = 0; j < 8; ++j) loc += acc[i][j] * acc[i][j];
        psum[(row_t * 4 + i) * 16 + col_t] = loc;
    }
    __syncthreads();
    if (tid < GROWS) {
        float ssum = 0.f;
#pragma unroll
        for (int cc = 0; cc < 16; ++cc) ssum += psum[tid * 16 + cc];
        scl[tid] = 1.f / fmaxf(sqrtf(ssum), 1e-12f);
    }
    __syncthreads();

#pragma unroll
    for (int i = 0; i < 4; ++i) {
        int row = row0 + row_t * 4 + i;
        if (row < n2) {
            float sc = scl[row_t * 4 + i];
            float4 o0 = make_float4(acc[i][0] * sc, acc[i][1] * sc,
                                    acc[i][2] * sc, acc[i][3] * sc);
            float4 o1 = make_float4(acc[i][4] * sc, acc[i][5] * sc,
                                    acc[i][6] * sc, acc[i][7] * sc);
            *(float4*)&out[(size_t)row * H + col_t * 8]     = o0;
            *(float4*)&out[(size_t)row * H + col_t * 8 + 4] = o1;
        }
    }
}

// ---------------------------------------------------------------------------
extern "C" void kernel_launch(void* const* d_in, const int* in_sizes, int n_in,
                              void* d_out, int out_size) {
    const float* x     = (const float*)d_in[0];
    const float* attr  = (const float*)d_in[1];
    const int*   e_id1 = (const int*)d_in[3];
    const int*   src1  = (const int*)d_in[6];
    const int*   tgt1  = (const int*)d_in[7];
    const int*   n1p   = (const int*)d_in[8];
    const float* gcn_W = (const float*)d_in[10];
    const float* gcn_b = (const float*)d_in[11];
    const float* Wl1   = (const float*)d_in[15];
    const float* bl1   = (const float*)d_in[16];
    const float* Wr1   = (const float*)d_in[17];
    float* out = (float*)d_out;

    int N0 = in_sizes[0] / H;  if (N0 > MAXN0) N0 = MAXN0;
    int E1 = in_sizes[3];      if (E1 > MAXE)  E1 = MAXE;
    int n2 = out_size / H;     if (n2 > MAXN2) n2 = MAXN2;

    constexpr int SMEM_GEMM = 128 * XST * 2 * 4;
    constexpr int SMEM_SCAN = MAXN2 * 4;
    constexpr int SMEM_K8 = (2 * H * SW + 2 * H * SX + GROWS * 16 + GROWS) * 4;
    cudaFuncSetAttribute(k_gemm_tc, cudaFuncAttributeMaxDynamicSharedMemorySize, SMEM_GEMM);
    cudaFuncSetAttribute(k_scan, cudaFuncAttributeMaxDynamicSharedMemorySize, SMEM_SCAN);
    cudaFuncSetAttribute(k_sage_out, cudaFuncAttributeMaxDynamicSharedMemorySize, SMEM_K8);

    void* p_hd;
    cudaGetSymbolAddress(&p_hd, g_hd);

    cudaStream_t s2;
    cudaStreamCreateWithFlags(&s2, cudaStreamNonBlocking);
    cudaEvent_t evFork, evGemm;
    cudaEventCreateWithFlags(&evFork, cudaEventDisableTiming);
    cudaEventCreateWithFlags(&evGemm, cudaEventDisableTiming);

    // Fork: GEMM on side stream.
    cudaEventRecord(evFork, 0);
    cudaStreamWaitEvent(s2, evFork, 0);
    k_gemm_tc<<<(N0 + 127) / 128, 256, SMEM_GEMM, s2>>>(x, gcn_W, n1p, N0);
    cudaEventRecord(evGemm, s2);

    // Main stream: edge preprocessing.
    cudaMemsetAsync(p_hd, 0, (size_t)2 * MAXN2 * 4, 0);
    k_hist<<<(E1 + 511) / 512, 256>>>(attr, e_id1, tgt1, E1, n2);
    k_scan<<<1, 1024, SMEM_SCAN>>>(n2);
    k_scatter<<<(E1 + 511) / 512, 256>>>(src1, tgt1, E1, n2);

    cudaStreamWaitEvent(0, evGemm, 0);  // join

    k_gather_gcn<<<(n2 + 7) / 8, 256>>>(gcn_b, n2);
    k_sage2<<<(n2 + 7) / 8, 256>>>(gcn_b, n2);
    k_sage_out<<<(n2 + GROWS - 1) / GROWS, 256, SMEM_K8>>>(Wl1, bl1, Wr1, n2, out);
}

// round 11
// speedup vs baseline: 1.3287x; 1.0045x over previous
#include <cuda_runtime.h>
#include <cuda_fp16.h>
#include <cstdint>

// ---------------------------------------------------------------------------
// GlobalGNN layer-1-only pipeline:
//   s2  : xW = x@gcn_W^T (tf32 TC GEMM, fp16 out)
//   main: hist(x2) -> scan(writes g_off excl + g_hd inclusive-end)
//         -> scatter(x2: pos = atomicAdd(end,-1)-1, store (s,w))
//   join: gather_gcn (agg,p1,g1) -> sage2 (p2,mean; restores g_hd to zero)
//         -> sage_out (GEMM + l2norm)
// State is self-restoring across graph replays (no memset node).
// ---------------------------------------------------------------------------

#define H 128
#define MAXN0 131072
#define MAXN2 16384
#define MAXE  1048576
#define GROWS 64
#define SW 132
#define SX 68
#define XST 72

__device__ __align__(16) __half g_xWh [(size_t)MAXN0 * H];
__device__ __align__(16) __half g_aggh[(size_t)MAXN2 * H];
__device__ __align__(16) float  g_g1f [(size_t)MAXN2 * H];
__device__ __align__(16) float  g_p1f [(size_t)MAXN2 * H];
__device__ __align__(16) float  g_s   [(size_t)MAXN2 * H];
__device__ __align__(16) int    g_hd  [2 * MAXN2];   // [i]=count/end-pos, [MAXN2+i]=degx bits
__device__ __align__(16) int    g_off [MAXN2 + 4];
__device__ __align__(16) float2 g_epk [MAXE];        // (.x=src bits, .y=w)
__device__ __align__(16) float  g_wst [MAXE];

__device__ __forceinline__ int clamp_n1(const int* p, int N0) {
    int v = *p;
    if (v <= 0 || v > N0) v = N0;
    return v;
}

__device__ __forceinline__ void tf32split(float f, uint32_t& hi, uint32_t& lo) {
    uint32_t h;
    asm("cvt.rna.tf32.f32 %0, %1;" : "=r"(h) : "f"(f));
    float r = f - __uint_as_float(h);
    asm("cvt.rna.tf32.f32 %0, %1;" : "=r"(lo) : "f"(r));
    hi = h;
}

__device__ __forceinline__ float4 h4_to_f4(uint2 raw) {
    __half2 h0 = *reinterpret_cast<__half2*>(&raw.x);
    __half2 h1 = *reinterpret_cast<__half2*>(&raw.y);
    float2 f0 = __half22float2(h0);
    float2 f1 = __half22float2(h1);
    return make_float4(f0.x, f0.y, f1.x, f1.y);
}

__device__ __forceinline__ uint2 f4_to_h4(float4 v) {
    __half2 h0 = __floats2half2_rn(v.x, v.y);
    __half2 h1 = __floats2half2_rn(v.z, v.w);
    uint2 r;
    r.x = *reinterpret_cast<uint32_t*>(&h0);
    r.y = *reinterpret_cast<uint32_t*>(&h1);
    return r;
}

#define MMA(d, a0, a1, a2, a3, b0, b1)                                        \
    asm volatile(                                                             \
        "mma.sync.aligned.m16n8k8.row.col.f32.tf32.tf32.f32 "                 \
        "{%0,%1,%2,%3},{%4,%5,%6,%7},{%8,%9},{%0,%1,%2,%3};"                  \
        : "+f"(d[0]), "+f"(d[1]), "+f"(d[2]), "+f"(d[3])                      \
        : "r"(a0), "r"(a1), "r"(a2), "r"(a3), "r"(b0), "r"(b1))

// ---- K1: histogram + weighted degree + weight staging, 2 edges/thread ---------
// (g_hd arrives all-zero: BSS on first run, restored by sage2 on later runs)
__global__ void k_hist(const float* __restrict__ attr, const int* __restrict__ eid,
                       const int* __restrict__ tgt, int E, int n2) {
    int base = (blockIdx.x * blockDim.x + threadIdx.x) * 2;
    if (base >= E) return;
    if (base + 2 <= E) {
        int2 t2  = *(const int2*)&tgt[base];
        int2 id2 = *(const int2*)&eid[base];
        float w0 = __ldg(&attr[id2.x]);
        float w1 = __ldg(&attr[id2.y]);
        *(float2*)&g_wst[base] = make_float2(w0, w1);
        if (t2.x < n2) { atomicAdd(&g_hd[t2.x], 1); atomicAdd((float*)&g_hd[MAXN2 + t2.x], w0); }
        if (t2.y < n2) { atomicAdd(&g_hd[t2.y], 1); atomicAdd((float*)&g_hd[MAXN2 + t2.y], w1); }
    } else {
        int t = __ldg(&tgt[base]);
        float w = __ldg(&attr[__ldg(&eid[base])]);
        g_wst[base] = w;
        if (t < n2) {
            atomicAdd(&g_hd[t], 1);
            atomicAdd((float*)&g_hd[MAXN2 + t], w);
        }
    }
}

// ---- K2: scan: g_off[i]=exclusive, g_hd[i]=inclusive end (i<n2) ----------------
__global__ void __launch_bounds__(1024) k_scan(int n2) {
    extern __shared__ int sh[];          // MAXN2 ints (64 KB dynamic)
    __shared__ int wsum[32];
    int tid = threadIdx.x, lane = tid & 31, wid = tid >> 5;

    int n2v = (n2 + 3) >> 2;
    const int4* cnt4 = (const int4*)g_hd;
    for (int v = tid; v < n2v; v += 1024)
        ((int4*)sh)[v] = cnt4[v];
    for (int v = n2v + tid; v < MAXN2 / 4; v += 1024)
        ((int4*)sh)[v] = make_int4(0, 0, 0, 0);
    __syncthreads();

    int base = tid * 16;
    int vals[16], cnts[16];
    int local = 0;
#pragma unroll
    for (int i4 = 0; i4 < 4; ++i4) {
        int4 q = *(const int4*)&sh[base + i4 * 4];
        int cc[4] = {q.x, q.y, q.z, q.w};
#pragma unroll
        for (int j = 0; j < 4; ++j) {
            vals[i4 * 4 + j] = local;
            cnts[i4 * 4 + j] = cc[j];
            local += cc[j];
        }
    }
    int inc = local;
#pragma unroll
    for (int off = 1; off < 32; off <<= 1) {
        int nb = __shfl_up_sync(0xffffffffu, inc, off);
        if (lane >= off) inc += nb;
    }
    if (lane == 31) wsum[wid] = inc;
    __syncthreads();
    if (wid == 0) {
        int s = wsum[lane];
#pragma unroll
        for (int off = 1; off < 32; off <<= 1) {
            int nb = __shfl_up_sync(0xffffffffu, s, off);
            if (lane >= off) s += nb;
        }
        wsum[lane] = s;
    }
    __syncthreads();
    int excl = ((wid > 0) ? wsum[wid - 1] : 0) + inc - local;
#pragma unroll
    for (int i4 = 0; i4 < 4; ++i4) {
        int4 q = make_int4(excl + vals[i4 * 4],     excl + vals[i4 * 4 + 1],
                           excl + vals[i4 * 4 + 2], excl + vals[i4 * 4 + 3]);
        *(int4*)&sh[base + i4 * 4] = q;
        // inclusive end positions into the countdown cells (extent-guarded)
        int idx = base + i4 * 4;
        if (idx + 3 < n2) {
            int4 e = make_int4(q.x + cnts[i4 * 4],     q.y + cnts[i4 * 4 + 1],
                               q.z + cnts[i4 * 4 + 2], q.w + cnts[i4 * 4 + 3]);
            *(int4*)&g_hd[idx] = e;
        } else {
#pragma unroll
            for (int j = 0; j < 4; ++j)
                if (idx + j < n2)
                    g_hd[idx + j] = (&q.x)[j] + cnts[i4 * 4 + j];
        }
    }
    int total = wsum[31];
    __syncthreads();
    int4* off4 = (int4*)g_off;
    for (int v = tid; v < n2v; v += 1024)
        off4[v] = ((const int4*)sh)[v];
    if (tid == 0) g_off[n2] = total;
}

// ---- K3: scatter (countdown on end positions), 2 edges/thread ------------------
__global__ void k_scatter(const int* __restrict__ src, const int* __restrict__ tgt,
                          int E, int n2) {
    int base = (blockIdx.x * blockDim.x + threadIdx.x) * 2;
    if (base >= E) return;
    int t[2], s[2];
    float w[2];
    if (base + 2 <= E) {
        int2 t2 = *(const int2*)&tgt[base];
        int2 s2 = *(const int2*)&src[base];
        float2 w2 = *(const float2*)&g_wst[base];
        t[0] = t2.x; t[1] = t2.y;
        s[0] = s2.x; s[1] = s2.y;
        w[0] = w2.x; w[1] = w2.y;
    } else {
        t[0] = __ldg(&tgt[base]); t[1] = n2;
        s[0] = __ldg(&src[base]); s[1] = 0;
        w[0] = __ldg(&g_wst[base]); w[1] = 0.f;
    }
    int pos[2];
#pragma unroll
    for (int j = 0; j < 2; ++j)
        pos[j] = (t[j] < n2) ? (atomicAdd(&g_hd[t[j]], -1) - 1) : -1;
#pragma unroll
    for (int j = 0; j < 2; ++j)
        if (pos[j] >= 0)
            g_epk[pos[j]] = make_float2(__int_as_float(s[j]), w[j]);
}

// ---- K4: xW = x @ W^T via tf32 TC, fp16 output (rows < n1) --------------------
__global__ void __launch_bounds__(256) k_gemm_tc(
    const float* __restrict__ x, const float* __restrict__ W,
    const int* __restrict__ n1p, int N0) {
    extern __shared__ float sm[];
    float* xs = sm;
    float* ws = sm + 128 * XST;

    int n1 = clamp_n1(n1p, N0);
    int row0 = blockIdx.x * 128;
    if (row0 >= n1) return;

    int tid = threadIdx.x, lane = tid & 31, warp = tid >> 5;
    int wm = warp >> 1, wn = warp & 1;
    int lq = lane >> 2, lr = lane & 3;

    float acc[2][8][4];
#pragma unroll
    for (int mi = 0; mi < 2; ++mi)
#pragma unroll
        for (int ni = 0; ni < 8; ++ni)
#pragma unroll
            for (int j = 0; j < 4; ++j) acc[mi][ni][j] = 0.f;

    for (int kc = 0; kc < H; kc += 64) {
        if (kc) __syncthreads();
#pragma unroll
        for (int it = 0; it < 8; ++it) {
            int f4 = it * 256 + tid;
            int r = f4 >> 4, k4 = f4 & 15;
            int row = row0 + r;
            float4 v = make_float4(0.f, 0.f, 0.f, 0.f);
            if (row < N0) v = *(const float4*)&x[(size_t)row * H + kc + k4 * 4];
            *(float4*)&xs[r * XST + k4 * 4] = v;
            float4 wv = *(const float4*)&W[(size_t)r * H + kc + k4 * 4];
            *(float4*)&ws[r * XST + k4 * 4] = wv;
        }
        __syncthreads();

#pragma unroll
        for (int ks = 0; ks < 8; ++ks) {
            int kb = ks * 8 + lr;
            uint32_t ah[2][4], al[2][4];
#pragma unroll
            for (int mi = 0; mi < 2; ++mi) {
                int r = wm * 32 + mi * 16 + lq;
                tf32split(xs[r * XST + kb],           ah[mi][0], al[mi][0]);
                tf32split(xs[(r + 8) * XST + kb],     ah[mi][1], al[mi][1]);
                tf32split(xs[r * XST + kb + 4],       ah[mi][2], al[mi][2]);
                tf32split(xs[(r + 8) * XST + kb + 4], ah[mi][3], al[mi][3]);
            }
#pragma unroll
            for (int ni = 0; ni < 8; ++ni) {
                int n = wn * 64 + ni * 8 + lq;
                uint32_t bh0, bl0, bh1, bl1;
                tf32split(ws[n * XST + kb],     bh0, bl0);
                tf32split(ws[n * XST + kb + 4], bh1, bl1);
#pragma unroll
                for (int mi = 0; mi < 2; ++mi) {
                    MMA(acc[mi][ni], ah[mi][0], ah[mi][1], ah[mi][2], ah[mi][3], bh0, bh1);
                    MMA(acc[mi][ni], ah[mi][0], ah[mi][1], ah[mi][2], ah[mi][3], bl0, bl1);
                    MMA(acc[mi][ni], al[mi][0], al[mi][1], al[mi][2], al[mi][3], bh0, bh1);
                }
            }
        }
    }

#pragma unroll
    for (int mi = 0; mi < 2; ++mi) {
        int r0 = row0 + wm * 32 + mi * 16 + lq;
#pragma unroll
        for (int ni = 0; ni < 8; ++ni) {
            int col = wn * 64 + ni * 8 + lr * 2;
            if (r0 < n1) {
                __half2 h = __floats2half2_rn(acc[mi][ni][0], acc[mi][ni][1]);
                *(__half2*)&g_xWh[(size_t)r0 * H + col] = h;
            }
            if (r0 + 8 < n1) {
                __half2 h = __floats2half2_rn(acc[mi][ni][2], acc[mi][ni][3]);
                *(__half2*)&g_xWh[(size_t)(r0 + 8) * H + col] = h;
            }
        }
    }
}

// ---- K5: GCN gather + SAGE partial p1 (t<n2), warp per target, in-gather norm --
__global__ void __launch_bounds__(256) k_gather_gcn(const float* __restrict__ b, int n2) {
    int t = blockIdx.x * 8 + (threadIdx.x >> 5);
    if (t >= n2) return;
    int lane = threadIdx.x & 31;
    int c = lane * 4;
    int base = __ldg(&g_off[t]);
    int end  = __ldg(&g_off[t + 1]);

    float4 ag0 = make_float4(0.f, 0.f, 0.f, 0.f), ag1 = ag0;
    float4 ap0 = ag0, ap1 = ag0;

    for (int i0 = base; i0 < end; i0 += 32) {
        int idx = i0 + lane;
        int s = 0; float nm = 0.f, u = 0.f;
        if (idx < end) {
            float2 p = __ldg(&g_epk[idx]);
            s = __float_as_int(p.x);
            float w = p.y;
            float ds = 1.f, d2 = 1.f;
            if (s < n2) {
                float dg = __int_as_float(__ldg(&g_hd[MAXN2 + s]));
                d2 = 1.f / (1.f + dg);
                ds = rsqrtf(1.f + dg);
            }
            nm = ds * w;
            u = d2;
        }
        int cnt = min(32, end - i0);
        int j = 0;
        for (; j + 4 <= cnt; j += 4) {
            int   s0 = __shfl_sync(0xffffffffu, s, j);
            float w0 = __shfl_sync(0xffffffffu, nm, j);
            float u0 = __shfl_sync(0xffffffffu, u, j);
            int   s1 = __shfl_sync(0xffffffffu, s, j + 1);
            float w1 = __shfl_sync(0xffffffffu, nm, j + 1);
            float u1 = __shfl_sync(0xffffffffu, u, j + 1);
            int   s2 = __shfl_sync(0xffffffffu, s, j + 2);
            float w2 = __shfl_sync(0xffffffffu, nm, j + 2);
            float u2 = __shfl_sync(0xffffffffu, u, j + 2);
            int   s3 = __shfl_sync(0xffffffffu, s, j + 3);
            float w3 = __shfl_sync(0xffffffffu, nm, j + 3);
            float u3 = __shfl_sync(0xffffffffu, u, j + 3);
            float4 v0 = h4_to_f4(*(const uint2*)&g_xWh[(size_t)s0 * H + c]);
            float4 v1 = h4_to_f4(*(const uint2*)&g_xWh[(size_t)s1 * H + c]);
            float4 v2 = h4_to_f4(*(const uint2*)&g_xWh[(size_t)s2 * H + c]);
            float4 v3 = h4_to_f4(*(const uint2*)&g_xWh[(size_t)s3 * H + c]);
            ag0.x += w0 * v0.x; ag0.y += w0 * v0.y; ag0.z += w0 * v0.z; ag0.w += w0 * v0.w;
            ap0.x += u0 * v0.x; ap0.y += u0 * v0.y; ap0.z += u0 * v0.z; ap0.w += u0 * v0.w;
            ag1.x += w1 * v1.x; ag1.y += w1 * v1.y; ag1.z += w1 * v1.z; ag1.w += w1 * v1.w;
            ap1.x += u1 * v1.x; ap1.y += u1 * v1.y; ap1.z += u1 * v1.z; ap1.w += u1 * v1.w;
            ag0.x += w2 * v2.x; ag0.y += w2 * v2.y; ag0.z += w2 * v2.z; ag0.w += w2 * v2.w;
            ap0.x += u2 * v2.x; ap0.y += u2 * v2.y; ap0.z += u2 * v2.z; ap0.w += u2 * v2.w;
            ag1.x += w3 * v3.x; ag1.y += w3 * v3.y; ag1.z += w3 * v3.z; ag1.w += w3 * v3.w;
            ap1.x += u3 * v3.x; ap1.y += u3 * v3.y; ap1.z += u3 * v3.z; ap1.w += u3 * v3.w;
        }
        for (; j < cnt; ++j) {
            int   s0 = __shfl_sync(0xffffffffu, s, j);
            float w0 = __shfl_sync(0xffffffffu, nm, j);
            float u0 = __shfl_sync(0xffffffffu, u, j);
            float4 v0 = h4_to_f4(*(const uint2*)&g_xWh[(size_t)s0 * H + c]);
            ag0.x += w0 * v0.x; ag0.y += w0 * v0.y; ag0.z += w0 * v0.z; ag0.w += w0 * v0.w;
            ap0.x += u0 * v0.x; ap0.y += u0 * v0.y; ap0.z += u0 * v0.z; ap0.w += u0 * v0.w;
        }
    }

    float degt = __int_as_float(g_hd[MAXN2 + t]);
    float dt  = rsqrtf(1.f + degt);
    float d2t = 1.f / (1.f + degt);
    float4 agg;
    agg.x = (ag0.x + ag1.x) * dt;
    agg.y = (ag0.y + ag1.y) * dt;
    agg.z = (ag0.z + ag1.z) * dt;
    agg.w = (ag0.w + ag1.w) * dt;
    float4 p1 = make_float4(ap0.x + ap1.x, ap0.y + ap1.y, ap0.z + ap1.z, ap0.w + ap1.w);
    float4 xw = h4_to_f4(*(const uint2*)&g_xWh[(size_t)t * H + c]);
    float4 bb = *(const float4*)&b[c];
    float4 g1;
    g1.x = agg.x + xw.x * d2t + bb.x;
    g1.y = agg.y + xw.y * d2t + bb.y;
    g1.z = agg.z + xw.z * d2t + bb.z;
    g1.w = agg.w + xw.w * d2t + bb.w;
    *(float4*)&g_g1f[(size_t)t * H + c] = g1;
    *(uint2*)&g_aggh[(size_t)t * H + c] = f4_to_h4(agg);
    *(float4*)&g_p1f[(size_t)t * H + c] = p1;
}

// ---- K6: SAGE p2 gather + mean; restores g_hd[t] (count & degx) to zero --------
__global__ void __launch_bounds__(256) k_sage2(const float* __restrict__ b, int n2) {
    int t = blockIdx.x * 8 + (threadIdx.x >> 5);
    if (t >= n2) return;
    int lane = threadIdx.x & 31;
    int c = lane * 4;
    int base = __ldg(&g_off[t]);
    int end  = __ldg(&g_off[t + 1]);
    int cnt = end - base;

    // restore self-zeroing invariant for the next graph replay
    if (lane == 0) { g_hd[t] = 0; g_hd[MAXN2 + t] = 0; }

    float4 a0 = make_float4(0.f, 0.f, 0.f, 0.f), a1 = a0;

    for (int i0 = base; i0 < end; i0 += 32) {
        int idx = i0 + lane;
        int s = n2;
        if (idx < end) s = __float_as_int(__ldg(&g_epk[idx]).x);
        int cl = min(32, end - i0);
        int j = 0;
        for (; j + 4 <= cl; j += 4) {
            int s0 = __shfl_sync(0xffffffffu, s, j);
            int s1 = __shfl_sync(0xffffffffu, s, j + 1);
            int s2 = __shfl_sync(0xffffffffu, s, j + 2);
            int s3 = __shfl_sync(0xffffffffu, s, j + 3);
            if (s0 < n2) {
                float4 v = h4_to_f4(*(const uint2*)&g_aggh[(size_t)s0 * H + c]);
                a0.x += v.x; a0.y += v.y; a0.z += v.z; a0.w += v.w;
            }
            if (s1 < n2) {
                float4 v = h4_to_f4(*(const uint2*)&g_aggh[(size_t)s1 * H + c]);
                a1.x += v.x; a1.y += v.y; a1.z += v.z; a1.w += v.w;
            }
            if (s2 < n2) {
                float4 v = h4_to_f4(*(const uint2*)&g_aggh[(size_t)s2 * H + c]);
                a0.x += v.x; a0.y += v.y; a0.z += v.z; a0.w += v.w;
            }
            if (s3 < n2) {
                float4 v = h4_to_f4(*(const uint2*)&g_aggh[(size_t)s3 * H + c]);
                a1.x += v.x; a1.y += v.y; a1.z += v.z; a1.w += v.w;
            }
        }
        for (; j < cl; ++j) {
            int s0 = __shfl_sync(0xffffffffu, s, j);
            if (s0 < n2) {
                float4 v = h4_to_f4(*(const uint2*)&g_aggh[(size_t)s0 * H + c]);
                a0.x += v.x; a0.y += v.y; a0.z += v.z; a0.w += v.w;
            }
        }
    }

    float4 o = make_float4(0.f, 0.f, 0.f, 0.f);
    if (cnt > 0) {
        float sc = 1.f / (float)cnt;
        float4 p1 = *(const float4*)&g_p1f[(size_t)t * H + c];
        float4 bb = *(const float4*)&b[c];
        o.x = (p1.x + a0.x + a1.x) * sc + bb.x;
        o.y = (p1.y + a0.y + a1.y) * sc + bb.y;
        o.z = (p1.z + a0.z + a1.z) * sc + bb.z;
        o.w = (p1.w + a0.w + a1.w) * sc + bb.w;
    }
    *(float4*)&g_s[(size_t)t * H + c] = o;
}

// ---- K7: out = l2norm( mean @ Wl^T + bl + g1 @ Wr^T ) --------------------------
__global__ void __launch_bounds__(256) k_sage_out(
    const float* __restrict__ Wl, const float* __restrict__ bl,
    const float* __restrict__ Wr, int n2, float* __restrict__ out) {
    extern __shared__ float sm[];
    float* Wlt  = sm;
    float* Wrt  = Wlt + H * SW;
    float* ms   = Wrt + H * SW;
    float* gs   = ms  + H * SX;
    float* psum = gs  + H * SX;
    float* scl  = psum + GROWS * 16;

    int row0 = blockIdx.x * GROWS;
    int tid = threadIdx.x;

    for (int idx = tid; idx < H * H; idx += 256) {
        int j = idx >> 7, k = idx & 127;
        Wlt[k * SW + j] = Wl[idx];
        Wrt[k * SW + j] = Wr[idx];
    }
    for (int idx = tid; idx < GROWS * H; idx += 256) {
        int r = idx >> 7, k = idx & 127;
        int row = row0 + r;
        if (row < n2) {
            size_t off = (size_t)row * H + k;
            ms[k * SX + r] = g_s[off];
            gs[k * SX + r] = g_g1f[off];
        } else {
            ms[k * SX + r] = 0.f;
            gs[k * SX + r] = 0.f;
        }
    }
    __syncthreads();

    int col_t = tid & 15;
    int row_t = tid >> 4;
    float acc[4][8];
#pragma unroll
    for (int j = 0; j < 8; ++j) {
        float bv = bl[col_t * 8 + j];
#pragma unroll
        for (int i = 0; i < 4; ++i) acc[i][j] = bv;
    }

    for (int k = 0; k < H; ++k) {
        float4 am4 = *(const float4*)&ms[k * SX + row_t * 4];
        float4 ag4 = *(const float4*)&gs[k * SX + row_t * 4];
        float4 l0 = *(const float4*)&Wlt[k * SW + col_t * 8];
        float4 l1 = *(const float4*)&Wlt[k * SW + col_t * 8 + 4];
        float4 r0 = *(const float4*)&Wrt[k * SW + col_t * 8];
        float4 r1 = *(const float4*)&Wrt[k * SW + col_t * 8 + 4];
        float am[4] = {am4.x, am4.y, am4.z, am4.w};
        float ag[4] = {ag4.x, ag4.y, ag4.z, ag4.w};
        float wl[8] = {l0.x, l0.y, l0.z, l0.w, l1.x, l1.y, l1.z, l1.w};
        float wr[8] = {r0.x, r0.y, r0.z, r0.w, r1.x, r1.y, r1.z, r1.w};
#pragma unroll
        for (int i = 0; i < 4; ++i)
#pragma unroll
            for (int j = 0; j < 8; ++j)
                acc[i][j] += am[i] * wl[j] + ag[i] * wr[j];
    }

#pragma unroll
    for (int i = 0; i < 4; ++i) {
        float loc = 0.f;
#pragma unroll
        for (int j = 0; j < 8; ++j) loc += acc[i][j] * acc[i][j];
        psum[(row_t * 4 + i) * 16 + col_t] = loc;
    }
    __syncthreads();
    if (tid < GROWS) {
        float ssum = 0.f;
#pragma unroll
        for (int cc = 0; cc < 16; ++cc) ssum += psum[tid * 16 + cc];
        scl[tid] = 1.f / fmaxf(sqrtf(ssum), 1e-12f);
    }
    __syncthreads();

#pragma unroll
    for (int i = 0; i < 4; ++i) {
        int row = row0 + row_t * 4 + i;
        if (row < n2) {
            float sc = scl[row_t * 4 + i];
            float4 o0 = make_float4(acc[i][0] * sc, acc[i][1] * sc,
                                    acc[i][2] * sc, acc[i][3] * sc);
            float4 o1 = make_float4(acc[i][4] * sc, acc[i][5] * sc,
                                    acc[i][6] * sc, acc[i][7] * sc);
            *(float4*)&out[(size_t)row * H + col_t * 8]     = o0;
            *(float4*)&out[(size_t)row * H + col_t * 8 + 4] = o1;
        }
    }
}

// ---------------------------------------------------------------------------
extern "C" void kernel_launch(void* const* d_in, const int* in_sizes, int n_in,
                              void* d_out, int out_size) {
    const float* x     = (const float*)d_in[0];
    const float* attr  = (const float*)d_in[1];
    const int*   e_id1 = (const int*)d_in[3];
    const int*   src1  = (const int*)d_in[6];
    const int*   tgt1  = (const int*)d_in[7];
    const int*   n1p   = (const int*)d_in[8];
    const float* gcn_W = (const float*)d_in[10];
    const float* gcn_b = (const float*)d_in[11];
    const float* Wl1   = (const float*)d_in[15];
    const float* bl1   = (const float*)d_in[16];
    const float* Wr1   = (const float*)d_in[17];
    float* out = (float*)d_out;

    int N0 = in_sizes[0] / H;  if (N0 > MAXN0) N0 = MAXN0;
    int E1 = in_sizes[3];      if (E1 > MAXE)  E1 = MAXE;
    int n2 = out_size / H;     if (n2 > MAXN2) n2 = MAXN2;

    constexpr int SMEM_GEMM = 128 * XST * 2 * 4;
    constexpr int SMEM_SCAN = MAXN2 * 4;
    constexpr int SMEM_K8 = (2 * H * SW + 2 * H * SX + GROWS * 16 + GROWS) * 4;
    cudaFuncSetAttribute(k_gemm_tc, cudaFuncAttributeMaxDynamicSharedMemorySize, SMEM_GEMM);
    cudaFuncSetAttribute(k_scan, cudaFuncAttributeMaxDynamicSharedMemorySize, SMEM_SCAN);
    cudaFuncSetAttribute(k_sage_out, cudaFuncAttributeMaxDynamicSharedMemorySize, SMEM_K8);

    cudaStream_t s2;
    cudaStreamCreateWithFlags(&s2, cudaStreamNonBlocking);
    cudaEvent_t evFork, evGemm;
    cudaEventCreateWithFlags(&evFork, cudaEventDisableTiming);
    cudaEventCreateWithFlags(&evGemm, cudaEventDisableTiming);

    // Fork: GEMM on side stream.
    cudaEventRecord(evFork, 0);
    cudaStreamWaitEvent(s2, evFork, 0);
    k_gemm_tc<<<(N0 + 127) / 128, 256, SMEM_GEMM, s2>>>(x, gcn_W, n1p, N0);
    cudaEventRecord(evGemm, s2);

    // Main stream: edge preprocessing (g_hd arrives zero: BSS / self-restored).
    k_hist<<<(E1 + 511) / 512, 256>>>(attr, e_id1, tgt1, E1, n2);
    k_scan<<<1, 1024, SMEM_SCAN>>>(n2);
    k_scatter<<<(E1 + 511) / 512, 256>>>(src1, tgt1, E1, n2);

    cudaStreamWaitEvent(0, evGemm, 0);  // join

    k_gather_gcn<<<(n2 + 7) / 8, 256>>>(gcn_b, n2);
    k_sage2<<<(n2 + 7) / 8, 256>>>(gcn_b, n2);
    k_sage_out<<<(n2 + GROWS - 1) / GROWS, 256, SMEM_K8>>>(Wl1, bl1, Wr1, n2, out);
}

// round 12
// speedup vs baseline: 1.4539x; 1.0942x over previous
#include <cuda_runtime.h>
#include <cuda_fp16.h>
#include <cstdint>

// ---------------------------------------------------------------------------
// GlobalGNN layer-1-only pipeline:
//   s2  : xW = x@gcn_W^T (fp16 MMA m16n8k16, fp32 accum, fp16 out)
//   main: hist(x2) -> scan(g_off excl + g_hd inclusive-end) -> scatter(x2)
//   join: gather_gcn (agg,p1,g1) -> sage2 (p2,mean; restores g_hd)
//         -> sage_out (GEMM + l2norm)
// State is self-restoring across graph replays (no memset node).
// ---------------------------------------------------------------------------

#define H 128
#define MAXN0 131072
#define MAXN2 16384
#define MAXE  1048576
#define GROWS 64
#define SW 132
#define SX 68
#define HSTR 136   // halves per smem row (128 + 8 pad): bank = 4*lq + lr, conflict-free

__device__ __align__(16) __half g_xWh [(size_t)MAXN0 * H];
__device__ __align__(16) __half g_aggh[(size_t)MAXN2 * H];
__device__ __align__(16) float  g_g1f [(size_t)MAXN2 * H];
__device__ __align__(16) float  g_p1f [(size_t)MAXN2 * H];
__device__ __align__(16) float  g_s   [(size_t)MAXN2 * H];
__device__ __align__(16) int    g_hd  [2 * MAXN2];   // [i]=count/end-pos, [MAXN2+i]=degx bits
__device__ __align__(16) int    g_off [MAXN2 + 4];
__device__ __align__(16) float2 g_epk [MAXE];        // (.x=src bits, .y=w)
__device__ __align__(16) float  g_wst [MAXE];

__device__ __forceinline__ int clamp_n1(const int* p, int N0) {
    int v = *p;
    if (v <= 0 || v > N0) v = N0;
    return v;
}

__device__ __forceinline__ float4 h4_to_f4(uint2 raw) {
    __half2 h0 = *reinterpret_cast<__half2*>(&raw.x);
    __half2 h1 = *reinterpret_cast<__half2*>(&raw.y);
    float2 f0 = __half22float2(h0);
    float2 f1 = __half22float2(h1);
    return make_float4(f0.x, f0.y, f1.x, f1.y);
}

__device__ __forceinline__ uint2 f4_to_h4(float4 v) {
    __half2 h0 = __floats2half2_rn(v.x, v.y);
    __half2 h1 = __floats2half2_rn(v.z, v.w);
    uint2 r;
    r.x = *reinterpret_cast<uint32_t*>(&h0);
    r.y = *reinterpret_cast<uint32_t*>(&h1);
    return r;
}

#define MMA_F16(d, a0, a1, a2, a3, b0, b1)                                    \
    asm volatile(                                                             \
        "mma.sync.aligned.m16n8k16.row.col.f32.f16.f16.f32 "                  \
        "{%0,%1,%2,%3},{%4,%5,%6,%7},{%8,%9},{%0,%1,%2,%3};"                  \
        : "+f"(d[0]), "+f"(d[1]), "+f"(d[2]), "+f"(d[3])                      \
        : "r"(a0), "r"(a1), "r"(a2), "r"(a3), "r"(b0), "r"(b1))

// ---- K1: histogram + weighted degree + weight staging, 2 edges/thread ---------
__global__ void k_hist(const float* __restrict__ attr, const int* __restrict__ eid,
                       const int* __restrict__ tgt, int E, int n2) {
    int base = (blockIdx.x * blockDim.x + threadIdx.x) * 2;
    if (base >= E) return;
    if (base + 2 <= E) {
        int2 t2  = *(const int2*)&tgt[base];
        int2 id2 = *(const int2*)&eid[base];
        float w0 = __ldg(&attr[id2.x]);
        float w1 = __ldg(&attr[id2.y]);
        *(float2*)&g_wst[base] = make_float2(w0, w1);
        if (t2.x < n2) { atomicAdd(&g_hd[t2.x], 1); atomicAdd((float*)&g_hd[MAXN2 + t2.x], w0); }
        if (t2.y < n2) { atomicAdd(&g_hd[t2.y], 1); atomicAdd((float*)&g_hd[MAXN2 + t2.y], w1); }
    } else {
        int t = __ldg(&tgt[base]);
        float w = __ldg(&attr[__ldg(&eid[base])]);
        g_wst[base] = w;
        if (t < n2) {
            atomicAdd(&g_hd[t], 1);
            atomicAdd((float*)&g_hd[MAXN2 + t], w);
        }
    }
}

// ---- K2: scan: g_off[i]=exclusive, g_hd[i]=inclusive end (i<n2) ----------------
__global__ void __launch_bounds__(1024) k_scan(int n2) {
    extern __shared__ int sh[];
    __shared__ int wsum[32];
    int tid = threadIdx.x, lane = tid & 31, wid = tid >> 5;

    int n2v = (n2 + 3) >> 2;
    const int4* cnt4 = (const int4*)g_hd;
    for (int v = tid; v < n2v; v += 1024)
        ((int4*)sh)[v] = cnt4[v];
    for (int v = n2v + tid; v < MAXN2 / 4; v += 1024)
        ((int4*)sh)[v] = make_int4(0, 0, 0, 0);
    __syncthreads();

    int base = tid * 16;
    int vals[16], cnts[16];
    int local = 0;
#pragma unroll
    for (int i4 = 0; i4 < 4; ++i4) {
        int4 q = *(const int4*)&sh[base + i4 * 4];
        int cc[4] = {q.x, q.y, q.z, q.w};
#pragma unroll
        for (int j = 0; j < 4; ++j) {
            vals[i4 * 4 + j] = local;
            cnts[i4 * 4 + j] = cc[j];
            local += cc[j];
        }
    }
    int inc = local;
#pragma unroll
    for (int off = 1; off < 32; off <<= 1) {
        int nb = __shfl_up_sync(0xffffffffu, inc, off);
        if (lane >= off) inc += nb;
    }
    if (lane == 31) wsum[wid] = inc;
    __syncthreads();
    if (wid == 0) {
        int s = wsum[lane];
#pragma unroll
        for (int off = 1; off < 32; off <<= 1) {
            int nb = __shfl_up_sync(0xffffffffu, s, off);
            if (lane >= off) s += nb;
        }
        wsum[lane] = s;
    }
    __syncthreads();
    int excl = ((wid > 0) ? wsum[wid - 1] : 0) + inc - local;
#pragma unroll
    for (int i4 = 0; i4 < 4; ++i4) {
        int4 q = make_int4(excl + vals[i4 * 4],     excl + vals[i4 * 4 + 1],
                           excl + vals[i4 * 4 + 2], excl + vals[i4 * 4 + 3]);
        *(int4*)&sh[base + i4 * 4] = q;
        int idx = base + i4 * 4;
        if (idx + 3 < n2) {
            int4 e = make_int4(q.x + cnts[i4 * 4],     q.y + cnts[i4 * 4 + 1],
                               q.z + cnts[i4 * 4 + 2], q.w + cnts[i4 * 4 + 3]);
            *(int4*)&g_hd[idx] = e;
        } else {
#pragma unroll
            for (int j = 0; j < 4; ++j)
                if (idx + j < n2)
                    g_hd[idx + j] = (&q.x)[j] + cnts[i4 * 4 + j];
        }
    }
    int total = wsum[31];
    __syncthreads();
    int4* off4 = (int4*)g_off;
    for (int v = tid; v < n2v; v += 1024)
        off4[v] = ((const int4*)sh)[v];
    if (tid == 0) g_off[n2] = total;
}

// ---- K3: scatter (countdown on end positions), 2 edges/thread ------------------
__global__ void k_scatter(const int* __restrict__ src, const int* __restrict__ tgt,
                          int E, int n2) {
    int base = (blockIdx.x * blockDim.x + threadIdx.x) * 2;
    if (base >= E) return;
    int t[2], s[2];
    float w[2];
    if (base + 2 <= E) {
        int2 t2 = *(const int2*)&tgt[base];
        int2 s2 = *(const int2*)&src[base];
        float2 w2 = *(const float2*)&g_wst[base];
        t[0] = t2.x; t[1] = t2.y;
        s[0] = s2.x; s[1] = s2.y;
        w[0] = w2.x; w[1] = w2.y;
    } else {
        t[0] = __ldg(&tgt[base]); t[1] = n2;
        s[0] = __ldg(&src[base]); s[1] = 0;
        w[0] = __ldg(&g_wst[base]); w[1] = 0.f;
    }
    int pos[2];
#pragma unroll
    for (int j = 0; j < 2; ++j)
        pos[j] = (t[j] < n2) ? (atomicAdd(&g_hd[t[j]], -1) - 1) : -1;
#pragma unroll
    for (int j = 0; j < 2; ++j)
        if (pos[j] >= 0)
            g_epk[pos[j]] = make_float2(__int_as_float(s[j]), w[j]);
}

// ---- K4: xW = x @ W^T via fp16 MMA (m16n8k16, fp32 accum), rows < n1 -----------
__global__ void __launch_bounds__(256) k_gemm_tc(
    const float* __restrict__ x, const float* __restrict__ W,
    const int* __restrict__ n1p, int N0) {
    extern __shared__ __half hsm[];
    __half* xs = hsm;                  // [128][HSTR]
    __half* ws = hsm + 128 * HSTR;     // [128][HSTR]

    int n1 = clamp_n1(n1p, N0);
    int row0 = blockIdx.x * 128;
    if (row0 >= n1) return;

    int tid = threadIdx.x, lane = tid & 31, warp = tid >> 5;
    int wm = warp >> 1, wn = warp & 1;  // 4 row-slabs x 2 col-slabs
    int lq = lane >> 2, lr = lane & 3;

    // load + convert fp32 -> fp16 (whole K=128 tile resident)
#pragma unroll
    for (int it = 0; it < 16; ++it) {
        int f4 = it * 256 + tid;       // 4096 float4 chunks per matrix
        int r = f4 >> 5, k4 = f4 & 31;
        int row = row0 + r;
        float4 v = make_float4(0.f, 0.f, 0.f, 0.f);
        if (row < N0) v = *(const float4*)&x[(size_t)row * H + k4 * 4];
        *(uint2*)&xs[r * HSTR + k4 * 4] = f4_to_h4(v);
        float4 wv = *(const float4*)&W[(size_t)r * H + k4 * 4];
        *(uint2*)&ws[r * HSTR + k4 * 4] = f4_to_h4(wv);
    }
    __syncthreads();

    float acc[2][8][4];
#pragma unroll
    for (int mi = 0; mi < 2; ++mi)
#pragma unroll
        for (int ni = 0; ni < 8; ++ni)
#pragma unroll
            for (int j = 0; j < 4; ++j) acc[mi][ni][j] = 0.f;

#pragma unroll
    for (int ks = 0; ks < 8; ++ks) {
        int kb = ks * 16;
        uint32_t a[2][4];
#pragma unroll
        for (int mi = 0; mi < 2; ++mi) {
            int r0 = wm * 32 + mi * 16 + lq;
            a[mi][0] = *(const uint32_t*)&xs[r0 * HSTR + kb + lr * 2];
            a[mi][1] = *(const uint32_t*)&xs[(r0 + 8) * HSTR + kb + lr * 2];
            a[mi][2] = *(const uint32_t*)&xs[r0 * HSTR + kb + 8 + lr * 2];
            a[mi][3] = *(const uint32_t*)&xs[(r0 + 8) * HSTR + kb + 8 + lr * 2];
        }
#pragma unroll
        for (int ni = 0; ni < 8; ++ni) {
            int n = wn * 64 + ni * 8 + lq;
            uint32_t b0 = *(const uint32_t*)&ws[n * HSTR + kb + lr * 2];
            uint32_t b1 = *(const uint32_t*)&ws[n * HSTR + kb + 8 + lr * 2];
#pragma unroll
            for (int mi = 0; mi < 2; ++mi)
                MMA_F16(acc[mi][ni], a[mi][0], a[mi][1], a[mi][2], a[mi][3], b0, b1);
        }
    }

#pragma unroll
    for (int mi = 0; mi < 2; ++mi) {
        int r0 = row0 + wm * 32 + mi * 16 + lq;
#pragma unroll
        for (int ni = 0; ni < 8; ++ni) {
            int col = wn * 64 + ni * 8 + lr * 2;
            if (r0 < n1) {
                __half2 h = __floats2half2_rn(acc[mi][ni][0], acc[mi][ni][1]);
                *(__half2*)&g_xWh[(size_t)r0 * H + col] = h;
            }
            if (r0 + 8 < n1) {
                __half2 h = __floats2half2_rn(acc[mi][ni][2], acc[mi][ni][3]);
                *(__half2*)&g_xWh[(size_t)(r0 + 8) * H + col] = h;
            }
        }
    }
}

// ---- K5: GCN gather + SAGE partial p1 (t<n2), warp per target ------------------
__global__ void __launch_bounds__(256) k_gather_gcn(const float* __restrict__ b, int n2) {
    int t = blockIdx.x * 8 + (threadIdx.x >> 5);
    if (t >= n2) return;
    int lane = threadIdx.x & 31;
    int c = lane * 4;
    int base = __ldg(&g_off[t]);
    int end  = __ldg(&g_off[t + 1]);

    float4 ag0 = make_float4(0.f, 0.f, 0.f, 0.f), ag1 = ag0;
    float4 ap0 = ag0, ap1 = ag0;

    for (int i0 = base; i0 < end; i0 += 32) {
        int idx = i0 + lane;
        int s = 0; float nm = 0.f, u = 0.f;
        if (idx < end) {
            float2 p = __ldg(&g_epk[idx]);
            s = __float_as_int(p.x);
            float w = p.y;
            float ds = 1.f, d2 = 1.f;
            if (s < n2) {
                float dg = __int_as_float(__ldg(&g_hd[MAXN2 + s]));
                d2 = 1.f / (1.f + dg);
                ds = rsqrtf(1.f + dg);
            }
            nm = ds * w;
            u = d2;
        }
        int cnt = min(32, end - i0);
        int j = 0;
        for (; j + 4 <= cnt; j += 4) {
            int   s0 = __shfl_sync(0xffffffffu, s, j);
            float w0 = __shfl_sync(0xffffffffu, nm, j);
            float u0 = __shfl_sync(0xffffffffu, u, j);
            int   s1 = __shfl_sync(0xffffffffu, s, j + 1);
            float w1 = __shfl_sync(0xffffffffu, nm, j + 1);
            float u1 = __shfl_sync(0xffffffffu, u, j + 1);
            int   s2 = __shfl_sync(0xffffffffu, s, j + 2);
            float w2 = __shfl_sync(0xffffffffu, nm, j + 2);
            float u2 = __shfl_sync(0xffffffffu, u, j + 2);
            int   s3 = __shfl_sync(0xffffffffu, s, j + 3);
            float w3 = __shfl_sync(0xffffffffu, nm, j + 3);
            float u3 = __shfl_sync(0xffffffffu, u, j + 3);
            float4 v0 = h4_to_f4(*(const uint2*)&g_xWh[(size_t)s0 * H + c]);
            float4 v1 = h4_to_f4(*(const uint2*)&g_xWh[(size_t)s1 * H + c]);
            float4 v2 = h4_to_f4(*(const uint2*)&g_xWh[(size_t)s2 * H + c]);
            float4 v3 = h4_to_f4(*(const uint2*)&g_xWh[(size_t)s3 * H + c]);
            ag0.x += w0 * v0.x; ag0.y += w0 * v0.y; ag0.z += w0 * v0.z; ag0.w += w0 * v0.w;
            ap0.x += u0 * v0.x; ap0.y += u0 * v0.y; ap0.z += u0 * v0.z; ap0.w += u0 * v0.w;
            ag1.x += w1 * v1.x; ag1.y += w1 * v1.y; ag1.z += w1 * v1.z; ag1.w += w1 * v1.w;
            ap1.x += u1 * v1.x; ap1.y += u1 * v1.y; ap1.z += u1 * v1.z; ap1.w += u1 * v1.w;
            ag0.x += w2 * v2.x; ag0.y += w2 * v2.y; ag0.z += w2 * v2.z; ag0.w += w2 * v2.w;
            ap0.x += u2 * v2.x; ap0.y += u2 * v2.y; ap0.z += u2 * v2.z; ap0.w += u2 * v2.w;
            ag1.x += w3 * v3.x; ag1.y += w3 * v3.y; ag1.z += w3 * v3.z; ag1.w += w3 * v3.w;
            ap1.x += u3 * v3.x; ap1.y += u3 * v3.y; ap1.z += u3 * v3.z; ap1.w += u3 * v3.w;
        }
        for (; j < cnt; ++j) {
            int   s0 = __shfl_sync(0xffffffffu, s, j);
            float w0 = __shfl_sync(0xffffffffu, nm, j);
            float u0 = __shfl_sync(0xffffffffu, u, j);
            float4 v0 = h4_to_f4(*(const uint2*)&g_xWh[(size_t)s0 * H + c]);
            ag0.x += w0 * v0.x; ag0.y += w0 * v0.y; ag0.z += w0 * v0.z; ag0.w += w0 * v0.w;
            ap0.x += u0 * v0.x; ap0.y += u0 * v0.y; ap0.z += u0 * v0.z; ap0.w += u0 * v0.w;
        }
    }

    float degt = __int_as_float(g_hd[MAXN2 + t]);
    float dt  = rsqrtf(1.f + degt);
    float d2t = 1.f / (1.f + degt);
    float4 agg;
    agg.x = (ag0.x + ag1.x) * dt;
    agg.y = (ag0.y + ag1.y) * dt;
    agg.z = (ag0.z + ag1.z) * dt;
    agg.w = (ag0.w + ag1.w) * dt;
    float4 p1 = make_float4(ap0.x + ap1.x, ap0.y + ap1.y, ap0.z + ap1.z, ap0.w + ap1.w);
    float4 xw = h4_to_f4(*(const uint2*)&g_xWh[(size_t)t * H + c]);
    float4 bb = *(const float4*)&b[c];
    float4 g1;
    g1.x = agg.x + xw.x * d2t + bb.x;
    g1.y = agg.y + xw.y * d2t + bb.y;
    g1.z = agg.z + xw.z * d2t + bb.z;
    g1.w = agg.w + xw.w * d2t + bb.w;
    *(float4*)&g_g1f[(size_t)t * H + c] = g1;
    *(uint2*)&g_aggh[(size_t)t * H + c] = f4_to_h4(agg);
    *(float4*)&g_p1f[(size_t)t * H + c] = p1;
}

// ---- K6: SAGE p2 gather + mean; restores g_hd[t] to zero -----------------------
__global__ void __launch_bounds__(256) k_sage2(const float* __restrict__ b, int n2) {
    int t = blockIdx.x * 8 + (threadIdx.x >> 5);
    if (t >= n2) return;
    int lane = threadIdx.x & 31;
    int c = lane * 4;
    int base = __ldg(&g_off[t]);
    int end  = __ldg(&g_off[t + 1]);
    int cnt = end - base;

    if (lane == 0) { g_hd[t] = 0; g_hd[MAXN2 + t] = 0; }

    float4 a0 = make_float4(0.f, 0.f, 0.f, 0.f), a1 = a0;

    for (int i0 = base; i0 < end; i0 += 32) {
        int idx = i0 + lane;
        int s = n2;
        if (idx < end) s = __float_as_int(__ldg(&g_epk[idx]).x);
        int cl = min(32, end - i0);
        int j = 0;
        for (; j + 4 <= cl; j += 4) {
            int s0 = __shfl_sync(0xffffffffu, s, j);
            int s1 = __shfl_sync(0xffffffffu, s, j + 1);
            int s2 = __shfl_sync(0xffffffffu, s, j + 2);
            int s3 = __shfl_sync(0xffffffffu, s, j + 3);
            if (s0 < n2) {
                float4 v = h4_to_f4(*(const uint2*)&g_aggh[(size_t)s0 * H + c]);
                a0.x += v.x; a0.y += v.y; a0.z += v.z; a0.w += v.w;
            }
            if (s1 < n2) {
                float4 v = h4_to_f4(*(const uint2*)&g_aggh[(size_t)s1 * H + c]);
                a1.x += v.x; a1.y += v.y; a1.z += v.z; a1.w += v.w;
            }
            if (s2 < n2) {
                float4 v = h4_to_f4(*(const uint2*)&g_aggh[(size_t)s2 * H + c]);
                a0.x += v.x; a0.y += v.y; a0.z += v.z; a0.w += v.w;
            }
            if (s3 < n2) {
                float4 v = h4_to_f4(*(const uint2*)&g_aggh[(size_t)s3 * H + c]);
                a1.x += v.x; a1.y += v.y; a1.z += v.z; a1.w += v.w;
            }
        }
        for (; j < cl; ++j) {
            int s0 = __shfl_sync(0xffffffffu, s, j);
            if (s0 < n2) {
                float4 v = h4_to_f4(*(const uint2*)&g_aggh[(size_t)s0 * H + c]);
                a0.x += v.x; a0.y += v.y; a0.z += v.z; a0.w += v.w;
            }
        }
    }

    float4 o = make_float4(0.f, 0.f, 0.f, 0.f);
    if (cnt > 0) {
        float sc = 1.f / (float)cnt;
        float4 p1 = *(const float4*)&g_p1f[(size_t)t * H + c];
        float4 bb = *(const float4*)&b[c];
        o.x = (p1.x + a0.x + a1.x) * sc + bb.x;
        o.y = (p1.y + a0.y + a1.y) * sc + bb.y;
        o.z = (p1.z + a0.z + a1.z) * sc + bb.z;
        o.w = (p1.w + a0.w + a1.w) * sc + bb.w;
    }
    *(float4*)&g_s[(size_t)t * H + c] = o;
}

// ---- K7: out = l2norm( mean @ Wl^T + bl + g1 @ Wr^T ) --------------------------
__global__ void __launch_bounds__(256) k_sage_out(
    const float* __restrict__ Wl, const float* __restrict__ bl,
    const float* __restrict__ Wr, int n2, float* __restrict__ out) {
    extern __shared__ float sm[];
    float* Wlt  = sm;
    float* Wrt  = Wlt + H * SW;
    float* ms   = Wrt + H * SW;
    float* gs   = ms  + H * SX;
    float* psum = gs  + H * SX;
    float* scl  = psum + GROWS * 16;

    int row0 = blockIdx.x * GROWS;
    int tid = threadIdx.x;

    for (int idx = tid; idx < H * H; idx += 256) {
        int j = idx >> 7, k = idx & 127;
        Wlt[k * SW + j] = Wl[idx];
        Wrt[k * SW + j] = Wr[idx];
    }
    for (int idx = tid; idx < GROWS * H; idx += 256) {
        int r = idx >> 7, k = idx & 127;
        int row = row0 + r;
        if (row < n2) {
            size_t off = (size_t)row * H + k;
            ms[k * SX + r] = g_s[off];
            gs[k * SX + r] = g_g1f[off];
        } else {
            ms[k * SX + r] = 0.f;
            gs[k * SX + r] = 0.f;
        }
    }
    __syncthreads();

    int col_t = tid & 15;
    int row_t = tid >> 4;
    float acc[4][8];
#pragma unroll
    for (int j = 0; j < 8; ++j) {
        float bv = bl[col_t * 8 + j];
#pragma unroll
        for (int i = 0; i < 4; ++i) acc[i][j] = bv;
    }

    for (int k = 0; k < H; ++k) {
        float4 am4 = *(const float4*)&ms[k * SX + row_t * 4];
        float4 ag4 = *(const float4*)&gs[k * SX + row_t * 4];
        float4 l0 = *(const float4*)&Wlt[k * SW + col_t * 8];
        float4 l1 = *(const float4*)&Wlt[k * SW + col_t * 8 + 4];
        float4 r0 = *(const float4*)&Wrt[k * SW + col_t * 8];
        float4 r1 = *(const float4*)&Wrt[k * SW + col_t * 8 + 4];
        float am[4] = {am4.x, am4.y, am4.z, am4.w};
        float ag[4] = {ag4.x, ag4.y, ag4.z, ag4.w};
        float wl[8] = {l0.x, l0.y, l0.z, l0.w, l1.x, l1.y, l1.z, l1.w};
        float wr[8] = {r0.x, r0.y, r0.z, r0.w, r1.x, r1.y, r1.z, r1.w};
#pragma unroll
        for (int i = 0; i < 4; ++i)
#pragma unroll
            for (int j = 0; j < 8; ++j)
                acc[i][j] += am[i] * wl[j] + ag[i] * wr[j];
    }

#pragma unroll
    for (int i = 0; i < 4; ++i) {
        float loc = 0.f;
#pragma unroll
        for (int j = 0; j < 8; ++j) loc += acc[i][j] * acc[i][j];
        psum[(row_t * 4 + i) * 16 + col_t] = loc;
    }
    __syncthreads();
    if (tid < GROWS) {
        float ssum = 0.f;
#pragma unroll
        for (int cc = 0; cc < 16; ++cc) ssum += psum[tid * 16 + cc];
        scl[tid] = 1.f / fmaxf(sqrtf(ssum), 1e-12f);
    }
    __syncthreads();

#pragma unroll
    for (int i = 0; i < 4; ++i) {
        int row = row0 + row_t * 4 + i;
        if (row < n2) {
            float sc = scl[row_t * 4 + i];
            float4 o0 = make_float4(acc[i][0] * sc, acc[i][1] * sc,
                                    acc[i][2] * sc, acc[i][3] * sc);
            float4 o1 = make_float4(acc[i][4] * sc, acc[i][5] * sc,
                                    acc[i][6] * sc, acc[i][7] * sc);
            *(float4*)&out[(size_t)row * H + col_t * 8]     = o0;
            *(float4*)&out[(size_t)row * H + col_t * 8 + 4] = o1;
        }
    }
}

// ---------------------------------------------------------------------------
extern "C" void kernel_launch(void* const* d_in, const int* in_sizes, int n_in,
                              void* d_out, int out_size) {
    const float* x     = (const float*)d_in[0];
    const float* attr  = (const float*)d_in[1];
    const int*   e_id1 = (const int*)d_in[3];
    const int*   src1  = (const int*)d_in[6];
    const int*   tgt1  = (const int*)d_in[7];
    const int*   n1p   = (const int*)d_in[8];
    const float* gcn_W = (const float*)d_in[10];
    const float* gcn_b = (const float*)d_in[11];
    const float* Wl1   = (const float*)d_in[15];
    const float* bl1   = (const float*)d_in[16];
    const float* Wr1   = (const float*)d_in[17];
    float* out = (float*)d_out;

    int N0 = in_sizes[0] / H;  if (N0 > MAXN0) N0 = MAXN0;
    int E1 = in_sizes[3];      if (E1 > MAXE)  E1 = MAXE;
    int n2 = out_size / H;     if (n2 > MAXN2) n2 = MAXN2;

    constexpr int SMEM_GEMM = 2 * 128 * HSTR * 2;   // two fp16 tiles: 69,632 B
    constexpr int SMEM_SCAN = MAXN2 * 4;
    constexpr int SMEM_K8 = (2 * H * SW + 2 * H * SX + GROWS * 16 + GROWS) * 4;
    cudaFuncSetAttribute(k_gemm_tc, cudaFuncAttributeMaxDynamicSharedMemorySize, SMEM_GEMM);
    cudaFuncSetAttribute(k_scan, cudaFuncAttributeMaxDynamicSharedMemorySize, SMEM_SCAN);
    cudaFuncSetAttribute(k_sage_out, cudaFuncAttributeMaxDynamicSharedMemorySize, SMEM_K8);

    cudaStream_t s2;
    cudaStreamCreateWithFlags(&s2, cudaStreamNonBlocking);
    cudaEvent_t evFork, evGemm;
    cudaEventCreateWithFlags(&evFork, cudaEventDisableTiming);
    cudaEventCreateWithFlags(&evGemm, cudaEventDisableTiming);

    // Fork: GEMM on side stream.
    cudaEventRecord(evFork, 0);
    cudaStreamWaitEvent(s2, evFork, 0);
    k_gemm_tc<<<(N0 + 127) / 128, 256, SMEM_GEMM, s2>>>(x, gcn_W, n1p, N0);
    cudaEventRecord(evGemm, s2);

    // Main stream: edge preprocessing (g_hd arrives zero: BSS / self-restored).
    k_hist<<<(E1 + 511) / 512, 256>>>(attr, e_id1, tgt1, E1, n2);
    k_scan<<<1, 1024, SMEM_SCAN>>>(n2);
    k_scatter<<<(E1 + 511) / 512, 256>>>(src1, tgt1, E1, n2);

    cudaStreamWaitEvent(0, evGemm, 0);  // join

    k_gather_gcn<<<(n2 + 7) / 8, 256>>>(gcn_b, n2);
    k_sage2<<<(n2 + 7) / 8, 256>>>(gcn_b, n2);
    k_sage_out<<<(n2 + GROWS - 1) / GROWS, 256, SMEM_K8>>>(Wl1, bl1, Wr1, n2, out);
}

// round 13
// speedup vs baseline: 2.1937x; 1.5088x over previous
#include <cuda_runtime.h>
#include <cuda_fp16.h>
#include <cstdint>

// ---------------------------------------------------------------------------
// GlobalGNN layer-1-only pipeline:
//   s2  : xW = x@gcn_W^T (fp16 MMA m16n8k16, fp32 accum, fp16 out)
//   main: hist(x2) -> scan(g_off excl + g_hd inclusive-end) -> scatter(x2)
//   join: gather_gcn (agg,p1,g1[fp16]) -> sage2 (mean[fp16]; restores g_hd)
//         -> sage_out (single K=256 fp16 MMA GEMM: [mean|g1]@[Wl|Wr]^T + l2norm)
// ---------------------------------------------------------------------------

#define H 128
#define MAXN0 131072
#define MAXN2 16384
#define MAXE  1048576
#define GROWS 64
#define HSTR 136   // halves/row for 128-wide fp16 tiles (132 words? no: 68 words, %32=4)
#define HS2  264   // halves/row for 256-wide fp16 tiles (132 words, %32=4) conflict-free

__device__ __align__(16) __half g_xWh  [(size_t)MAXN0 * H];
__device__ __align__(16) __half g_aggh [(size_t)MAXN2 * H];
__device__ __align__(16) __half g_g1h  [(size_t)MAXN2 * H];
__device__ __align__(16) __half g_meanh[(size_t)MAXN2 * H];
__device__ __align__(16) float  g_p1f  [(size_t)MAXN2 * H];
__device__ __align__(16) int    g_hd   [2 * MAXN2];  // [i]=count/end-pos, [MAXN2+i]=degx
__device__ __align__(16) int    g_off  [MAXN2 + 4];
__device__ __align__(16) float2 g_epk  [MAXE];       // (.x=src bits, .y=w)
__device__ __align__(16) float  g_wst  [MAXE];

__device__ __forceinline__ int clamp_n1(const int* p, int N0) {
    int v = *p;
    if (v <= 0 || v > N0) v = N0;
    return v;
}

__device__ __forceinline__ float4 h4_to_f4(uint2 raw) {
    __half2 h0 = *reinterpret_cast<__half2*>(&raw.x);
    __half2 h1 = *reinterpret_cast<__half2*>(&raw.y);
    float2 f0 = __half22float2(h0);
    float2 f1 = __half22float2(h1);
    return make_float4(f0.x, f0.y, f1.x, f1.y);
}

__device__ __forceinline__ uint2 f4_to_h4(float4 v) {
    __half2 h0 = __floats2half2_rn(v.x, v.y);
    __half2 h1 = __floats2half2_rn(v.z, v.w);
    uint2 r;
    r.x = *reinterpret_cast<uint32_t*>(&h0);
    r.y = *reinterpret_cast<uint32_t*>(&h1);
    return r;
}

#define MMA_F16(d, a0, a1, a2, a3, b0, b1)                                    \
    asm volatile(                                                             \
        "mma.sync.aligned.m16n8k16.row.col.f32.f16.f16.f32 "                  \
        "{%0,%1,%2,%3},{%4,%5,%6,%7},{%8,%9},{%0,%1,%2,%3};"                  \
        : "+f"(d[0]), "+f"(d[1]), "+f"(d[2]), "+f"(d[3])                      \
        : "r"(a0), "r"(a1), "r"(a2), "r"(a3), "r"(b0), "r"(b1))

// ---- K1: histogram + weighted degree + weight staging, 2 edges/thread ---------
__global__ void k_hist(const float* __restrict__ attr, const int* __restrict__ eid,
                       const int* __restrict__ tgt, int E, int n2) {
    int base = (blockIdx.x * blockDim.x + threadIdx.x) * 2;
    if (base >= E) return;
    if (base + 2 <= E) {
        int2 t2  = *(const int2*)&tgt[base];
        int2 id2 = *(const int2*)&eid[base];
        float w0 = __ldg(&attr[id2.x]);
        float w1 = __ldg(&attr[id2.y]);
        *(float2*)&g_wst[base] = make_float2(w0, w1);
        if (t2.x < n2) { atomicAdd(&g_hd[t2.x], 1); atomicAdd((float*)&g_hd[MAXN2 + t2.x], w0); }
        if (t2.y < n2) { atomicAdd(&g_hd[t2.y], 1); atomicAdd((float*)&g_hd[MAXN2 + t2.y], w1); }
    } else {
        int t = __ldg(&tgt[base]);
        float w = __ldg(&attr[__ldg(&eid[base])]);
        g_wst[base] = w;
        if (t < n2) {
            atomicAdd(&g_hd[t], 1);
            atomicAdd((float*)&g_hd[MAXN2 + t], w);
        }
    }
}

// ---- K2: scan: g_off[i]=exclusive, g_hd[i]=inclusive end (i<n2) ----------------
__global__ void __launch_bounds__(1024) k_scan(int n2) {
    extern __shared__ int sh[];
    __shared__ int wsum[32];
    int tid = threadIdx.x, lane = tid & 31, wid = tid >> 5;

    int n2v = (n2 + 3) >> 2;
    const int4* cnt4 = (const int4*)g_hd;
    for (int v = tid; v < n2v; v += 1024)
        ((int4*)sh)[v] = cnt4[v];
    for (int v = n2v + tid; v < MAXN2 / 4; v += 1024)
        ((int4*)sh)[v] = make_int4(0, 0, 0, 0);
    __syncthreads();

    int base = tid * 16;
    int vals[16], cnts[16];
    int local = 0;
#pragma unroll
    for (int i4 = 0; i4 < 4; ++i4) {
        int4 q = *(const int4*)&sh[base + i4 * 4];
        int cc[4] = {q.x, q.y, q.z, q.w};
#pragma unroll
        for (int j = 0; j < 4; ++j) {
            vals[i4 * 4 + j] = local;
            cnts[i4 * 4 + j] = cc[j];
            local += cc[j];
        }
    }
    int inc = local;
#pragma unroll
    for (int off = 1; off < 32; off <<= 1) {
        int nb = __shfl_up_sync(0xffffffffu, inc, off);
        if (lane >= off) inc += nb;
    }
    if (lane == 31) wsum[wid] = inc;
    __syncthreads();
    if (wid == 0) {
        int s = wsum[lane];
#pragma unroll
        for (int off = 1; off < 32; off <<= 1) {
            int nb = __shfl_up_sync(0xffffffffu, s, off);
            if (lane >= off) s += nb;
        }
        wsum[lane] = s;
    }
    __syncthreads();
    int excl = ((wid > 0) ? wsum[wid - 1] : 0) + inc - local;
#pragma unroll
    for (int i4 = 0; i4 < 4; ++i4) {
        int4 q = make_int4(excl + vals[i4 * 4],     excl + vals[i4 * 4 + 1],
                           excl + vals[i4 * 4 + 2], excl + vals[i4 * 4 + 3]);
        *(int4*)&sh[base + i4 * 4] = q;
        int idx = base + i4 * 4;
        if (idx + 3 < n2) {
            int4 e = make_int4(q.x + cnts[i4 * 4],     q.y + cnts[i4 * 4 + 1],
                               q.z + cnts[i4 * 4 + 2], q.w + cnts[i4 * 4 + 3]);
            *(int4*)&g_hd[idx] = e;
        } else {
#pragma unroll
            for (int j = 0; j < 4; ++j)
                if (idx + j < n2)
                    g_hd[idx + j] = (&q.x)[j] + cnts[i4 * 4 + j];
        }
    }
    int total = wsum[31];
    __syncthreads();
    int4* off4 = (int4*)g_off;
    for (int v = tid; v < n2v; v += 1024)
        off4[v] = ((const int4*)sh)[v];
    if (tid == 0) g_off[n2] = total;
}

// ---- K3: scatter (countdown on end positions), 2 edges/thread ------------------
__global__ void k_scatter(const int* __restrict__ src, const int* __restrict__ tgt,
                          int E, int n2) {
    int base = (blockIdx.x * blockDim.x + threadIdx.x) * 2;
    if (base >= E) return;
    int t[2], s[2];
    float w[2];
    if (base + 2 <= E) {
        int2 t2 = *(const int2*)&tgt[base];
        int2 s2 = *(const int2*)&src[base];
        float2 w2 = *(const float2*)&g_wst[base];
        t[0] = t2.x; t[1] = t2.y;
        s[0] = s2.x; s[1] = s2.y;
        w[0] = w2.x; w[1] = w2.y;
    } else {
        t[0] = __ldg(&tgt[base]); t[1] = n2;
        s[0] = __ldg(&src[base]); s[1] = 0;
        w[0] = __ldg(&g_wst[base]); w[1] = 0.f;
    }
    int pos[2];
#pragma unroll
    for (int j = 0; j < 2; ++j)
        pos[j] = (t[j] < n2) ? (atomicAdd(&g_hd[t[j]], -1) - 1) : -1;
#pragma unroll
    for (int j = 0; j < 2; ++j)
        if (pos[j] >= 0)
            g_epk[pos[j]] = make_float2(__int_as_float(s[j]), w[j]);
}

// ---- K4: xW = x @ W^T via fp16 MMA (m16n8k16, fp32 accum), rows < n1 -----------
__global__ void __launch_bounds__(256) k_gemm_tc(
    const float* __restrict__ x, const float* __restrict__ W,
    const int* __restrict__ n1p, int N0) {
    extern __shared__ __half hsm[];
    __half* xs = hsm;                  // [128][HSTR]
    __half* ws = hsm + 128 * HSTR;     // [128][HSTR]

    int n1 = clamp_n1(n1p, N0);
    int row0 = blockIdx.x * 128;
    if (row0 >= n1) return;

    int tid = threadIdx.x, lane = tid & 31, warp = tid >> 5;
    int wm = warp >> 1, wn = warp & 1;
    int lq = lane >> 2, lr = lane & 3;

#pragma unroll
    for (int it = 0; it < 16; ++it) {
        int f4 = it * 256 + tid;
        int r = f4 >> 5, k4 = f4 & 31;
        int row = row0 + r;
        float4 v = make_float4(0.f, 0.f, 0.f, 0.f);
        if (row < N0) v = *(const float4*)&x[(size_t)row * H + k4 * 4];
        *(uint2*)&xs[r * HSTR + k4 * 4] = f4_to_h4(v);
        float4 wv = *(const float4*)&W[(size_t)r * H + k4 * 4];
        *(uint2*)&ws[r * HSTR + k4 * 4] = f4_to_h4(wv);
    }
    __syncthreads();

    float acc[2][8][4];
#pragma unroll
    for (int mi = 0; mi < 2; ++mi)
#pragma unroll
        for (int ni = 0; ni < 8; ++ni)
#pragma unroll
            for (int j = 0; j < 4; ++j) acc[mi][ni][j] = 0.f;

#pragma unroll
    for (int ks = 0; ks < 8; ++ks) {
        int kb = ks * 16;
        uint32_t a[2][4];
#pragma unroll
        for (int mi = 0; mi < 2; ++mi) {
            int r0 = wm * 32 + mi * 16 + lq;
            a[mi][0] = *(const uint32_t*)&xs[r0 * HSTR + kb + lr * 2];
            a[mi][1] = *(const uint32_t*)&xs[(r0 + 8) * HSTR + kb + lr * 2];
            a[mi][2] = *(const uint32_t*)&xs[r0 * HSTR + kb + 8 + lr * 2];
            a[mi][3] = *(const uint32_t*)&xs[(r0 + 8) * HSTR + kb + 8 + lr * 2];
        }
#pragma unroll
        for (int ni = 0; ni < 8; ++ni) {
            int n = wn * 64 + ni * 8 + lq;
            uint32_t b0 = *(const uint32_t*)&ws[n * HSTR + kb + lr * 2];
            uint32_t b1 = *(const uint32_t*)&ws[n * HSTR + kb + 8 + lr * 2];
#pragma unroll
            for (int mi = 0; mi < 2; ++mi)
                MMA_F16(acc[mi][ni], a[mi][0], a[mi][1], a[mi][2], a[mi][3], b0, b1);
        }
    }

#pragma unroll
    for (int mi = 0; mi < 2; ++mi) {
        int r0 = row0 + wm * 32 + mi * 16 + lq;
#pragma unroll
        for (int ni = 0; ni < 8; ++ni) {
            int col = wn * 64 + ni * 8 + lr * 2;
            if (r0 < n1) {
                __half2 h = __floats2half2_rn(acc[mi][ni][0], acc[mi][ni][1]);
                *(__half2*)&g_xWh[(size_t)r0 * H + col] = h;
            }
            if (r0 + 8 < n1) {
                __half2 h = __floats2half2_rn(acc[mi][ni][2], acc[mi][ni][3]);
                *(__half2*)&g_xWh[(size_t)(r0 + 8) * H + col] = h;
            }
        }
    }
}

// ---- K5: GCN gather + SAGE partial p1 (t<n2), warp per target ------------------
__global__ void __launch_bounds__(256) k_gather_gcn(const float* __restrict__ b, int n2) {
    int t = blockIdx.x * 8 + (threadIdx.x >> 5);
    if (t >= n2) return;
    int lane = threadIdx.x & 31;
    int c = lane * 4;
    int base = __ldg(&g_off[t]);
    int end  = __ldg(&g_off[t + 1]);

    float4 ag0 = make_float4(0.f, 0.f, 0.f, 0.f), ag1 = ag0;
    float4 ap0 = ag0, ap1 = ag0;

    for (int i0 = base; i0 < end; i0 += 32) {
        int idx = i0 + lane;
        int s = 0; float nm = 0.f, u = 0.f;
        if (idx < end) {
            float2 p = __ldg(&g_epk[idx]);
            s = __float_as_int(p.x);
            float w = p.y;
            float ds = 1.f, d2 = 1.f;
            if (s < n2) {
                float dg = __int_as_float(__ldg(&g_hd[MAXN2 + s]));
                d2 = 1.f / (1.f + dg);
                ds = rsqrtf(1.f + dg);
            }
            nm = ds * w;
            u = d2;
        }
        int cnt = min(32, end - i0);
        int j = 0;
        for (; j + 4 <= cnt; j += 4) {
            int   s0 = __shfl_sync(0xffffffffu, s, j);
            float w0 = __shfl_sync(0xffffffffu, nm, j);
            float u0 = __shfl_sync(0xffffffffu, u, j);
            int   s1 = __shfl_sync(0xffffffffu, s, j + 1);
            float w1 = __shfl_sync(0xffffffffu, nm, j + 1);
            float u1 = __shfl_sync(0xffffffffu, u, j + 1);
            int   s2 = __shfl_sync(0xffffffffu, s, j + 2);
            float w2 = __shfl_sync(0xffffffffu, nm, j + 2);
            float u2 = __shfl_sync(0xffffffffu, u, j + 2);
            int   s3 = __shfl_sync(0xffffffffu, s, j + 3);
            float w3 = __shfl_sync(0xffffffffu, nm, j + 3);
            float u3 = __shfl_sync(0xffffffffu, u, j + 3);
            float4 v0 = h4_to_f4(*(const uint2*)&g_xWh[(size_t)s0 * H + c]);
            float4 v1 = h4_to_f4(*(const uint2*)&g_xWh[(size_t)s1 * H + c]);
            float4 v2 = h4_to_f4(*(const uint2*)&g_xWh[(size_t)s2 * H + c]);
            float4 v3 = h4_to_f4(*(const uint2*)&g_xWh[(size_t)s3 * H + c]);
            ag0.x += w0 * v0.x; ag0.y += w0 * v0.y; ag0.z += w0 * v0.z; ag0.w += w0 * v0.w;
            ap0.x += u0 * v0.x; ap0.y += u0 * v0.y; ap0.z += u0 * v0.z; ap0.w += u0 * v0.w;
            ag1.x += w1 * v1.x; ag1.y += w1 * v1.y; ag1.z += w1 * v1.z; ag1.w += w1 * v1.w;
            ap1.x += u1 * v1.x; ap1.y += u1 * v1.y; ap1.z += u1 * v1.z; ap1.w += u1 * v1.w;
            ag0.x += w2 * v2.x; ag0.y += w2 * v2.y; ag0.z += w2 * v2.z; ag0.w += w2 * v2.w;
            ap0.x += u2 * v2.x; ap0.y += u2 * v2.y; ap0.z += u2 * v2.z; ap0.w += u2 * v2.w;
            ag1.x += w3 * v3.x; ag1.y += w3 * v3.y; ag1.z += w3 * v3.z; ag1.w += w3 * v3.w;
            ap1.x += u3 * v3.x; ap1.y += u3 * v3.y; ap1.z += u3 * v3.z; ap1.w += u3 * v3.w;
        }
        for (; j < cnt; ++j) {
            int   s0 = __shfl_sync(0xffffffffu, s, j);
            float w0 = __shfl_sync(0xffffffffu, nm, j);
            float u0 = __shfl_sync(0xffffffffu, u, j);
            float4 v0 = h4_to_f4(*(const uint2*)&g_xWh[(size_t)s0 * H + c]);
            ag0.x += w0 * v0.x; ag0.y += w0 * v0.y; ag0.z += w0 * v0.z; ag0.w += w0 * v0.w;
            ap0.x += u0 * v0.x; ap0.y += u0 * v0.y; ap0.z += u0 * v0.z; ap0.w += u0 * v0.w;
        }
    }

    float degt = __int_as_float(g_hd[MAXN2 + t]);
    float dt  = rsqrtf(1.f + degt);
    float d2t = 1.f / (1.f + degt);
    float4 agg;
    agg.x = (ag0.x + ag1.x) * dt;
    agg.y = (ag0.y + ag1.y) * dt;
    agg.z = (ag0.z + ag1.z) * dt;
    agg.w = (ag0.w + ag1.w) * dt;
    float4 p1 = make_float4(ap0.x + ap1.x, ap0.y + ap1.y, ap0.z + ap1.z, ap0.w + ap1.w);
    float4 xw = h4_to_f4(*(const uint2*)&g_xWh[(size_t)t * H + c]);
    float4 bb = *(const float4*)&b[c];
    float4 g1;
    g1.x = agg.x + xw.x * d2t + bb.x;
    g1.y = agg.y + xw.y * d2t + bb.y;
    g1.z = agg.z + xw.z * d2t + bb.z;
    g1.w = agg.w + xw.w * d2t + bb.w;
    *(uint2*)&g_g1h[(size_t)t * H + c] = f4_to_h4(g1);    // fp16 for sage_out
    *(uint2*)&g_aggh[(size_t)t * H + c] = f4_to_h4(agg);
    *(float4*)&g_p1f[(size_t)t * H + c] = p1;
}

// ---- K6: SAGE p2 gather + mean(fp16); restores g_hd[t] to zero -----------------
__global__ void __launch_bounds__(256) k_sage2(const float* __restrict__ b, int n2) {
    int t = blockIdx.x * 8 + (threadIdx.x >> 5);
    if (t >= n2) return;
    int lane = threadIdx.x & 31;
    int c = lane * 4;
    int base = __ldg(&g_off[t]);
    int end  = __ldg(&g_off[t + 1]);
    int cnt = end - base;

    if (lane == 0) { g_hd[t] = 0; g_hd[MAXN2 + t] = 0; }

    float4 a0 = make_float4(0.f, 0.f, 0.f, 0.f), a1 = a0;

    for (int i0 = base; i0 < end; i0 += 32) {
        int idx = i0 + lane;
        int s = n2;
        if (idx < end) s = __float_as_int(__ldg(&g_epk[idx]).x);
        int cl = min(32, end - i0);
        int j = 0;
        for (; j + 4 <= cl; j += 4) {
            int s0 = __shfl_sync(0xffffffffu, s, j);
            int s1 = __shfl_sync(0xffffffffu, s, j + 1);
            int s2 = __shfl_sync(0xffffffffu, s, j + 2);
            int s3 = __shfl_sync(0xffffffffu, s, j + 3);
            if (s0 < n2) {
                float4 v = h4_to_f4(*(const uint2*)&g_aggh[(size_t)s0 * H + c]);
                a0.x += v.x; a0.y += v.y; a0.z += v.z; a0.w += v.w;
            }
            if (s1 < n2) {
                float4 v = h4_to_f4(*(const uint2*)&g_aggh[(size_t)s1 * H + c]);
                a1.x += v.x; a1.y += v.y; a1.z += v.z; a1.w += v.w;
            }
            if (s2 < n2) {
                float4 v = h4_to_f4(*(const uint2*)&g_aggh[(size_t)s2 * H + c]);
                a0.x += v.x; a0.y += v.y; a0.z += v.z; a0.w += v.w;
            }
            if (s3 < n2) {
                float4 v = h4_to_f4(*(const uint2*)&g_aggh[(size_t)s3 * H + c]);
                a1.x += v.x; a1.y += v.y; a1.z += v.z; a1.w += v.w;
            }
        }
        for (; j < cl; ++j) {
            int s0 = __shfl_sync(0xffffffffu, s, j);
            if (s0 < n2) {
                float4 v = h4_to_f4(*(const uint2*)&g_aggh[(size_t)s0 * H + c]);
                a0.x += v.x; a0.y += v.y; a0.z += v.z; a0.w += v.w;
            }
        }
    }

    float4 o = make_float4(0.f, 0.f, 0.f, 0.f);
    if (cnt > 0) {
        float sc = 1.f / (float)cnt;
        float4 p1 = *(const float4*)&g_p1f[(size_t)t * H + c];
        float4 bb = *(const float4*)&b[c];
        o.x = (p1.x + a0.x + a1.x) * sc + bb.x;
        o.y = (p1.y + a0.y + a1.y) * sc + bb.y;
        o.z = (p1.z + a0.z + a1.z) * sc + bb.z;
        o.w = (p1.w + a0.w + a1.w) * sc + bb.w;
    }
    *(uint2*)&g_meanh[(size_t)t * H + c] = f4_to_h4(o);
}

// ---- K7: out = l2norm( [mean|g1] @ [Wl|Wr]^T + bl ), K=256 fp16 MMA ------------
__global__ void __launch_bounds__(256) k_sage_out(
    const float* __restrict__ Wl, const float* __restrict__ bl,
    const float* __restrict__ Wr, int n2, float* __restrict__ out) {
    extern __shared__ __half hsm[];
    __half* As = hsm;                   // [64][HS2]   rows: [mean(128) | g1(128)]
    __half* Bs = hsm + 64 * HS2;        // [128][HS2]  rows: [Wl(128)   | Wr(128)]
    float* psum = (float*)(hsm + 192 * HS2);   // [64][8]
    float* scl  = psum + GROWS * 8;            // [64]

    int row0 = blockIdx.x * GROWS;
    int tid = threadIdx.x, lane = tid & 31, warp = tid >> 5;
    int wm = warp >> 1, wn = warp & 1;  // 4 M-slabs(16) x 2 N-slabs(64)
    int lq = lane >> 2, lr = lane & 3;

    // load A: 64 rows x 256 halves (uint2 chunks of 4 halves; 4096 chunks)
#pragma unroll
    for (int it = 0; it < 16; ++it) {
        int ch = it * 256 + tid;
        int r = ch >> 6, q = ch & 63;
        int row = row0 + r;
        uint2 v = make_uint2(0u, 0u);
        if (row < n2) {
            if (q < 32) v = *(const uint2*)&g_meanh[(size_t)row * H + q * 4];
            else        v = *(const uint2*)&g_g1h[(size_t)row * H + (q - 32) * 4];
        }
        int k = (q < 32) ? q * 4 : 128 + (q - 32) * 4;
        *(uint2*)&As[r * HS2 + k] = v;
    }
    // load B: 128 rows x 256 halves from fp32 Wl/Wr (8192 float4 chunks)
#pragma unroll
    for (int it = 0; it < 32; ++it) {
        int ch = it * 256 + tid;
        int j = ch >> 6, q = ch & 63;
        float4 v;
        int k;
        if (q < 32) { v = *(const float4*)&Wl[(size_t)j * H + q * 4]; k = q * 4; }
        else        { v = *(const float4*)&Wr[(size_t)j * H + (q - 32) * 4]; k = 128 + (q - 32) * 4; }
        *(uint2*)&Bs[j * HS2 + k] = f4_to_h4(v);
    }
    __syncthreads();

    float acc[8][4];
#pragma unroll
    for (int ni = 0; ni < 8; ++ni)
#pragma unroll
        for (int j = 0; j < 4; ++j) acc[ni][j] = 0.f;

#pragma unroll
    for (int ks = 0; ks < 16; ++ks) {
        int kb = ks * 16;
        int r0 = wm * 16 + lq;
        uint32_t a0 = *(const uint32_t*)&As[r0 * HS2 + kb + lr * 2];
        uint32_t a1 = *(const uint32_t*)&As[(r0 + 8) * HS2 + kb + lr * 2];
        uint32_t a2 = *(const uint32_t*)&As[r0 * HS2 + kb + 8 + lr * 2];
        uint32_t a3 = *(const uint32_t*)&As[(r0 + 8) * HS2 + kb + 8 + lr * 2];
#pragma unroll
        for (int ni = 0; ni < 8; ++ni) {
            int n = wn * 64 + ni * 8 + lq;
            uint32_t b0 = *(const uint32_t*)&Bs[n * HS2 + kb + lr * 2];
            uint32_t b1 = *(const uint32_t*)&Bs[n * HS2 + kb + 8 + lr * 2];
            MMA_F16(acc[ni], a0, a1, a2, a3, b0, b1);
        }
    }

    // bias + row-norm partials
    float p0 = 0.f, p8 = 0.f;
#pragma unroll
    for (int ni = 0; ni < 8; ++ni) {
        int col = wn * 64 + ni * 8 + lr * 2;
        float2 bb = *(const float2*)&bl[col];
        acc[ni][0] += bb.x; acc[ni][1] += bb.y;
        acc[ni][2] += bb.x; acc[ni][3] += bb.y;
        p0 += acc[ni][0] * acc[ni][0] + acc[ni][1] * acc[ni][1];
        p8 += acc[ni][2] * acc[ni][2] + acc[ni][3] * acc[ni][3];
    }
    int rl = wm * 16 + lq;
    psum[rl * 8 + wn * 4 + lr] = p0;
    psum[(rl + 8) * 8 + wn * 4 + lr] = p8;
    __syncthreads();
    if (tid < GROWS) {
        float ssum = 0.f;
#pragma unroll
        for (int c8 = 0; c8 < 8; ++c8) ssum += psum[tid * 8 + c8];
        scl[tid] = 1.f / fmaxf(sqrtf(ssum), 1e-12f);
    }
    __syncthreads();

    float s0 = scl[rl], s8 = scl[rl + 8];
    int row_a = row0 + rl, row_b = row0 + rl + 8;
#pragma unroll
    for (int ni = 0; ni < 8; ++ni) {
        int col = wn * 64 + ni * 8 + lr * 2;
        if (row_a < n2)
            *(float2*)&out[(size_t)row_a * H + col] =
                make_float2(acc[ni][0] * s0, acc[ni][1] * s0);
        if (row_b < n2)
            *(float2*)&out[(size_t)row_b * H + col] =
                make_float2(acc[ni][2] * s8, acc[ni][3] * s8);
    }
}

// ---------------------------------------------------------------------------
extern "C" void kernel_launch(void* const* d_in, const int* in_sizes, int n_in,
                              void* d_out, int out_size) {
    const float* x     = (const float*)d_in[0];
    const float* attr  = (const float*)d_in[1];
    const int*   e_id1 = (const int*)d_in[3];
    const int*   src1  = (const int*)d_in[6];
    const int*   tgt1  = (const int*)d_in[7];
    const int*   n1p   = (const int*)d_in[8];
    const float* gcn_W = (const float*)d_in[10];
    const float* gcn_b = (const float*)d_in[11];
    const float* Wl1   = (const float*)d_in[15];
    const float* bl1   = (const float*)d_in[16];
    const float* Wr1   = (const float*)d_in[17];
    float* out = (float*)d_out;

    int N0 = in_sizes[0] / H;  if (N0 > MAXN0) N0 = MAXN0;
    int E1 = in_sizes[3];      if (E1 > MAXE)  E1 = MAXE;
    int n2 = out_size / H;     if (n2 > MAXN2) n2 = MAXN2;

    constexpr int SMEM_GEMM = 2 * 128 * HSTR * 2;
    constexpr int SMEM_SCAN = MAXN2 * 4;
    constexpr int SMEM_SOUT = 192 * HS2 * 2 + GROWS * 8 * 4 + GROWS * 4;
    cudaFuncSetAttribute(k_gemm_tc, cudaFuncAttributeMaxDynamicSharedMemorySize, SMEM_GEMM);
    cudaFuncSetAttribute(k_scan, cudaFuncAttributeMaxDynamicSharedMemorySize, SMEM_SCAN);
    cudaFuncSetAttribute(k_sage_out, cudaFuncAttributeMaxDynamicSharedMemorySize, SMEM_SOUT);

    cudaStream_t s2;
    cudaStreamCreateWithFlags(&s2, cudaStreamNonBlocking);
    cudaEvent_t evFork, evGemm;
    cudaEventCreateWithFlags(&evFork, cudaEventDisableTiming);
    cudaEventCreateWithFlags(&evGemm, cudaEventDisableTiming);

    // Fork: GEMM on side stream.
    cudaEventRecord(evFork, 0);
    cudaStreamWaitEvent(s2, evFork, 0);
    k_gemm_tc<<<(N0 + 127) / 128, 256, SMEM_GEMM, s2>>>(x, gcn_W, n1p, N0);
    cudaEventRecord(evGemm, s2);

    // Main stream: edge preprocessing (g_hd arrives zero: BSS / self-restored).
    k_hist<<<(E1 + 511) / 512, 256>>>(attr, e_id1, tgt1, E1, n2);
    k_scan<<<1, 1024, SMEM_SCAN>>>(n2);
    k_scatter<<<(E1 + 511) / 512, 256>>>(src1, tgt1, E1, n2);

    cudaStreamWaitEvent(0, evGemm, 0);  // join

    k_gather_gcn<<<(n2 + 7) / 8, 256>>>(gcn_b, n2);
    k_sage2<<<(n2 + 7) / 8, 256>>>(gcn_b, n2);
    k_sage_out<<<(n2 + GROWS - 1) / GROWS, 256, SMEM_SOUT>>>(Wl1, bl1, Wr1, n2, out);
}

// round 14
// speedup vs baseline: 2.2400x; 1.0211x over previous
#include <cuda_runtime.h>
#include <cuda_fp16.h>
#include <cstdint>

// ---------------------------------------------------------------------------
// GlobalGNN layer-1-only pipeline:
//   s2  : xW = x@gcn_W^T (fp16 MMA m16n8k16, fp32 accum, fp16 out)
//   main: hist(x2) -> scan(g_off excl + g_hd inclusive-end) -> scatter(x2)
//   join: gather_gcn (agg,p1,g1[fp16]; packed half2 edge scalars, unroll8)
//         -> sage2 (mean[fp16], unroll8; restores g_hd)
//         -> sage_out (K=256 fp16 MMA GEMM: [mean|g1]@[Wl|Wr]^T + l2norm)
// ---------------------------------------------------------------------------

#define H 128
#define MAXN0 131072
#define MAXN2 16384
#define MAXE  1048576
#define GROWS 64
#define HSTR 136
#define HS2  264

__device__ __align__(16) __half g_xWh  [(size_t)MAXN0 * H];
__device__ __align__(16) __half g_aggh [(size_t)MAXN2 * H];
__device__ __align__(16) __half g_g1h  [(size_t)MAXN2 * H];
__device__ __align__(16) __half g_meanh[(size_t)MAXN2 * H];
__device__ __align__(16) __half g_p1h  [(size_t)MAXN2 * H];
__device__ __align__(16) int    g_hd   [2 * MAXN2];
__device__ __align__(16) int    g_off  [MAXN2 + 4];
__device__ __align__(16) float2 g_epk  [MAXE];
__device__ __align__(16) float  g_wst  [MAXE];

__device__ __forceinline__ int clamp_n1(const int* p, int N0) {
    int v = *p;
    if (v <= 0 || v > N0) v = N0;
    return v;
}

__device__ __forceinline__ float4 h4_to_f4(uint2 raw) {
    __half2 h0 = *reinterpret_cast<__half2*>(&raw.x);
    __half2 h1 = *reinterpret_cast<__half2*>(&raw.y);
    float2 f0 = __half22float2(h0);
    float2 f1 = __half22float2(h1);
    return make_float4(f0.x, f0.y, f1.x, f1.y);
}

__device__ __forceinline__ uint2 f4_to_h4(float4 v) {
    __half2 h0 = __floats2half2_rn(v.x, v.y);
    __half2 h1 = __floats2half2_rn(v.z, v.w);
    uint2 r;
    r.x = *reinterpret_cast<uint32_t*>(&h0);
    r.y = *reinterpret_cast<uint32_t*>(&h1);
    return r;
}

#define MMA_F16(d, a0, a1, a2, a3, b0, b1)                                    \
    asm volatile(                                                             \
        "mma.sync.aligned.m16n8k16.row.col.f32.f16.f16.f32 "                  \
        "{%0,%1,%2,%3},{%4,%5,%6,%7},{%8,%9},{%0,%1,%2,%3};"                  \
        : "+f"(d[0]), "+f"(d[1]), "+f"(d[2]), "+f"(d[3])                      \
        : "r"(a0), "r"(a1), "r"(a2), "r"(a3), "r"(b0), "r"(b1))

// ---- K1: histogram + weighted degree + weight staging, 2 edges/thread ---------
__global__ void k_hist(const float* __restrict__ attr, const int* __restrict__ eid,
                       const int* __restrict__ tgt, int E, int n2) {
    int base = (blockIdx.x * blockDim.x + threadIdx.x) * 2;
    if (base >= E) return;
    if (base + 2 <= E) {
        int2 t2  = *(const int2*)&tgt[base];
        int2 id2 = *(const int2*)&eid[base];
        float w0 = __ldg(&attr[id2.x]);
        float w1 = __ldg(&attr[id2.y]);
        *(float2*)&g_wst[base] = make_float2(w0, w1);
        if (t2.x < n2) { atomicAdd(&g_hd[t2.x], 1); atomicAdd((float*)&g_hd[MAXN2 + t2.x], w0); }
        if (t2.y < n2) { atomicAdd(&g_hd[t2.y], 1); atomicAdd((float*)&g_hd[MAXN2 + t2.y], w1); }
    } else {
        int t = __ldg(&tgt[base]);
        float w = __ldg(&attr[__ldg(&eid[base])]);
        g_wst[base] = w;
        if (t < n2) {
            atomicAdd(&g_hd[t], 1);
            atomicAdd((float*)&g_hd[MAXN2 + t], w);
        }
    }
}

// ---- K2: scan: g_off[i]=exclusive, g_hd[i]=inclusive end (i<n2) ----------------
__global__ void __launch_bounds__(1024) k_scan(int n2) {
    extern __shared__ int sh[];
    __shared__ int wsum[32];
    int tid = threadIdx.x, lane = tid & 31, wid = tid >> 5;

    int n2v = (n2 + 3) >> 2;
    const int4* cnt4 = (const int4*)g_hd;
    for (int v = tid; v < n2v; v += 1024)
        ((int4*)sh)[v] = cnt4[v];
    for (int v = n2v + tid; v < MAXN2 / 4; v += 1024)
        ((int4*)sh)[v] = make_int4(0, 0, 0, 0);
    __syncthreads();

    int base = tid * 16;
    int vals[16], cnts[16];
    int local = 0;
#pragma unroll
    for (int i4 = 0; i4 < 4; ++i4) {
        int4 q = *(const int4*)&sh[base + i4 * 4];
        int cc[4] = {q.x, q.y, q.z, q.w};
#pragma unroll
        for (int j = 0; j < 4; ++j) {
            vals[i4 * 4 + j] = local;
            cnts[i4 * 4 + j] = cc[j];
            local += cc[j];
        }
    }
    int inc = local;
#pragma unroll
    for (int off = 1; off < 32; off <<= 1) {
        int nb = __shfl_up_sync(0xffffffffu, inc, off);
        if (lane >= off) inc += nb;
    }
    if (lane == 31) wsum[wid] = inc;
    __syncthreads();
    if (wid == 0) {
        int s = wsum[lane];
#pragma unroll
        for (int off = 1; off < 32; off <<= 1) {
            int nb = __shfl_up_sync(0xffffffffu, s, off);
            if (lane >= off) s += nb;
        }
        wsum[lane] = s;
    }
    __syncthreads();
    int excl = ((wid > 0) ? wsum[wid - 1] : 0) + inc - local;
#pragma unroll
    for (int i4 = 0; i4 < 4; ++i4) {
        int4 q = make_int4(excl + vals[i4 * 4],     excl + vals[i4 * 4 + 1],
                           excl + vals[i4 * 4 + 2], excl + vals[i4 * 4 + 3]);
        *(int4*)&sh[base + i4 * 4] = q;
        int idx = base + i4 * 4;
        if (idx + 3 < n2) {
            int4 e = make_int4(q.x + cnts[i4 * 4],     q.y + cnts[i4 * 4 + 1],
                               q.z + cnts[i4 * 4 + 2], q.w + cnts[i4 * 4 + 3]);
            *(int4*)&g_hd[idx] = e;
        } else {
#pragma unroll
            for (int j = 0; j < 4; ++j)
                if (idx + j < n2)
                    g_hd[idx + j] = (&q.x)[j] + cnts[i4 * 4 + j];
        }
    }
    int total = wsum[31];
    __syncthreads();
    int4* off4 = (int4*)g_off;
    for (int v = tid; v < n2v; v += 1024)
        off4[v] = ((const int4*)sh)[v];
    if (tid == 0) g_off[n2] = total;
}

// ---- K3: scatter (countdown on end positions), 2 edges/thread ------------------
__global__ void k_scatter(const int* __restrict__ src, const int* __restrict__ tgt,
                          int E, int n2) {
    int base = (blockIdx.x * blockDim.x + threadIdx.x) * 2;
    if (base >= E) return;
    int t[2], s[2];
    float w[2];
    if (base + 2 <= E) {
        int2 t2 = *(const int2*)&tgt[base];
        int2 s2 = *(const int2*)&src[base];
        float2 w2 = *(const float2*)&g_wst[base];
        t[0] = t2.x; t[1] = t2.y;
        s[0] = s2.x; s[1] = s2.y;
        w[0] = w2.x; w[1] = w2.y;
    } else {
        t[0] = __ldg(&tgt[base]); t[1] = n2;
        s[0] = __ldg(&src[base]); s[1] = 0;
        w[0] = __ldg(&g_wst[base]); w[1] = 0.f;
    }
    int pos[2];
#pragma unroll
    for (int j = 0; j < 2; ++j)
        pos[j] = (t[j] < n2) ? (atomicAdd(&g_hd[t[j]], -1) - 1) : -1;
#pragma unroll
    for (int j = 0; j < 2; ++j)
        if (pos[j] >= 0)
            g_epk[pos[j]] = make_float2(__int_as_float(s[j]), w[j]);
}

// ---- K4: xW = x @ W^T via fp16 MMA (m16n8k16, fp32 accum), rows < n1 -----------
__global__ void __launch_bounds__(256) k_gemm_tc(
    const float* __restrict__ x, const float* __restrict__ W,
    const int* __restrict__ n1p, int N0) {
    extern __shared__ __half hsm[];
    __half* xs = hsm;
    __half* ws = hsm + 128 * HSTR;

    int n1 = clamp_n1(n1p, N0);
    int row0 = blockIdx.x * 128;
    if (row0 >= n1) return;

    int tid = threadIdx.x, lane = tid & 31, warp = tid >> 5;
    int wm = warp >> 1, wn = warp & 1;
    int lq = lane >> 2, lr = lane & 3;

#pragma unroll
    for (int it = 0; it < 16; ++it) {
        int f4 = it * 256 + tid;
        int r = f4 >> 5, k4 = f4 & 31;
        int row = row0 + r;
        float4 v = make_float4(0.f, 0.f, 0.f, 0.f);
        if (row < N0) v = *(const float4*)&x[(size_t)row * H + k4 * 4];
        *(uint2*)&xs[r * HSTR + k4 * 4] = f4_to_h4(v);
        float4 wv = *(const float4*)&W[(size_t)r * H + k4 * 4];
        *(uint2*)&ws[r * HSTR + k4 * 4] = f4_to_h4(wv);
    }
    __syncthreads();

    float acc[2][8][4];
#pragma unroll
    for (int mi = 0; mi < 2; ++mi)
#pragma unroll
        for (int ni = 0; ni < 8; ++ni)
#pragma unroll
            for (int j = 0; j < 4; ++j) acc[mi][ni][j] = 0.f;

#pragma unroll
    for (int ks = 0; ks < 8; ++ks) {
        int kb = ks * 16;
        uint32_t a[2][4];
#pragma unroll
        for (int mi = 0; mi < 2; ++mi) {
            int r0 = wm * 32 + mi * 16 + lq;
            a[mi][0] = *(const uint32_t*)&xs[r0 * HSTR + kb + lr * 2];
            a[mi][1] = *(const uint32_t*)&xs[(r0 + 8) * HSTR + kb + lr * 2];
            a[mi][2] = *(const uint32_t*)&xs[r0 * HSTR + kb + 8 + lr * 2];
            a[mi][3] = *(const uint32_t*)&xs[(r0 + 8) * HSTR + kb + 8 + lr * 2];
        }
#pragma unroll
        for (int ni = 0; ni < 8; ++ni) {
            int n = wn * 64 + ni * 8 + lq;
            uint32_t b0 = *(const uint32_t*)&ws[n * HSTR + kb + lr * 2];
            uint32_t b1 = *(const uint32_t*)&ws[n * HSTR + kb + 8 + lr * 2];
#pragma unroll
            for (int mi = 0; mi < 2; ++mi)
                MMA_F16(acc[mi][ni], a[mi][0], a[mi][1], a[mi][2], a[mi][3], b0, b1);
        }
    }

#pragma unroll
    for (int mi = 0; mi < 2; ++mi) {
        int r0 = row0 + wm * 32 + mi * 16 + lq;
#pragma unroll
        for (int ni = 0; ni < 8; ++ni) {
            int col = wn * 64 + ni * 8 + lr * 2;
            if (r0 < n1) {
                __half2 h = __floats2half2_rn(acc[mi][ni][0], acc[mi][ni][1]);
                *(__half2*)&g_xWh[(size_t)r0 * H + col] = h;
            }
            if (r0 + 8 < n1) {
                __half2 h = __floats2half2_rn(acc[mi][ni][2], acc[mi][ni][3]);
                *(__half2*)&g_xWh[(size_t)(r0 + 8) * H + col] = h;
            }
        }
    }
}

// ---- K5: GCN gather + SAGE partial p1 (t<n2), warp/target, unroll 8 ------------
__global__ void __launch_bounds__(256) k_gather_gcn(const float* __restrict__ b, int n2) {
    int t = blockIdx.x * 8 + (threadIdx.x >> 5);
    if (t >= n2) return;
    int lane = threadIdx.x & 31;
    int c = lane * 4;
    int base = __ldg(&g_off[t]);
    int end  = __ldg(&g_off[t + 1]);

    float4 ag0 = make_float4(0.f, 0.f, 0.f, 0.f), ag1 = ag0;
    float4 ap0 = ag0, ap1 = ag0;

    for (int i0 = base; i0 < end; i0 += 32) {
        int idx = i0 + lane;
        int s = 0;
        uint32_t pk = 0;   // half2(nm, u)
        if (idx < end) {
            float2 p = __ldg(&g_epk[idx]);
            s = __float_as_int(p.x);
            float w = p.y;
            float ds = 1.f, d2 = 1.f;
            if (s < n2) {
                float dg = __int_as_float(__ldg(&g_hd[MAXN2 + s]));
                d2 = 1.f / (1.f + dg);
                ds = rsqrtf(1.f + dg);
            }
            __half2 ph = __floats2half2_rn(ds * w, d2);
            pk = *reinterpret_cast<uint32_t*>(&ph);
        }
        int cnt = min(32, end - i0);
        int j = 0;
        for (; j + 8 <= cnt; j += 8) {
            int ss[8]; uint32_t pp[8];
#pragma unroll
            for (int q = 0; q < 8; ++q) {
                ss[q] = __shfl_sync(0xffffffffu, s, j + q);
                pp[q] = __shfl_sync(0xffffffffu, pk, j + q);
            }
            uint2 raw[8];
#pragma unroll
            for (int q = 0; q < 8; ++q)
                raw[q] = *(const uint2*)&g_xWh[(size_t)ss[q] * H + c];
#pragma unroll
            for (int q = 0; q < 8; ++q) {
                float2 wu = __half22float2(*reinterpret_cast<__half2*>(&pp[q]));
                float4 v = h4_to_f4(raw[q]);
                float4& ag = (q & 1) ? ag1 : ag0;
                float4& ap = (q & 1) ? ap1 : ap0;
                ag.x += wu.x * v.x; ag.y += wu.x * v.y; ag.z += wu.x * v.z; ag.w += wu.x * v.w;
                ap.x += wu.y * v.x; ap.y += wu.y * v.y; ap.z += wu.y * v.z; ap.w += wu.y * v.w;
            }
        }
        for (; j < cnt; ++j) {
            int s0 = __shfl_sync(0xffffffffu, s, j);
            uint32_t p0 = __shfl_sync(0xffffffffu, pk, j);
            float2 wu = __half22float2(*reinterpret_cast<__half2*>(&p0));
            float4 v = h4_to_f4(*(const uint2*)&g_xWh[(size_t)s0 * H + c]);
            ag0.x += wu.x * v.x; ag0.y += wu.x * v.y; ag0.z += wu.x * v.z; ag0.w += wu.x * v.w;
            ap0.x += wu.y * v.x; ap0.y += wu.y * v.y; ap0.z += wu.y * v.z; ap0.w += wu.y * v.w;
        }
    }

    float degt = __int_as_float(g_hd[MAXN2 + t]);
    float dt  = rsqrtf(1.f + degt);
    float d2t = 1.f / (1.f + degt);
    float4 agg;
    agg.x = (ag0.x + ag1.x) * dt;
    agg.y = (ag0.y + ag1.y) * dt;
    agg.z = (ag0.z + ag1.z) * dt;
    agg.w = (ag0.w + ag1.w) * dt;
    float4 p1 = make_float4(ap0.x + ap1.x, ap0.y + ap1.y, ap0.z + ap1.z, ap0.w + ap1.w);
    float4 xw = h4_to_f4(*(const uint2*)&g_xWh[(size_t)t * H + c]);
    float4 bb = *(const float4*)&b[c];
    float4 g1;
    g1.x = agg.x + xw.x * d2t + bb.x;
    g1.y = agg.y + xw.y * d2t + bb.y;
    g1.z = agg.z + xw.z * d2t + bb.z;
    g1.w = agg.w + xw.w * d2t + bb.w;
    *(uint2*)&g_g1h[(size_t)t * H + c] = f4_to_h4(g1);
    *(uint2*)&g_aggh[(size_t)t * H + c] = f4_to_h4(agg);
    *(uint2*)&g_p1h[(size_t)t * H + c] = f4_to_h4(p1);
}

// ---- K6: SAGE p2 gather + mean(fp16), unroll 8; restores g_hd[t] ---------------
__global__ void __launch_bounds__(256) k_sage2(const float* __restrict__ b, int n2) {
    int t = blockIdx.x * 8 + (threadIdx.x >> 5);
    if (t >= n2) return;
    int lane = threadIdx.x & 31;
    int c = lane * 4;
    int base = __ldg(&g_off[t]);
    int end  = __ldg(&g_off[t + 1]);
    int cnt = end - base;

    if (lane == 0) { g_hd[t] = 0; g_hd[MAXN2 + t] = 0; }

    float4 a0 = make_float4(0.f, 0.f, 0.f, 0.f), a1 = a0;

    for (int i0 = base; i0 < end; i0 += 32) {
        int idx = i0 + lane;
        int s = n2;
        if (idx < end) s = __float_as_int(__ldg(&g_epk[idx]).x);
        int cl = min(32, end - i0);
        int j = 0;
        for (; j + 8 <= cl; j += 8) {
            int ss[8];
#pragma unroll
            for (int q = 0; q < 8; ++q)
                ss[q] = __shfl_sync(0xffffffffu, s, j + q);
#pragma unroll
            for (int q = 0; q < 8; ++q) {
                if (ss[q] < n2) {
                    float4 v = h4_to_f4(*(const uint2*)&g_aggh[(size_t)ss[q] * H + c]);
                    float4& a = (q & 1) ? a1 : a0;
                    a.x += v.x; a.y += v.y; a.z += v.z; a.w += v.w;
                }
            }
        }
        for (; j < cl; ++j) {
            int s0 = __shfl_sync(0xffffffffu, s, j);
            if (s0 < n2) {
                float4 v = h4_to_f4(*(const uint2*)&g_aggh[(size_t)s0 * H + c]);
                a0.x += v.x; a0.y += v.y; a0.z += v.z; a0.w += v.w;
            }
        }
    }

    float4 o = make_float4(0.f, 0.f, 0.f, 0.f);
    if (cnt > 0) {
        float sc = 1.f / (float)cnt;
        float4 p1 = h4_to_f4(*(const uint2*)&g_p1h[(size_t)t * H + c]);
        float4 bb = *(const float4*)&b[c];
        o.x = (p1.x + a0.x + a1.x) * sc + bb.x;
        o.y = (p1.y + a0.y + a1.y) * sc + bb.y;
        o.z = (p1.z + a0.z + a1.z) * sc + bb.z;
        o.w = (p1.w + a0.w + a1.w) * sc + bb.w;
    }
    *(uint2*)&g_meanh[(size_t)t * H + c] = f4_to_h4(o);
}

// ---- K7: out = l2norm( [mean|g1] @ [Wl|Wr]^T + bl ), K=256 fp16 MMA ------------
__global__ void __launch_bounds__(256) k_sage_out(
    const float* __restrict__ Wl, const float* __restrict__ bl,
    const float* __restrict__ Wr, int n2, float* __restrict__ out) {
    extern __shared__ __half hsm[];
    __half* As = hsm;
    __half* Bs = hsm + 64 * HS2;
    float* psum = (float*)(hsm + 192 * HS2);
    float* scl  = psum + GROWS * 8;

    int row0 = blockIdx.x * GROWS;
    int tid = threadIdx.x, lane = tid & 31, warp = tid >> 5;
    int wm = warp >> 1, wn = warp & 1;
    int lq = lane >> 2, lr = lane & 3;

#pragma unroll
    for (int it = 0; it < 16; ++it) {
        int ch = it * 256 + tid;
        int r = ch >> 6, q = ch & 63;
        int row = row0 + r;
        uint2 v = make_uint2(0u, 0u);
        if (row < n2) {
            if (q < 32) v = *(const uint2*)&g_meanh[(size_t)row * H + q * 4];
            else        v = *(const uint2*)&g_g1h[(size_t)row * H + (q - 32) * 4];
        }
        int k = (q < 32) ? q * 4 : 128 + (q - 32) * 4;
        *(uint2*)&As[r * HS2 + k] = v;
    }
#pragma unroll
    for (int it = 0; it < 32; ++it) {
        int ch = it * 256 + tid;
        int j = ch >> 6, q = ch & 63;
        float4 v;
        int k;
        if (q < 32) { v = *(const float4*)&Wl[(size_t)j * H + q * 4]; k = q * 4; }
        else        { v = *(const float4*)&Wr[(size_t)j * H + (q - 32) * 4]; k = 128 + (q - 32) * 4; }
        *(uint2*)&Bs[j * HS2 + k] = f4_to_h4(v);
    }
    __syncthreads();

    float acc[8][4];
#pragma unroll
    for (int ni = 0; ni < 8; ++ni)
#pragma unroll
        for (int j = 0; j < 4; ++j) acc[ni][j] = 0.f;

#pragma unroll
    for (int ks = 0; ks < 16; ++ks) {
        int kb = ks * 16;
        int r0 = wm * 16 + lq;
        uint32_t a0 = *(const uint32_t*)&As[r0 * HS2 + kb + lr * 2];
        uint32_t a1 = *(const uint32_t*)&As[(r0 + 8) * HS2 + kb + lr * 2];
        uint32_t a2 = *(const uint32_t*)&As[r0 * HS2 + kb + 8 + lr * 2];
        uint32_t a3 = *(const uint32_t*)&As[(r0 + 8) * HS2 + kb + 8 + lr * 2];
#pragma unroll
        for (int ni = 0; ni < 8; ++ni) {
            int n = wn * 64 + ni * 8 + lq;
            uint32_t b0 = *(const uint32_t*)&Bs[n * HS2 + kb + lr * 2];
            uint32_t b1 = *(const uint32_t*)&Bs[n * HS2 + kb + 8 + lr * 2];
            MMA_F16(acc[ni], a0, a1, a2, a3, b0, b1);
        }
    }

    float p0 = 0.f, p8 = 0.f;
#pragma unroll
    for (int ni = 0; ni < 8; ++ni) {
        int col = wn * 64 + ni * 8 + lr * 2;
        float2 bb = *(const float2*)&bl[col];
        acc[ni][0] += bb.x; acc[ni][1] += bb.y;
        acc[ni][2] += bb.x; acc[ni][3] += bb.y;
        p0 += acc[ni][0] * acc[ni][0] + acc[ni][1] * acc[ni][1];
        p8 += acc[ni][2] * acc[ni][2] + acc[ni][3] * acc[ni][3];
    }
    int rl = wm * 16 + lq;
    psum[rl * 8 + wn * 4 + lr] = p0;
    psum[(rl + 8) * 8 + wn * 4 + lr] = p8;
    __syncthreads();
    if (tid < GROWS) {
        float ssum = 0.f;
#pragma unroll
        for (int c8 = 0; c8 < 8; ++c8) ssum += psum[tid * 8 + c8];
        scl[tid] = 1.f / fmaxf(sqrtf(ssum), 1e-12f);
    }
    __syncthreads();

    float s0 = scl[rl], s8 = scl[rl + 8];
    int row_a = row0 + rl, row_b = row0 + rl + 8;
#pragma unroll
    for (int ni = 0; ni < 8; ++ni) {
        int col = wn * 64 + ni * 8 + lr * 2;
        if (row_a < n2)
            *(float2*)&out[(size_t)row_a * H + col] =
                make_float2(acc[ni][0] * s0, acc[ni][1] * s0);
        if (row_b < n2)
            *(float2*)&out[(size_t)row_b * H + col] =
                make_float2(acc[ni][2] * s8, acc[ni][3] * s8);
    }
}

// ---------------------------------------------------------------------------
extern "C" void kernel_launch(void* const* d_in, const int* in_sizes, int n_in,
                              void* d_out, int out_size) {
    const float* x     = (const float*)d_in[0];
    const float* attr  = (const float*)d_in[1];
    const int*   e_id1 = (const int*)d_in[3];
    const int*   src1  = (const int*)d_in[6];
    const int*   tgt1  = (const int*)d_in[7];
    const int*   n1p   = (const int*)d_in[8];
    const float* gcn_W = (const float*)d_in[10];
    const float* gcn_b = (const float*)d_in[11];
    const float* Wl1   = (const float*)d_in[15];
    const float* bl1   = (const float*)d_in[16];
    const float* Wr1   = (const float*)d_in[17];
    float* out = (float*)d_out;

    int N0 = in_sizes[0] / H;  if (N0 > MAXN0) N0 = MAXN0;
    int E1 = in_sizes[3];      if (E1 > MAXE)  E1 = MAXE;
    int n2 = out_size / H;     if (n2 > MAXN2) n2 = MAXN2;

    constexpr int SMEM_GEMM = 2 * 128 * HSTR * 2;
    constexpr int SMEM_SCAN = MAXN2 * 4;
    constexpr int SMEM_SOUT = 192 * HS2 * 2 + GROWS * 8 * 4 + GROWS * 4;
    cudaFuncSetAttribute(k_gemm_tc, cudaFuncAttributeMaxDynamicSharedMemorySize, SMEM_GEMM);
    cudaFuncSetAttribute(k_scan, cudaFuncAttributeMaxDynamicSharedMemorySize, SMEM_SCAN);
    cudaFuncSetAttribute(k_sage_out, cudaFuncAttributeMaxDynamicSharedMemorySize, SMEM_SOUT);

    cudaStream_t s2;
    cudaStreamCreateWithFlags(&s2, cudaStreamNonBlocking);
    cudaEvent_t evFork, evGemm;
    cudaEventCreateWithFlags(&evFork, cudaEventDisableTiming);
    cudaEventCreateWithFlags(&evGemm, cudaEventDisableTiming);

    cudaEventRecord(evFork, 0);
    cudaStreamWaitEvent(s2, evFork, 0);
    k_gemm_tc<<<(N0 + 127) / 128, 256, SMEM_GEMM, s2>>>(x, gcn_W, n1p, N0);
    cudaEventRecord(evGemm, s2);

    k_hist<<<(E1 + 511) / 512, 256>>>(attr, e_id1, tgt1, E1, n2);
    k_scan<<<1, 1024, SMEM_SCAN>>>(n2);
    k_scatter<<<(E1 + 511) / 512, 256>>>(src1, tgt1, E1, n2);

    cudaStreamWaitEvent(0, evGemm, 0);

    k_gather_gcn<<<(n2 + 7) / 8, 256>>>(gcn_b, n2);
    k_sage2<<<(n2 + 7) / 8, 256>>>(gcn_b, n2);
    k_sage_out<<<(n2 + GROWS - 1) / GROWS, 256, SMEM_SOUT>>>(Wl1, bl1, Wr1, n2, out);
}